// round 10
// baseline (speedup 1.0000x reference)
#include <cuda_runtime.h>
#include <cuda_bf16.h>
#include <stdint.h>
#include <math.h>

#define Bb   4
#define Nn   4096
#define Dd   512
#define Hh   8
#define DHd  64
#define Mm   266
#define BHh  32          // B*H
#define BNn  16384       // B*N
#define MPAD 268
#define K2   1536        // split-bf16 expanded K (hi|lo|hi)

// -------------------- scratch (static device memory; no allocs) --------------------
__device__ float g_q  [(size_t)BHh * Nn * DHd];
__device__ float g_k  [(size_t)BHh * Nn * DHd];
__device__ float g_v  [(size_t)BHh * Nn * DHd];
__device__ float g_qp [(size_t)BHh * Nn * Mm];
__device__ float g_kp [(size_t)BHh * Nn * Mm];   // holds td_k, consumed by ctx_fused
__device__ float g_ctx [(size_t)BHh * Mm * DHd];
__device__ float g_ksum[(size_t)BHh * Mm];
__device__ float g_kmax[BHh];
__device__ float g_diag[(size_t)BHh * Nn];
__device__ float g_dinv[(size_t)BHh * Nn];

__device__ __nv_bfloat16 g_x2   [(size_t)BNn * K2];
__device__ __nv_bfloat16 g_attn2[(size_t)BNn * K2];
__device__ __nv_bfloat16 g_wq2  [(size_t)Dd * K2];
__device__ __nv_bfloat16 g_wk2  [(size_t)Dd * K2];
__device__ __nv_bfloat16 g_wv2  [(size_t)Dd * K2];
__device__ __nv_bfloat16 g_wo2  [(size_t)Dd * K2];

// -------------------- helpers --------------------
typedef unsigned long long u64t;

__device__ __forceinline__ uint32_t smem_to_u32(const void* p) {
    uint32_t a;
    asm("{ .reg .u64 t; cvta.to.shared.u64 t, %1; cvt.u32.u64 %0, t; }"
        : "=r"(a) : "l"(p));
    return a;
}

#define CP_ASYNC16(dst, src) \
    asm volatile("cp.async.cg.shared.global [%0], [%1], 16;" \
                 :: "r"(dst), "l"(src) : "memory")
#define CP_COMMIT()  asm volatile("cp.async.commit_group;" ::: "memory")
#define CP_WAIT1()   asm volatile("cp.async.wait_group 1;" ::: "memory")
#define CP_WAIT0()   asm volatile("cp.async.wait_group 0;" ::: "memory")

__device__ __forceinline__ void ldm_x4(uint32_t& r0, uint32_t& r1,
                                       uint32_t& r2, uint32_t& r3, uint32_t addr) {
    asm volatile("ldmatrix.sync.aligned.m8n8.x4.shared.b16 {%0,%1,%2,%3}, [%4];"
                 : "=r"(r0), "=r"(r1), "=r"(r2), "=r"(r3) : "r"(addr));
}

__device__ __forceinline__ void mma16816(float* c, const uint32_t* a, const uint32_t* b) {
    asm volatile(
        "mma.sync.aligned.m16n8k16.row.col.f32.bf16.bf16.f32 "
        "{%0,%1,%2,%3}, {%4,%5,%6,%7}, {%8,%9}, {%0,%1,%2,%3};"
        : "+f"(c[0]), "+f"(c[1]), "+f"(c[2]), "+f"(c[3])
        : "r"(a[0]), "r"(a[1]), "r"(a[2]), "r"(a[3]), "r"(b[0]), "r"(b[1]));
}

// ---- packed fp32x2 FMA (Blackwell base ISA) ----
__device__ __forceinline__ u64t pack2(float x, float y) {
    u64t r;
    asm("mov.b64 %0, {%1, %2};" : "=l"(r) : "f"(x), "f"(y));
    return r;
}
__device__ __forceinline__ u64t bcast2(float v) {
    u64t r;
    asm("mov.b64 %0, {%1, %1};" : "=l"(r) : "f"(v));
    return r;
}
__device__ __forceinline__ void ffma2(u64t& c, u64t a, u64t b) {
    asm("fma.rn.f32x2 %0, %1, %2, %0;" : "+l"(c) : "l"(a), "l"(b));
}
__device__ __forceinline__ float lane0(u64t v) { float2 t; *(u64t*)&t = v; return t.x; }
__device__ __forceinline__ float lane1(u64t v) { float2 t; *(u64t*)&t = v; return t.y; }
#define ACC2F(i, j) (((i) & 1) ? lane1(acc2[(i) >> 1][j]) : lane0(acc2[(i) >> 1][j]))

#define F32X2_STEP(a4, b4) do {                                   \
    u64t a01 = pack2((a4).x, (a4).y), a23 = pack2((a4).z, (a4).w);\
    u64t bb0 = bcast2((b4).x), bb1 = bcast2((b4).y);              \
    u64t bb2 = bcast2((b4).z), bb3 = bcast2((b4).w);              \
    ffma2(acc2[0][0], a01, bb0); ffma2(acc2[0][1], a01, bb1);     \
    ffma2(acc2[0][2], a01, bb2); ffma2(acc2[0][3], a01, bb3);     \
    ffma2(acc2[1][0], a23, bb0); ffma2(acc2[1][1], a23, bb1);     \
    ffma2(acc2[1][2], a23, bb2); ffma2(acc2[1][3], a23, bb3);     \
} while (0)

__device__ __forceinline__ void atomicMaxF(float* addr, float val) {
    int* ai = (int*)addr;
    int old = *ai;
    while (__int_as_float(old) < val) {
        int assumed = old;
        old = atomicCAS(ai, assumed, __float_as_int(val));
        if (old == assumed) break;
    }
}

__device__ __forceinline__ float fast_exp(float x) {
    float y = fmaxf(x * 1.4426950408889634f, -126.0f);
    float r = rintf(y);
    float f = y - r;
    float p = 1.5403530e-4f;
    p = fmaf(p, f, 1.3333558e-3f);
    p = fmaf(p, f, 9.6181291e-3f);
    p = fmaf(p, f, 5.5504109e-2f);
    p = fmaf(p, f, 2.4022651e-1f);
    p = fmaf(p, f, 6.9314718e-1f);
    p = fmaf(p, f, 1.0f);
    int e = (int)r;
    float s = __int_as_float((e + 127) << 23);
    return p * s;
}

#define NORMALIZER 0.35355339059327373f   // 64^-0.25
#define RATIO      0.061313934f           // 266^-0.5
#define EPSF       1e-4f

// -------------------- init scratch accumulators --------------------
__global__ void k_init() {
    int i = blockIdx.x * 256 + threadIdx.x;
    if (i < BHh * Mm * DHd) g_ctx[i]  = 0.0f;
    if (i < BHh * Mm)       g_ksum[i] = 0.0f;
    if (i < BHh)            g_kmax[i] = -3.0e38f;
}

// -------------------- fp32 -> split bf16 (hi|lo|hi at given offsets) --------------------
__global__ __launch_bounds__(256) void k_split(const float* __restrict__ src,
                                               __nv_bfloat16* __restrict__ dst,
                                               int nrows, int loOff, int dupOff) {
    int i = blockIdx.x * 256 + threadIdx.x;
    int total = nrows * 128;   // 4 floats per thread
    if (i >= total) return;
    int r = i >> 7;
    int c = (i & 127) << 2;
    float4 v = *(const float4*)(src + (size_t)r * 512 + c);
    __nv_bfloat16 h0 = __float2bfloat16(v.x), h1 = __float2bfloat16(v.y);
    __nv_bfloat16 h2 = __float2bfloat16(v.z), h3 = __float2bfloat16(v.w);
    __nv_bfloat16 l0 = __float2bfloat16(v.x - __bfloat162float(h0));
    __nv_bfloat16 l1 = __float2bfloat16(v.y - __bfloat162float(h1));
    __nv_bfloat16 l2 = __float2bfloat16(v.z - __bfloat162float(h2));
    __nv_bfloat16 l3 = __float2bfloat16(v.w - __bfloat162float(h3));
    size_t rb = (size_t)r * K2;
    __nv_bfloat162 H01; H01.x = h0; H01.y = h1;
    __nv_bfloat162 H23; H23.x = h2; H23.y = h3;
    __nv_bfloat162 L01; L01.x = l0; L01.y = l1;
    __nv_bfloat162 L23; L23.x = l2; L23.y = l3;
    *(__nv_bfloat162*)(dst + rb + c)              = H01;
    *(__nv_bfloat162*)(dst + rb + c + 2)          = H23;
    *(__nv_bfloat162*)(dst + rb + loOff + c)      = L01;
    *(__nv_bfloat162*)(dst + rb + loOff + c + 2)  = L23;
    *(__nv_bfloat162*)(dst + rb + dupOff + c)     = H01;
    *(__nv_bfloat162*)(dst + rb + dupOff + c + 2) = H23;
}

// -------------------- mma.sync GEMM: C[16384,512] = A2[16384,K2] @ B2[512,K2]^T --------
#define ASTR 40              // padded bf16 per smem row (80B, conflict-free ldmatrix)
#define TILE_B (128 * ASTR)  // bf16 elems per buffer

__global__ __launch_bounds__(256) void k_gemm(const __nv_bfloat16* __restrict__ A,
                                              const __nv_bfloat16* __restrict__ Bw,
                                              float* __restrict__ C,
                                              const float* __restrict__ xres,
                                              const float* __restrict__ bo,
                                              int finalmode) {
    __shared__ __nv_bfloat16 sA[2][TILE_B];
    __shared__ __nv_bfloat16 sB[2][TILE_B];
    int tid = threadIdx.x, lane = tid & 31, w = tid >> 5;
    int m0 = (w & 3) * 32, n0 = (w >> 2) * 64;
    int r0 = blockIdx.x * 128, e0 = blockIdx.y * 128;
    uint32_t sAu = smem_to_u32(sA), sBu = smem_to_u32(sB);

    float acc[2][8][4];
#pragma unroll
    for (int i = 0; i < 2; i++)
#pragma unroll
        for (int j = 0; j < 8; j++)
#pragma unroll
            for (int l = 0; l < 4; l++) acc[i][j][l] = 0.f;

    int lrow = tid >> 1;
    int lcol = (tid & 1) << 4;
    const __nv_bfloat16* Arow = A + (size_t)(r0 + lrow) * K2 + lcol;
    const __nv_bfloat16* Brow = Bw + (size_t)(e0 + lrow) * K2 + lcol;
    uint32_t sAdst = sAu + (uint32_t)(lrow * ASTR + lcol) * 2;
    uint32_t sBdst = sBu + (uint32_t)(lrow * ASTR + lcol) * 2;

#define LOAD_TILE(buf, t) do {                                         \
    uint32_t _o = (uint32_t)(buf) * (TILE_B * 2);                      \
    const __nv_bfloat16* _a = Arow + (t) * 32;                         \
    const __nv_bfloat16* _b = Brow + (t) * 32;                         \
    CP_ASYNC16(sAdst + _o,      _a);                                   \
    CP_ASYNC16(sAdst + _o + 16, _a + 8);                               \
    CP_ASYNC16(sBdst + _o,      _b);                                   \
    CP_ASYNC16(sBdst + _o + 16, _b + 8);                               \
} while (0)

    LOAD_TILE(0, 0);
    CP_COMMIT();

    const int NT = K2 / 32;   // 48
#pragma unroll 1
    for (int t = 0; t < NT; ++t) {
        int buf = t & 1;
        if (t + 1 < NT) {
            LOAD_TILE(buf ^ 1, t + 1);
            CP_COMMIT();
            CP_WAIT1();
        } else {
            CP_WAIT0();
        }
        __syncthreads();

        uint32_t ab = sAu + (uint32_t)buf * (TILE_B * 2);
        uint32_t bb = sBu + (uint32_t)buf * (TILE_B * 2);
#pragma unroll
        for (int ks = 0; ks < 32; ks += 16) {
            uint32_t a[2][4];
#pragma unroll
            for (int mt = 0; mt < 2; mt++) {
                uint32_t addr = ab +
                    (uint32_t)((m0 + mt * 16 + (lane & 15)) * ASTR + ks + ((lane >> 4) << 3)) * 2;
                ldm_x4(a[mt][0], a[mt][1], a[mt][2], a[mt][3], addr);
            }
            uint32_t b[8][2];
#pragma unroll
            for (int p = 0; p < 4; p++) {
                int nA = n0 + p * 16;
                uint32_t addr = bb +
                    (uint32_t)((nA + (lane & 7) + ((lane >> 4) << 3)) * ASTR + ks + (lane & 8)) * 2;
                ldm_x4(b[2 * p][0], b[2 * p][1], b[2 * p + 1][0], b[2 * p + 1][1], addr);
            }
#pragma unroll
            for (int mt = 0; mt < 2; mt++)
#pragma unroll
                for (int nt = 0; nt < 8; nt++)
                    mma16816(acc[mt][nt], a[mt], b[nt]);
        }
        __syncthreads();
    }

    int gid = lane >> 2, tig = lane & 3;
#pragma unroll
    for (int mt = 0; mt < 2; mt++) {
#pragma unroll
        for (int nt = 0; nt < 8; nt++) {
            int r = r0 + m0 + mt * 16 + gid;
            int e = e0 + n0 + nt * 8 + tig * 2;
            float2 v01 = make_float2(acc[mt][nt][0], acc[mt][nt][1]);
            float2 v23 = make_float2(acc[mt][nt][2], acc[mt][nt][3]);
            if (!finalmode) {
                int b = r >> 12, n = r & 4095;
                int h = e >> 6, dh = e & 63;
                float* d0 = C + (((size_t)((b << 3) + h) * Nn + n) * DHd + dh);
                *(float2*)d0 = v01;
                *(float2*)(d0 + 8 * DHd) = v23;
            } else {
                size_t b0 = (size_t)r * Dd + e;
                float2 x0 = *(const float2*)(xres + b0);
                float2 x1 = *(const float2*)(xres + b0 + 8 * Dd);
                float2 bv = *(const float2*)(bo + e);
                *(float2*)(C + b0) = make_float2(x0.x + bv.x + v01.x, x0.y + bv.y + v01.y);
                *(float2*)(C + b0 + 8 * Dd) = make_float2(x1.x + bv.x + v23.x, x1.y + bv.y + v23.y);
            }
        }
    }
}

// -------------------- phi_k: td = (k*nrm)@proj^T into g_kp, diag, per-head max ------
// One block per (n0, bh); loops all 5 m-tiles with the K tile resident (k read 1x).
__global__ __launch_bounds__(256) void k_phi_k(const float* __restrict__ proj) {
    __shared__ float Ks[64][68];   // [dh][n]
    __shared__ float Ps[64][68];   // [dh][m]
    __shared__ float red[256];
    int tid = threadIdx.x;
    int n0 = blockIdx.x * 64;
    int bh = blockIdx.y;

#pragma unroll
    for (int i = 0; i < 4; i++) {
        int s = tid + i * 256;
        int row = s >> 4;
        int kc = (s & 15) << 2;
        float4 a = *(const float4*)(g_k + ((size_t)bh * Nn + n0 + row) * DHd + kc);
        Ks[kc + 0][row] = a.x * NORMALIZER; Ks[kc + 1][row] = a.y * NORMALIZER;
        Ks[kc + 2][row] = a.z * NORMALIZER; Ks[kc + 3][row] = a.w * NORMALIZER;
    }
    __syncthreads();

    if (tid < 64) {
        float ss = 0.f;
#pragma unroll
        for (int d = 0; d < 64; d++) { float q = Ks[d][tid]; ss += q * q; }
        g_diag[(size_t)bh * Nn + n0 + tid] = 0.5f * ss;
    }

    int ty = tid >> 4, tx = tid & 15;
    float mymax = -3.0e38f;
    for (int mt = 0; mt < 5; mt++) {
        int m0 = mt * 64;
#pragma unroll
        for (int i = 0; i < 4; i++) {
            int s = tid + i * 256;
            int row = s >> 4;
            int kc = (s & 15) << 2;
            float4 p = make_float4(0.f, 0.f, 0.f, 0.f);
            if (m0 + row < Mm) p = *(const float4*)(proj + (size_t)(m0 + row) * DHd + kc);
            Ps[kc + 0][row] = p.x; Ps[kc + 1][row] = p.y;
            Ps[kc + 2][row] = p.z; Ps[kc + 3][row] = p.w;
        }
        __syncthreads();
        u64t acc2[2][4];
#pragma unroll
        for (int i = 0; i < 2; i++)
#pragma unroll
            for (int j = 0; j < 4; j++) acc2[i][j] = 0ull;
#pragma unroll
        for (int kk = 0; kk < 64; kk++) {
            float4 a = *(const float4*)&Ks[kk][ty * 4];
            float4 b = *(const float4*)&Ps[kk][tx * 4];
            F32X2_STEP(a, b);
        }
#pragma unroll
        for (int i = 0; i < 4; i++) {
            int n = n0 + ty * 4 + i;
#pragma unroll
            for (int j = 0; j < 4; j++) {
                int m = m0 + tx * 4 + j;
                if (m < Mm) {
                    float av = ACC2F(i, j);
                    g_kp[((size_t)bh * Nn + n) * Mm + m] = av;
                    mymax = fmaxf(mymax, av);
                }
            }
        }
        __syncthreads();
    }
    red[tid] = mymax;
    __syncthreads();
    for (int off = 128; off > 0; off >>= 1) {
        if (tid < off) red[tid] = fmaxf(red[tid], red[tid + off]);
        __syncthreads();
    }
    if (tid == 0) atomicMaxF(&g_kmax[bh], red[0]);
}

// -------------------- ctx_fused: exp(td) inline + ctx MMA + ksum -------------------
// ctx[m,dh] += sum_n kp[n,m]*v[n,dh]; kp computed on the fly from td in g_kp.
__global__ __launch_bounds__(256) void k_ctx() {
    __shared__ float Ksm[64][68];  // [n][m]  (kp values)
    __shared__ float Vs[64][68];   // [n][dh]
    __shared__ float rsum[256];
    int tid = threadIdx.x;
    int m0 = blockIdx.x * 64;
    int nc = blockIdx.y * 512;
    int bh = blockIdx.z;
    float mx = g_kmax[bh];
    u64t acc2[2][4];
#pragma unroll
    for (int i = 0; i < 2; i++)
#pragma unroll
        for (int j = 0; j < 4; j++) acc2[i][j] = 0ull;
    int ty = tid >> 4, tx = tid & 15;
    float cs = 0.f;    // column partial sum; this thread's column = m0 + (tid & 63)

    for (int n0 = nc; n0 < nc + 512; n0 += 64) {
#pragma unroll
        for (int i = 0; i < 16; i++) {
            int s = tid + i * 256;
            int n = s >> 6, mm = s & 63;
            int m = m0 + mm;
            float v = 0.f;
            if (m < Mm) {
                float td = g_kp[((size_t)bh * Nn + n0 + n) * Mm + m];
                float dg = g_diag[(size_t)bh * Nn + n0 + n];
                v = RATIO * (fast_exp(td - dg - mx) + EPSF);
                cs += v;
            }
            Ksm[n][mm] = v;
        }
#pragma unroll
        for (int i = 0; i < 4; i++) {
            int s = tid + i * 256;
            int n = s >> 4, c = (s & 15) << 2;
            float4 v = *(const float4*)(g_v + ((size_t)bh * Nn + n0 + n) * DHd + c);
            Vs[n][c] = v.x; Vs[n][c + 1] = v.y; Vs[n][c + 2] = v.z; Vs[n][c + 3] = v.w;
        }
        __syncthreads();
#pragma unroll
        for (int kk = 0; kk < 64; kk++) {
            float4 a = *(const float4*)&Ksm[kk][ty * 4];
            float4 b = *(const float4*)&Vs[kk][tx * 4];
            F32X2_STEP(a, b);
        }
        __syncthreads();
    }
#pragma unroll
    for (int i = 0; i < 4; i++) {
        int m = m0 + ty * 4 + i;
        if (m < Mm)
#pragma unroll
            for (int j = 0; j < 4; j++)
                atomicAdd(&g_ctx[((size_t)bh * Mm + m) * DHd + tx * 4 + j], ACC2F(i, j));
    }
    // ksum: threads tid, tid+64, tid+128, tid+192 share column (tid & 63)
    rsum[tid] = cs;
    __syncthreads();
    if (tid < 64) {
        int m = m0 + tid;
        if (m < Mm) {
            float t = rsum[tid] + rsum[tid + 64] + rsum[tid + 128] + rsum[tid + 192];
            atomicAdd(&g_ksum[bh * Mm + m], t);
        }
    }
}

// -------------------- phi_q fully fused: td -> rowmax -> exp -> qp + d_inv --------------------
#define QP_SMEM_FLOATS (4352 + 4352 + 17152 + MPAD + 64)
__global__ __launch_bounds__(256) void k_phi_q(const float* __restrict__ proj) {
    extern __shared__ float sm[];
    float* Qs     = sm;                       // 64*68  [dh][n]
    float* Ps     = sm + 4352;                // 64*68  [dh][m]
    float* tds    = sm + 8704;                // 64*MPAD
    float* ksum_s = sm + 8704 + 17152;        // MPAD
    float* diag_s = ksum_s + MPAD;            // 64

    int tid = threadIdx.x;
    int n0 = blockIdx.x * 64;
    int bh = blockIdx.y;

    for (int i = tid; i < Mm; i += 256) ksum_s[i] = g_ksum[bh * Mm + i];

#pragma unroll
    for (int i = 0; i < 4; i++) {
        int s = tid + i * 256;
        int row = s >> 4;
        int kc = (s & 15) << 2;
        float4 a = *(const float4*)(g_q + ((size_t)bh * Nn + n0 + row) * DHd + kc);
        Qs[(kc + 0) * 68 + row] = a.x * NORMALIZER;
        Qs[(kc + 1) * 68 + row] = a.y * NORMALIZER;
        Qs[(kc + 2) * 68 + row] = a.z * NORMALIZER;
        Qs[(kc + 3) * 68 + row] = a.w * NORMALIZER;
    }
    __syncthreads();
    if (tid < 64) {
        float ss = 0.f;
#pragma unroll
        for (int d = 0; d < 64; d++) { float q = Qs[d * 68 + tid]; ss += q * q; }
        diag_s[tid] = 0.5f * ss;
    }

    int ty = tid >> 4, tx = tid & 15;
    for (int mt = 0; mt < 5; mt++) {
        int m0 = mt * 64;
#pragma unroll
        for (int i = 0; i < 4; i++) {
            int s = tid + i * 256;
            int row = s >> 4;
            int kc = (s & 15) << 2;
            float4 p = make_float4(0.f, 0.f, 0.f, 0.f);
            if (m0 + row < Mm) p = *(const float4*)(proj + (size_t)(m0 + row) * DHd + kc);
            Ps[(kc + 0) * 68 + row] = p.x;
            Ps[(kc + 1) * 68 + row] = p.y;
            Ps[(kc + 2) * 68 + row] = p.z;
            Ps[(kc + 3) * 68 + row] = p.w;
        }
        __syncthreads();
        u64t acc2[2][4];
#pragma unroll
        for (int i = 0; i < 2; i++)
#pragma unroll
            for (int j = 0; j < 4; j++) acc2[i][j] = 0ull;
#pragma unroll
        for (int kk = 0; kk < 64; kk++) {
            float4 a = *(const float4*)&Qs[kk * 68 + ty * 4];
            float4 b = *(const float4*)&Ps[kk * 68 + tx * 4];
            F32X2_STEP(a, b);
        }
#pragma unroll
        for (int i = 0; i < 4; i++)
#pragma unroll
            for (int j = 0; j < 4; j++) {
                int m = m0 + tx * 4 + j;
                if (m < Mm) tds[(ty * 4 + i) * MPAD + m] = ACC2F(i, j);
            }
        __syncthreads();
    }

    int row = tid >> 2, lane = tid & 3;
    float pm = -3.0e38f;
    for (int m = lane; m < Mm; m += 4) pm = fmaxf(pm, tds[row * MPAD + m]);
    pm = fmaxf(pm, __shfl_xor_sync(0xffffffffu, pm, 1));
    pm = fmaxf(pm, __shfl_xor_sync(0xffffffffu, pm, 2));
    float dg = diag_s[row];
    float sum = 0.f;
    size_t gb = ((size_t)bh * Nn + n0 + row) * Mm;
    for (int m = lane; m < Mm; m += 4) {
        float v = RATIO * (fast_exp(tds[row * MPAD + m] - dg - pm) + EPSF);
        g_qp[gb + m] = v;
        sum += v * ksum_s[m];
    }
    sum += __shfl_xor_sync(0xffffffffu, sum, 1);
    sum += __shfl_xor_sync(0xffffffffu, sum, 2);
    if (lane == 0) g_dinv[(size_t)bh * Nn + n0 + row] = 1.0f / sum;
}

// -------------------- out: attn2 (split bf16) = d_inv[n] * sum_m qp[n,m]*ctx[m,dh] --------------------
__global__ __launch_bounds__(256) void k_out() {
    __shared__ float Qs[64][68];  // [k][n]
    __shared__ float Cs[64][68];  // [k][dh]
    int tid = threadIdx.x;
    int n0 = blockIdx.x * 64;
    int bh = blockIdx.y;
    u64t acc2[2][4];
#pragma unroll
    for (int i = 0; i < 2; i++)
#pragma unroll
        for (int j = 0; j < 4; j++) acc2[i][j] = 0ull;
    int ty = tid >> 4, tx = tid & 15;

    for (int c0 = 0; c0 < Mm; c0 += 64) {
#pragma unroll
        for (int i = 0; i < 16; i++) {
            int s = tid + i * 256;
            int r = s >> 6, kc = s & 63;
            Qs[kc][r] = (c0 + kc < Mm)
                            ? g_qp[((size_t)bh * Nn + n0 + r) * Mm + c0 + kc]
                            : 0.f;
        }
#pragma unroll
        for (int i = 0; i < 16; i++) {
            int s = tid + i * 256;
            int kk = s >> 6, dh = s & 63;
            Cs[kk][dh] = (c0 + kk < Mm)
                             ? g_ctx[((size_t)bh * Mm + c0 + kk) * DHd + dh]
                             : 0.f;
        }
        __syncthreads();
#pragma unroll
        for (int kk = 0; kk < 64; kk++) {
            float4 a = *(const float4*)&Qs[kk][ty * 4];
            float4 b = *(const float4*)&Cs[kk][tx * 4];
            F32X2_STEP(a, b);
        }
        __syncthreads();
    }
    int b = bh >> 3, h = bh & 7;
#pragma unroll
    for (int i = 0; i < 4; i++) {
        int n = n0 + ty * 4 + i;
        float dv = g_dinv[(size_t)bh * Nn + n];
        size_t rb = (size_t)(b * Nn + n) * K2 + h * 64 + tx * 4;
#pragma unroll
        for (int j = 0; j < 4; j++) {
            float val = ACC2F(i, j) * dv;
            __nv_bfloat16 hv = __float2bfloat16(val);
            __nv_bfloat16 lv = __float2bfloat16(val - __bfloat162float(hv));
            g_attn2[rb + j]        = hv;   // hi
            g_attn2[rb + 512 + j]  = lv;   // lo  (pairs with Wo hi)
            g_attn2[rb + 1024 + j] = hv;   // hi  (pairs with Wo lo)
        }
    }
}

// -------------------- launch --------------------
extern "C" void kernel_launch(void* const* d_in, const int* in_sizes, int n_in,
                              void* d_out, int out_size) {
    const float* x    = (const float*)d_in[0];
    const float* Wq   = (const float*)d_in[1];
    const float* Wk   = (const float*)d_in[2];
    const float* Wv   = (const float*)d_in[3];
    const float* Wo   = (const float*)d_in[4];
    const float* bo   = (const float*)d_in[5];
    const float* proj = (const float*)d_in[6];
    float* out = (float*)d_out;
    (void)in_sizes; (void)n_in; (void)out_size;

    cudaFuncSetAttribute(k_phi_q, cudaFuncAttributeMaxDynamicSharedMemorySize,
                         QP_SMEM_FLOATS * (int)sizeof(float));

    __nv_bfloat16 *x2p, *wq2p, *wk2p, *wv2p, *wo2p, *attn2p;
    cudaGetSymbolAddress((void**)&x2p, g_x2);
    cudaGetSymbolAddress((void**)&wq2p, g_wq2);
    cudaGetSymbolAddress((void**)&wk2p, g_wk2);
    cudaGetSymbolAddress((void**)&wv2p, g_wv2);
    cudaGetSymbolAddress((void**)&wo2p, g_wo2);
    cudaGetSymbolAddress((void**)&attn2p, g_attn2);
    float *qp_, *kp_, *vp_;
    cudaGetSymbolAddress((void**)&qp_, g_q);
    cudaGetSymbolAddress((void**)&kp_, g_k);
    cudaGetSymbolAddress((void**)&vp_, g_v);

    k_init<<<(BHh * Mm * DHd + 255) / 256, 256>>>();
    k_split<<<(BNn * 128 + 255) / 256, 256>>>(x, x2p, BNn, 512, 1024);
    k_split<<<(Dd * 128 + 255) / 256, 256>>>(Wq, wq2p, Dd, 1024, 512);
    k_split<<<(Dd * 128 + 255) / 256, 256>>>(Wk, wk2p, Dd, 1024, 512);
    k_split<<<(Dd * 128 + 255) / 256, 256>>>(Wv, wv2p, Dd, 1024, 512);

    dim3 gG(BNn / 128, Dd / 128);
    k_gemm<<<gG, 256>>>(x2p, wq2p, qp_, nullptr, nullptr, 0);
    k_gemm<<<gG, 256>>>(x2p, wk2p, kp_, nullptr, nullptr, 0);
    k_gemm<<<gG, 256>>>(x2p, wv2p, vp_, nullptr, nullptr, 0);

    k_split<<<(Dd * 128 + 255) / 256, 256>>>(Wo, wo2p, Dd, 1024, 512);

    k_phi_k<<<dim3(Nn / 64, BHh), 256>>>(proj);
    k_ctx<<<dim3(5, Nn / 512, BHh), 256>>>();
    k_phi_q<<<dim3(Nn / 64, BHh), 256, QP_SMEM_FLOATS * (int)sizeof(float)>>>(proj);
    k_out<<<dim3(Nn / 64, BHh), 256>>>();

    k_gemm<<<gG, 256>>>(attn2p, wo2p, out, x, bo, 1);
}

// round 11
// speedup vs baseline: 1.1370x; 1.1370x over previous
#include <cuda_runtime.h>
#include <cuda_bf16.h>
#include <stdint.h>
#include <math.h>

#define Bb   4
#define Nn   4096
#define Dd   512
#define Hh   8
#define DHd  64
#define Mm   266
#define BHh  32          // B*H
#define BNn  16384       // B*N
#define MPAD 268
#define K2   1536        // split-bf16 expanded K (hi|lo|hi)

// -------------------- scratch (static device memory; no allocs) --------------------
__device__ float g_q  [(size_t)BHh * Nn * DHd];
__device__ float g_k  [(size_t)BHh * Nn * DHd];
__device__ float g_v  [(size_t)BHh * Nn * DHd];
__device__ float g_qp [(size_t)BHh * Nn * Mm];
__device__ float g_kp [(size_t)BHh * Nn * Mm];
__device__ float g_ctx [(size_t)BHh * Mm * DHd];
__device__ float g_ksum[(size_t)BHh * Mm];
__device__ float g_kmax[BHh];
__device__ float g_diag[(size_t)BHh * Nn];
__device__ float g_dinv[(size_t)BHh * Nn];

__device__ __nv_bfloat16 g_x2   [(size_t)BNn * K2];
__device__ __nv_bfloat16 g_attn2[(size_t)BNn * K2];
__device__ __nv_bfloat16 g_wq2  [(size_t)Dd * K2];
__device__ __nv_bfloat16 g_wk2  [(size_t)Dd * K2];
__device__ __nv_bfloat16 g_wv2  [(size_t)Dd * K2];
__device__ __nv_bfloat16 g_wo2  [(size_t)Dd * K2];

// -------------------- helpers --------------------
typedef unsigned long long u64t;

__device__ __forceinline__ uint32_t smem_to_u32(const void* p) {
    uint32_t a;
    asm("{ .reg .u64 t; cvta.to.shared.u64 t, %1; cvt.u32.u64 %0, t; }"
        : "=r"(a) : "l"(p));
    return a;
}

#define CP_ASYNC16(dst, src) \
    asm volatile("cp.async.cg.shared.global [%0], [%1], 16;" \
                 :: "r"(dst), "l"(src) : "memory")
#define CP_COMMIT()  asm volatile("cp.async.commit_group;" ::: "memory")
#define CP_WAIT1()   asm volatile("cp.async.wait_group 1;" ::: "memory")
#define CP_WAIT0()   asm volatile("cp.async.wait_group 0;" ::: "memory")

__device__ __forceinline__ void ldm_x4(uint32_t& r0, uint32_t& r1,
                                       uint32_t& r2, uint32_t& r3, uint32_t addr) {
    asm volatile("ldmatrix.sync.aligned.m8n8.x4.shared.b16 {%0,%1,%2,%3}, [%4];"
                 : "=r"(r0), "=r"(r1), "=r"(r2), "=r"(r3) : "r"(addr));
}

__device__ __forceinline__ void mma16816(float* c, const uint32_t* a, const uint32_t* b) {
    asm volatile(
        "mma.sync.aligned.m16n8k16.row.col.f32.bf16.bf16.f32 "
        "{%0,%1,%2,%3}, {%4,%5,%6,%7}, {%8,%9}, {%0,%1,%2,%3};"
        : "+f"(c[0]), "+f"(c[1]), "+f"(c[2]), "+f"(c[3])
        : "r"(a[0]), "r"(a[1]), "r"(a[2]), "r"(a[3]), "r"(b[0]), "r"(b[1]));
}

// ---- packed fp32x2 FMA (Blackwell base ISA) ----
__device__ __forceinline__ u64t pack2(float x, float y) {
    u64t r;
    asm("mov.b64 %0, {%1, %2};" : "=l"(r) : "f"(x), "f"(y));
    return r;
}
__device__ __forceinline__ u64t bcast2(float v) {
    u64t r;
    asm("mov.b64 %0, {%1, %1};" : "=l"(r) : "f"(v));
    return r;
}
__device__ __forceinline__ void ffma2(u64t& c, u64t a, u64t b) {
    asm("fma.rn.f32x2 %0, %1, %2, %0;" : "+l"(c) : "l"(a), "l"(b));
}
__device__ __forceinline__ float lane0(u64t v) { float2 t; *(u64t*)&t = v; return t.x; }
__device__ __forceinline__ float lane1(u64t v) { float2 t; *(u64t*)&t = v; return t.y; }
#define ACC2F(i, j) (((i) & 1) ? lane1(acc2[(i) >> 1][j]) : lane0(acc2[(i) >> 1][j]))

#define F32X2_STEP(a4, b4) do {                                   \
    u64t a01 = pack2((a4).x, (a4).y), a23 = pack2((a4).z, (a4).w);\
    u64t bb0 = bcast2((b4).x), bb1 = bcast2((b4).y);              \
    u64t bb2 = bcast2((b4).z), bb3 = bcast2((b4).w);              \
    ffma2(acc2[0][0], a01, bb0); ffma2(acc2[0][1], a01, bb1);     \
    ffma2(acc2[0][2], a01, bb2); ffma2(acc2[0][3], a01, bb3);     \
    ffma2(acc2[1][0], a23, bb0); ffma2(acc2[1][1], a23, bb1);     \
    ffma2(acc2[1][2], a23, bb2); ffma2(acc2[1][3], a23, bb3);     \
} while (0)

__device__ __forceinline__ void atomicMaxF(float* addr, float val) {
    int* ai = (int*)addr;
    int old = *ai;
    while (__int_as_float(old) < val) {
        int assumed = old;
        old = atomicCAS(ai, assumed, __float_as_int(val));
        if (old == assumed) break;
    }
}

__device__ __forceinline__ float fast_exp(float x) {
    float y = fmaxf(x * 1.4426950408889634f, -126.0f);
    float r = rintf(y);
    float f = y - r;
    float p = 1.5403530e-4f;
    p = fmaf(p, f, 1.3333558e-3f);
    p = fmaf(p, f, 9.6181291e-3f);
    p = fmaf(p, f, 5.5504109e-2f);
    p = fmaf(p, f, 2.4022651e-1f);
    p = fmaf(p, f, 6.9314718e-1f);
    p = fmaf(p, f, 1.0f);
    int e = (int)r;
    float s = __int_as_float((e + 127) << 23);
    return p * s;
}

#define NORMALIZER 0.35355339059327373f   // 64^-0.25
#define RATIO      0.061313934f           // 266^-0.5
#define EPSF       1e-4f

// -------------------- init scratch accumulators --------------------
__global__ void k_init() {
    int i = blockIdx.x * 256 + threadIdx.x;
    if (i < BHh * Mm * DHd) g_ctx[i]  = 0.0f;
    if (i < BHh * Mm)       g_ksum[i] = 0.0f;
    if (i < BHh)            g_kmax[i] = -3.0e38f;
}

// -------------------- fp32 -> split bf16 (hi|lo|hi at given offsets) --------------------
__global__ __launch_bounds__(256) void k_split(const float* __restrict__ src,
                                               __nv_bfloat16* __restrict__ dst,
                                               int nrows, int loOff, int dupOff) {
    int i = blockIdx.x * 256 + threadIdx.x;
    int total = nrows * 128;   // 4 floats per thread
    if (i >= total) return;
    int r = i >> 7;
    int c = (i & 127) << 2;
    float4 v = *(const float4*)(src + (size_t)r * 512 + c);
    __nv_bfloat16 h0 = __float2bfloat16(v.x), h1 = __float2bfloat16(v.y);
    __nv_bfloat16 h2 = __float2bfloat16(v.z), h3 = __float2bfloat16(v.w);
    __nv_bfloat16 l0 = __float2bfloat16(v.x - __bfloat162float(h0));
    __nv_bfloat16 l1 = __float2bfloat16(v.y - __bfloat162float(h1));
    __nv_bfloat16 l2 = __float2bfloat16(v.z - __bfloat162float(h2));
    __nv_bfloat16 l3 = __float2bfloat16(v.w - __bfloat162float(h3));
    size_t rb = (size_t)r * K2;
    __nv_bfloat162 H01; H01.x = h0; H01.y = h1;
    __nv_bfloat162 H23; H23.x = h2; H23.y = h3;
    __nv_bfloat162 L01; L01.x = l0; L01.y = l1;
    __nv_bfloat162 L23; L23.x = l2; L23.y = l3;
    *(__nv_bfloat162*)(dst + rb + c)              = H01;
    *(__nv_bfloat162*)(dst + rb + c + 2)          = H23;
    *(__nv_bfloat162*)(dst + rb + loOff + c)      = L01;
    *(__nv_bfloat162*)(dst + rb + loOff + c + 2)  = L23;
    *(__nv_bfloat162*)(dst + rb + dupOff + c)     = H01;
    *(__nv_bfloat162*)(dst + rb + dupOff + c + 2) = H23;
}

// -------------------- mma.sync GEMM: C[16384,512] = A2[16384,K2] @ B2[512,K2]^T --------
// 128x128 tile, BK=32, 3-stage cp.async pipeline, ONE __syncthreads per K-iter.
#define ASTR 40              // padded bf16 per smem row (80B, conflict-free ldmatrix)
#define TILE_B (128 * ASTR)  // bf16 elems per buffer
#define GEMM_DSMEM (6 * TILE_B * 2)   // 3 bufs x (A+B) = 61440 bytes

__global__ __launch_bounds__(256) void k_gemm(const __nv_bfloat16* __restrict__ A,
                                              const __nv_bfloat16* __restrict__ Bw,
                                              float* __restrict__ C,
                                              const float* __restrict__ xres,
                                              const float* __restrict__ bo,
                                              int finalmode) {
    extern __shared__ __nv_bfloat16 dyn[];
    int tid = threadIdx.x, lane = tid & 31, w = tid >> 5;
    int m0 = (w & 3) * 32, n0 = (w >> 2) * 64;
    int r0 = blockIdx.x * 128, e0 = blockIdx.y * 128;
    uint32_t sAu = smem_to_u32(dyn);                     // 3 A buffers
    uint32_t sBu = sAu + 3u * (TILE_B * 2);              // 3 B buffers

    float acc[2][8][4];
#pragma unroll
    for (int i = 0; i < 2; i++)
#pragma unroll
        for (int j = 0; j < 8; j++)
#pragma unroll
            for (int l = 0; l < 4; l++) acc[i][j][l] = 0.f;

    int lrow = tid >> 1;
    int lcol = (tid & 1) << 4;
    const __nv_bfloat16* Arow = A + (size_t)(r0 + lrow) * K2 + lcol;
    const __nv_bfloat16* Brow = Bw + (size_t)(e0 + lrow) * K2 + lcol;
    uint32_t sAdst = sAu + (uint32_t)(lrow * ASTR + lcol) * 2;
    uint32_t sBdst = sBu + (uint32_t)(lrow * ASTR + lcol) * 2;

#define LOAD_TILE(buf, t) do {                                         \
    uint32_t _o = (uint32_t)(buf) * (TILE_B * 2);                      \
    const __nv_bfloat16* _a = Arow + (t) * 32;                         \
    const __nv_bfloat16* _b = Brow + (t) * 32;                         \
    CP_ASYNC16(sAdst + _o,      _a);                                   \
    CP_ASYNC16(sAdst + _o + 16, _a + 8);                               \
    CP_ASYNC16(sBdst + _o,      _b);                                   \
    CP_ASYNC16(sBdst + _o + 16, _b + 8);                               \
} while (0)

    LOAD_TILE(0, 0);
    CP_COMMIT();
    LOAD_TILE(1, 1);
    CP_COMMIT();

    const int NT = K2 / 32;   // 48
    int buf = 0;
#pragma unroll 1
    for (int t = 0; t < NT; ++t) {
        if (t + 1 < NT) CP_WAIT1(); else CP_WAIT0();
        __syncthreads();                 // buffer t%3 ready for all warps; iter t-1 compute done
        if (t + 2 < NT) {
            int nb = buf + 2; if (nb >= 3) nb -= 3;
            LOAD_TILE(nb, t + 2);        // overwrites (t-1)%3 — safe after the sync above
            CP_COMMIT();
        }
        uint32_t ab = sAu + (uint32_t)buf * (TILE_B * 2);
        uint32_t bb = sBu + (uint32_t)buf * (TILE_B * 2);
#pragma unroll
        for (int ks = 0; ks < 32; ks += 16) {
            uint32_t a[2][4];
#pragma unroll
            for (int mt = 0; mt < 2; mt++) {
                uint32_t addr = ab +
                    (uint32_t)((m0 + mt * 16 + (lane & 15)) * ASTR + ks + ((lane >> 4) << 3)) * 2;
                ldm_x4(a[mt][0], a[mt][1], a[mt][2], a[mt][3], addr);
            }
            uint32_t b[8][2];
#pragma unroll
            for (int p = 0; p < 4; p++) {
                int nA = n0 + p * 16;
                uint32_t addr = bb +
                    (uint32_t)((nA + (lane & 7) + ((lane >> 4) << 3)) * ASTR + ks + (lane & 8)) * 2;
                ldm_x4(b[2 * p][0], b[2 * p][1], b[2 * p + 1][0], b[2 * p + 1][1], addr);
            }
#pragma unroll
            for (int mt = 0; mt < 2; mt++)
#pragma unroll
                for (int nt = 0; nt < 8; nt++)
                    mma16816(acc[mt][nt], a[mt], b[nt]);
        }
        if (++buf == 3) buf = 0;
    }

    int gid = lane >> 2, tig = lane & 3;
#pragma unroll
    for (int mt = 0; mt < 2; mt++) {
#pragma unroll
        for (int nt = 0; nt < 8; nt++) {
            int r = r0 + m0 + mt * 16 + gid;
            int e = e0 + n0 + nt * 8 + tig * 2;
            float2 v01 = make_float2(acc[mt][nt][0], acc[mt][nt][1]);
            float2 v23 = make_float2(acc[mt][nt][2], acc[mt][nt][3]);
            if (!finalmode) {
                int b = r >> 12, n = r & 4095;
                int h = e >> 6, dh = e & 63;
                float* d0 = C + (((size_t)((b << 3) + h) * Nn + n) * DHd + dh);
                *(float2*)d0 = v01;
                *(float2*)(d0 + 8 * DHd) = v23;
            } else {
                size_t b0 = (size_t)r * Dd + e;
                float2 x0 = *(const float2*)(xres + b0);
                float2 x1 = *(const float2*)(xres + b0 + 8 * Dd);
                float2 bv = *(const float2*)(bo + e);
                *(float2*)(C + b0) = make_float2(x0.x + bv.x + v01.x, x0.y + bv.y + v01.y);
                *(float2*)(C + b0 + 8 * Dd) = make_float2(x1.x + bv.x + v23.x, x1.y + bv.y + v23.y);
            }
        }
    }
}

// -------------------- phi_k pass 1: td = (k*nrm)@proj^T, diag, per-head max --------------------
__global__ __launch_bounds__(256) void k_phi_k(const float* __restrict__ proj) {
    __shared__ float Ks[64][68];   // [dh][n]
    __shared__ float Ps[64][68];   // [dh][m]
    __shared__ float red[256];
    int tid = threadIdx.x;
    int n0 = blockIdx.x * 64;
    int m0 = blockIdx.y * 64;
    int bh = blockIdx.z;

#pragma unroll
    for (int i = 0; i < 4; i++) {
        int s = tid + i * 256;
        int row = s >> 4;
        int kc = (s & 15) << 2;
        float4 a = *(const float4*)(g_k + ((size_t)bh * Nn + n0 + row) * DHd + kc);
        Ks[kc + 0][row] = a.x * NORMALIZER; Ks[kc + 1][row] = a.y * NORMALIZER;
        Ks[kc + 2][row] = a.z * NORMALIZER; Ks[kc + 3][row] = a.w * NORMALIZER;
        float4 p = make_float4(0.f, 0.f, 0.f, 0.f);
        if (m0 + row < Mm) p = *(const float4*)(proj + (size_t)(m0 + row) * DHd + kc);
        Ps[kc + 0][row] = p.x; Ps[kc + 1][row] = p.y;
        Ps[kc + 2][row] = p.z; Ps[kc + 3][row] = p.w;
    }
    __syncthreads();

    if (m0 == 0 && tid < 64) {
        float ss = 0.f;
#pragma unroll
        for (int d = 0; d < 64; d++) { float q = Ks[d][tid]; ss += q * q; }
        g_diag[(size_t)bh * Nn + n0 + tid] = 0.5f * ss;
    }

    u64t acc2[2][4];
#pragma unroll
    for (int i = 0; i < 2; i++)
#pragma unroll
        for (int j = 0; j < 4; j++) acc2[i][j] = 0ull;
    int ty = tid >> 4, tx = tid & 15;
#pragma unroll
    for (int kk = 0; kk < 64; kk++) {
        float4 a = *(const float4*)&Ks[kk][ty * 4];
        float4 b = *(const float4*)&Ps[kk][tx * 4];
        F32X2_STEP(a, b);
    }

    float mymax = -3.0e38f;
#pragma unroll
    for (int i = 0; i < 4; i++) {
        int n = n0 + ty * 4 + i;
#pragma unroll
        for (int j = 0; j < 4; j++) {
            int m = m0 + tx * 4 + j;
            if (m < Mm) {
                float av = ACC2F(i, j);
                g_kp[((size_t)bh * Nn + n) * Mm + m] = av;
                mymax = fmaxf(mymax, av);
            }
        }
    }
    red[tid] = mymax;
    __syncthreads();
    for (int off = 128; off > 0; off >>= 1) {
        if (tid < off) red[tid] = fmaxf(red[tid], red[tid + off]);
        __syncthreads();
    }
    if (tid == 0) atomicMaxF(&g_kmax[bh], red[0]);
}

// -------------------- phi_k pass 2: exp + column sums --------------------
__global__ __launch_bounds__(256) void k_exp_k() {
    __shared__ float diag_s[64];
    int tid = threadIdx.x;
    int n0 = blockIdx.x * 64;
    int bh = blockIdx.y;
    if (tid < 64) diag_s[tid] = g_diag[(size_t)bh * Nn + n0 + tid];
    __syncthreads();
    float mx = g_kmax[bh];
    for (int m = tid; m < Mm; m += 256) {
        size_t base = ((size_t)bh * Nn + n0) * Mm + m;
        float cs = 0.f;
#pragma unroll 4
        for (int r = 0; r < 64; r++) {
            float td = g_kp[base + (size_t)r * Mm];
            float v = RATIO * (fast_exp(td - diag_s[r] - mx) + EPSF);
            g_kp[base + (size_t)r * Mm] = v;
            cs += v;
        }
        atomicAdd(&g_ksum[bh * Mm + m], cs);
    }
}

// -------------------- phi_q fully fused: td -> rowmax -> exp -> qp + d_inv --------------------
#define QP_SMEM_FLOATS (4352 + 4352 + 17152 + MPAD + 64)
__global__ __launch_bounds__(256) void k_phi_q(const float* __restrict__ proj) {
    extern __shared__ float sm[];
    float* Qs     = sm;                       // 64*68  [dh][n]
    float* Ps     = sm + 4352;                // 64*68  [dh][m]
    float* tds    = sm + 8704;                // 64*MPAD
    float* ksum_s = sm + 8704 + 17152;        // MPAD
    float* diag_s = ksum_s + MPAD;            // 64

    int tid = threadIdx.x;
    int n0 = blockIdx.x * 64;
    int bh = blockIdx.y;

    for (int i = tid; i < Mm; i += 256) ksum_s[i] = g_ksum[bh * Mm + i];

#pragma unroll
    for (int i = 0; i < 4; i++) {
        int s = tid + i * 256;
        int row = s >> 4;
        int kc = (s & 15) << 2;
        float4 a = *(const float4*)(g_q + ((size_t)bh * Nn + n0 + row) * DHd + kc);
        Qs[(kc + 0) * 68 + row] = a.x * NORMALIZER;
        Qs[(kc + 1) * 68 + row] = a.y * NORMALIZER;
        Qs[(kc + 2) * 68 + row] = a.z * NORMALIZER;
        Qs[(kc + 3) * 68 + row] = a.w * NORMALIZER;
    }
    __syncthreads();
    if (tid < 64) {
        float ss = 0.f;
#pragma unroll
        for (int d = 0; d < 64; d++) { float q = Qs[d * 68 + tid]; ss += q * q; }
        diag_s[tid] = 0.5f * ss;
    }

    int ty = tid >> 4, tx = tid & 15;
    for (int mt = 0; mt < 5; mt++) {
        int m0 = mt * 64;
#pragma unroll
        for (int i = 0; i < 4; i++) {
            int s = tid + i * 256;
            int row = s >> 4;
            int kc = (s & 15) << 2;
            float4 p = make_float4(0.f, 0.f, 0.f, 0.f);
            if (m0 + row < Mm) p = *(const float4*)(proj + (size_t)(m0 + row) * DHd + kc);
            Ps[(kc + 0) * 68 + row] = p.x;
            Ps[(kc + 1) * 68 + row] = p.y;
            Ps[(kc + 2) * 68 + row] = p.z;
            Ps[(kc + 3) * 68 + row] = p.w;
        }
        __syncthreads();
        u64t acc2[2][4];
#pragma unroll
        for (int i = 0; i < 2; i++)
#pragma unroll
            for (int j = 0; j < 4; j++) acc2[i][j] = 0ull;
#pragma unroll
        for (int kk = 0; kk < 64; kk++) {
            float4 a = *(const float4*)&Qs[kk * 68 + ty * 4];
            float4 b = *(const float4*)&Ps[kk * 68 + tx * 4];
            F32X2_STEP(a, b);
        }
#pragma unroll
        for (int i = 0; i < 4; i++)
#pragma unroll
            for (int j = 0; j < 4; j++) {
                int m = m0 + tx * 4 + j;
                if (m < Mm) tds[(ty * 4 + i) * MPAD + m] = ACC2F(i, j);
            }
        __syncthreads();
    }

    int row = tid >> 2, lane = tid & 3;
    float pm = -3.0e38f;
    for (int m = lane; m < Mm; m += 4) pm = fmaxf(pm, tds[row * MPAD + m]);
    pm = fmaxf(pm, __shfl_xor_sync(0xffffffffu, pm, 1));
    pm = fmaxf(pm, __shfl_xor_sync(0xffffffffu, pm, 2));
    float dg = diag_s[row];
    float sum = 0.f;
    size_t gb = ((size_t)bh * Nn + n0 + row) * Mm;
    for (int m = lane; m < Mm; m += 4) {
        float v = RATIO * (fast_exp(tds[row * MPAD + m] - dg - pm) + EPSF);
        g_qp[gb + m] = v;
        sum += v * ksum_s[m];
    }
    sum += __shfl_xor_sync(0xffffffffu, sum, 1);
    sum += __shfl_xor_sync(0xffffffffu, sum, 2);
    if (lane == 0) g_dinv[(size_t)bh * Nn + n0 + row] = 1.0f / sum;
}

// -------------------- context: ctx[m,dh] += sum_n kp[n,m]*v[n,dh] (split-K over n) --------------------
__global__ __launch_bounds__(256) void k_ctx() {
    __shared__ float Ksm[64][68];  // [n][m]
    __shared__ float Vs[64][68];   // [n][dh]
    int tid = threadIdx.x;
    int m0 = blockIdx.x * 64;
    int nc = blockIdx.y * 512;
    int bh = blockIdx.z;
    u64t acc2[2][4];
#pragma unroll
    for (int i = 0; i < 2; i++)
#pragma unroll
        for (int j = 0; j < 4; j++) acc2[i][j] = 0ull;
    int ty = tid >> 4, tx = tid & 15;

    for (int n0 = nc; n0 < nc + 512; n0 += 64) {
#pragma unroll
        for (int i = 0; i < 16; i++) {
            int s = tid + i * 256;
            int n = s >> 6, mm = s & 63;
            Ksm[n][mm] = (m0 + mm < Mm)
                             ? g_kp[((size_t)bh * Nn + n0 + n) * Mm + m0 + mm]
                             : 0.f;
        }
#pragma unroll
        for (int i = 0; i < 4; i++) {
            int s = tid + i * 256;
            int n = s >> 4, c = (s & 15) << 2;
            float4 v = *(const float4*)(g_v + ((size_t)bh * Nn + n0 + n) * DHd + c);
            Vs[n][c] = v.x; Vs[n][c + 1] = v.y; Vs[n][c + 2] = v.z; Vs[n][c + 3] = v.w;
        }
        __syncthreads();
#pragma unroll
        for (int kk = 0; kk < 64; kk++) {
            float4 a = *(const float4*)&Ksm[kk][ty * 4];
            float4 b = *(const float4*)&Vs[kk][tx * 4];
            F32X2_STEP(a, b);
        }
        __syncthreads();
    }
#pragma unroll
    for (int i = 0; i < 4; i++) {
        int m = m0 + ty * 4 + i;
        if (m < Mm)
#pragma unroll
            for (int j = 0; j < 4; j++)
                atomicAdd(&g_ctx[((size_t)bh * Mm + m) * DHd + tx * 4 + j], ACC2F(i, j));
    }
}

// -------------------- out: attn2 (split bf16) = d_inv[n] * sum_m qp[n,m]*ctx[m,dh] --------------------
__global__ __launch_bounds__(256) void k_out() {
    __shared__ float Qs[64][68];  // [k][n]
    __shared__ float Cs[64][68];  // [k][dh]
    int tid = threadIdx.x;
    int n0 = blockIdx.x * 64;
    int bh = blockIdx.y;
    u64t acc2[2][4];
#pragma unroll
    for (int i = 0; i < 2; i++)
#pragma unroll
        for (int j = 0; j < 4; j++) acc2[i][j] = 0ull;
    int ty = tid >> 4, tx = tid & 15;

    for (int c0 = 0; c0 < Mm; c0 += 64) {
#pragma unroll
        for (int i = 0; i < 16; i++) {
            int s = tid + i * 256;
            int r = s >> 6, kc = s & 63;
            Qs[kc][r] = (c0 + kc < Mm)
                            ? g_qp[((size_t)bh * Nn + n0 + r) * Mm + c0 + kc]
                            : 0.f;
        }
#pragma unroll
        for (int i = 0; i < 16; i++) {
            int s = tid + i * 256;
            int kk = s >> 6, dh = s & 63;
            Cs[kk][dh] = (c0 + kk < Mm)
                             ? g_ctx[((size_t)bh * Mm + c0 + kk) * DHd + dh]
                             : 0.f;
        }
        __syncthreads();
#pragma unroll
        for (int kk = 0; kk < 64; kk++) {
            float4 a = *(const float4*)&Qs[kk][ty * 4];
            float4 b = *(const float4*)&Cs[kk][tx * 4];
            F32X2_STEP(a, b);
        }
        __syncthreads();
    }
    int b = bh >> 3, h = bh & 7;
#pragma unroll
    for (int i = 0; i < 4; i++) {
        int n = n0 + ty * 4 + i;
        float dv = g_dinv[(size_t)bh * Nn + n];
        size_t rb = (size_t)(b * Nn + n) * K2 + h * 64 + tx * 4;
#pragma unroll
        for (int j = 0; j < 4; j++) {
            float val = ACC2F(i, j) * dv;
            __nv_bfloat16 hv = __float2bfloat16(val);
            __nv_bfloat16 lv = __float2bfloat16(val - __bfloat162float(hv));
            g_attn2[rb + j]        = hv;   // hi
            g_attn2[rb + 512 + j]  = lv;   // lo  (pairs with Wo hi)
            g_attn2[rb + 1024 + j] = hv;   // hi  (pairs with Wo lo)
        }
    }
}

// -------------------- launch --------------------
extern "C" void kernel_launch(void* const* d_in, const int* in_sizes, int n_in,
                              void* d_out, int out_size) {
    const float* x    = (const float*)d_in[0];
    const float* Wq   = (const float*)d_in[1];
    const float* Wk   = (const float*)d_in[2];
    const float* Wv   = (const float*)d_in[3];
    const float* Wo   = (const float*)d_in[4];
    const float* bo   = (const float*)d_in[5];
    const float* proj = (const float*)d_in[6];
    float* out = (float*)d_out;
    (void)in_sizes; (void)n_in; (void)out_size;

    cudaFuncSetAttribute(k_phi_q, cudaFuncAttributeMaxDynamicSharedMemorySize,
                         QP_SMEM_FLOATS * (int)sizeof(float));
    cudaFuncSetAttribute(k_gemm, cudaFuncAttributeMaxDynamicSharedMemorySize, GEMM_DSMEM);

    __nv_bfloat16 *x2p, *wq2p, *wk2p, *wv2p, *wo2p, *attn2p;
    cudaGetSymbolAddress((void**)&x2p, g_x2);
    cudaGetSymbolAddress((void**)&wq2p, g_wq2);
    cudaGetSymbolAddress((void**)&wk2p, g_wk2);
    cudaGetSymbolAddress((void**)&wv2p, g_wv2);
    cudaGetSymbolAddress((void**)&wo2p, g_wo2);
    cudaGetSymbolAddress((void**)&attn2p, g_attn2);
    float *qp_, *kp_, *vp_;
    cudaGetSymbolAddress((void**)&qp_, g_q);
    cudaGetSymbolAddress((void**)&kp_, g_k);
    cudaGetSymbolAddress((void**)&vp_, g_v);

    k_init<<<(BHh * Mm * DHd + 255) / 256, 256>>>();
    k_split<<<(BNn * 128 + 255) / 256, 256>>>(x, x2p, BNn, 512, 1024);
    k_split<<<(Dd * 128 + 255) / 256, 256>>>(Wq, wq2p, Dd, 1024, 512);
    k_split<<<(Dd * 128 + 255) / 256, 256>>>(Wk, wk2p, Dd, 1024, 512);
    k_split<<<(Dd * 128 + 255) / 256, 256>>>(Wv, wv2p, Dd, 1024, 512);

    dim3 gG(BNn / 128, Dd / 128);
    k_gemm<<<gG, 256, GEMM_DSMEM>>>(x2p, wq2p, qp_, nullptr, nullptr, 0);
    k_gemm<<<gG, 256, GEMM_DSMEM>>>(x2p, wk2p, kp_, nullptr, nullptr, 0);
    k_gemm<<<gG, 256, GEMM_DSMEM>>>(x2p, wv2p, vp_, nullptr, nullptr, 0);

    k_split<<<(Dd * 128 + 255) / 256, 256>>>(Wo, wo2p, Dd, 1024, 512);

    k_phi_k<<<dim3(Nn / 64, 5, BHh), 256>>>(proj);
    k_exp_k<<<dim3(Nn / 64, BHh), 256>>>();
    k_phi_q<<<dim3(Nn / 64, BHh), 256, QP_SMEM_FLOATS * (int)sizeof(float)>>>(proj);

    k_ctx<<<dim3(5, Nn / 512, BHh), 256>>>();
    k_out<<<dim3(Nn / 64, BHh), 256>>>();

    k_gemm<<<gG, 256, GEMM_DSMEM>>>(attn2p, wo2p, out, x, bo, 1);
}

// round 12
// speedup vs baseline: 1.1900x; 1.0466x over previous
#include <cuda_runtime.h>
#include <cuda_bf16.h>
#include <stdint.h>
#include <math.h>

#define Bb   4
#define Nn   4096
#define Dd   512
#define Hh   8
#define DHd  64
#define Mm   266
#define BHh  32          // B*H
#define BNn  16384       // B*N
#define MPAD 268
#define K2   1536        // split-bf16 expanded K (hi|lo|hi)

// -------------------- scratch (static device memory; no allocs) --------------------
__device__ float g_q  [(size_t)BHh * Nn * DHd];
__device__ float g_k  [(size_t)BHh * Nn * DHd];
__device__ float g_v  [(size_t)BHh * Nn * DHd];
__device__ float g_qp [(size_t)BHh * Nn * Mm];
__device__ float g_kp [(size_t)BHh * Nn * Mm];   // holds td_k; exp applied inside k_ctx
__device__ float g_ctx [(size_t)BHh * Mm * DHd];
__device__ float g_ksum[(size_t)BHh * Mm];
__device__ float g_kmax[BHh];
__device__ float g_diag[(size_t)BHh * Nn];
__device__ float g_dinv[(size_t)BHh * Nn];

__device__ __nv_bfloat16 g_x2   [(size_t)BNn * K2];
__device__ __nv_bfloat16 g_attn2[(size_t)BNn * K2];
__device__ __nv_bfloat16 g_wq2  [(size_t)Dd * K2];
__device__ __nv_bfloat16 g_wk2  [(size_t)Dd * K2];
__device__ __nv_bfloat16 g_wv2  [(size_t)Dd * K2];
__device__ __nv_bfloat16 g_wo2  [(size_t)Dd * K2];

// -------------------- helpers --------------------
typedef unsigned long long u64t;

__device__ __forceinline__ uint32_t smem_to_u32(const void* p) {
    uint32_t a;
    asm("{ .reg .u64 t; cvta.to.shared.u64 t, %1; cvt.u32.u64 %0, t; }"
        : "=r"(a) : "l"(p));
    return a;
}

#define CP_ASYNC16(dst, src) \
    asm volatile("cp.async.cg.shared.global [%0], [%1], 16;" \
                 :: "r"(dst), "l"(src) : "memory")
#define CP_COMMIT()  asm volatile("cp.async.commit_group;" ::: "memory")
#define CP_WAIT1()   asm volatile("cp.async.wait_group 1;" ::: "memory")
#define CP_WAIT0()   asm volatile("cp.async.wait_group 0;" ::: "memory")

__device__ __forceinline__ void ldm_x4(uint32_t& r0, uint32_t& r1,
                                       uint32_t& r2, uint32_t& r3, uint32_t addr) {
    asm volatile("ldmatrix.sync.aligned.m8n8.x4.shared.b16 {%0,%1,%2,%3}, [%4];"
                 : "=r"(r0), "=r"(r1), "=r"(r2), "=r"(r3) : "r"(addr));
}

__device__ __forceinline__ void mma16816(float* c, const uint32_t* a, const uint32_t* b) {
    asm volatile(
        "mma.sync.aligned.m16n8k16.row.col.f32.bf16.bf16.f32 "
        "{%0,%1,%2,%3}, {%4,%5,%6,%7}, {%8,%9}, {%0,%1,%2,%3};"
        : "+f"(c[0]), "+f"(c[1]), "+f"(c[2]), "+f"(c[3])
        : "r"(a[0]), "r"(a[1]), "r"(a[2]), "r"(a[3]), "r"(b[0]), "r"(b[1]));
}

// ---- packed fp32x2 FMA (Blackwell base ISA) ----
__device__ __forceinline__ u64t pack2(float x, float y) {
    u64t r;
    asm("mov.b64 %0, {%1, %2};" : "=l"(r) : "f"(x), "f"(y));
    return r;
}
__device__ __forceinline__ u64t bcast2(float v) {
    u64t r;
    asm("mov.b64 %0, {%1, %1};" : "=l"(r) : "f"(v));
    return r;
}
__device__ __forceinline__ void ffma2(u64t& c, u64t a, u64t b) {
    asm("fma.rn.f32x2 %0, %1, %2, %0;" : "+l"(c) : "l"(a), "l"(b));
}
__device__ __forceinline__ float lane0(u64t v) { float2 t; *(u64t*)&t = v; return t.x; }
__device__ __forceinline__ float lane1(u64t v) { float2 t; *(u64t*)&t = v; return t.y; }
#define ACC2F(i, j) (((i) & 1) ? lane1(acc2[(i) >> 1][j]) : lane0(acc2[(i) >> 1][j]))

#define F32X2_STEP(a4, b4) do {                                   \
    u64t a01 = pack2((a4).x, (a4).y), a23 = pack2((a4).z, (a4).w);\
    u64t bb0 = bcast2((b4).x), bb1 = bcast2((b4).y);              \
    u64t bb2 = bcast2((b4).z), bb3 = bcast2((b4).w);              \
    ffma2(acc2[0][0], a01, bb0); ffma2(acc2[0][1], a01, bb1);     \
    ffma2(acc2[0][2], a01, bb2); ffma2(acc2[0][3], a01, bb3);     \
    ffma2(acc2[1][0], a23, bb0); ffma2(acc2[1][1], a23, bb1);     \
    ffma2(acc2[1][2], a23, bb2); ffma2(acc2[1][3], a23, bb3);     \
} while (0)

__device__ __forceinline__ void atomicMaxF(float* addr, float val) {
    int* ai = (int*)addr;
    int old = *ai;
    while (__int_as_float(old) < val) {
        int assumed = old;
        old = atomicCAS(ai, assumed, __float_as_int(val));
        if (old == assumed) break;
    }
}

__device__ __forceinline__ float fast_exp(float x) {
    float y = fmaxf(x * 1.4426950408889634f, -126.0f);
    float r = rintf(y);
    float f = y - r;
    float p = 1.5403530e-4f;
    p = fmaf(p, f, 1.3333558e-3f);
    p = fmaf(p, f, 9.6181291e-3f);
    p = fmaf(p, f, 5.5504109e-2f);
    p = fmaf(p, f, 2.4022651e-1f);
    p = fmaf(p, f, 6.9314718e-1f);
    p = fmaf(p, f, 1.0f);
    int e = (int)r;
    float s = __int_as_float((e + 127) << 23);
    return p * s;
}

#define NORMALIZER 0.35355339059327373f   // 64^-0.25
#define RATIO      0.061313934f           // 266^-0.5
#define EPSF       1e-4f

// -------------------- init scratch accumulators --------------------
__global__ void k_init() {
    int i = blockIdx.x * 256 + threadIdx.x;
    if (i < BHh * Mm * DHd) g_ctx[i]  = 0.0f;
    if (i < BHh * Mm)       g_ksum[i] = 0.0f;
    if (i < BHh)            g_kmax[i] = -3.0e38f;
}

// -------------------- fp32 -> split bf16 (hi|lo|hi at given offsets) --------------------
__global__ __launch_bounds__(256) void k_split(const float* __restrict__ src,
                                               __nv_bfloat16* __restrict__ dst,
                                               int nrows, int loOff, int dupOff) {
    int i = blockIdx.x * 256 + threadIdx.x;
    int total = nrows * 128;   // 4 floats per thread
    if (i >= total) return;
    int r = i >> 7;
    int c = (i & 127) << 2;
    float4 v = *(const float4*)(src + (size_t)r * 512 + c);
    __nv_bfloat16 h0 = __float2bfloat16(v.x), h1 = __float2bfloat16(v.y);
    __nv_bfloat16 h2 = __float2bfloat16(v.z), h3 = __float2bfloat16(v.w);
    __nv_bfloat16 l0 = __float2bfloat16(v.x - __bfloat162float(h0));
    __nv_bfloat16 l1 = __float2bfloat16(v.y - __bfloat162float(h1));
    __nv_bfloat16 l2 = __float2bfloat16(v.z - __bfloat162float(h2));
    __nv_bfloat16 l3 = __float2bfloat16(v.w - __bfloat162float(h3));
    size_t rb = (size_t)r * K2;
    __nv_bfloat162 H01; H01.x = h0; H01.y = h1;
    __nv_bfloat162 H23; H23.x = h2; H23.y = h3;
    __nv_bfloat162 L01; L01.x = l0; L01.y = l1;
    __nv_bfloat162 L23; L23.x = l2; L23.y = l3;
    *(__nv_bfloat162*)(dst + rb + c)              = H01;
    *(__nv_bfloat162*)(dst + rb + c + 2)          = H23;
    *(__nv_bfloat162*)(dst + rb + loOff + c)      = L01;
    *(__nv_bfloat162*)(dst + rb + loOff + c + 2)  = L23;
    *(__nv_bfloat162*)(dst + rb + dupOff + c)     = H01;
    *(__nv_bfloat162*)(dst + rb + dupOff + c + 2) = H23;
}

// -------------------- mma.sync GEMM: C[16384,512] = A2[16384,K2] @ B2[512,K2]^T --------
// 128x128 tile, BK=32, 3-stage cp.async pipeline, one __syncthreads per K-iter.
#define ASTR 40
#define TILE_B (128 * ASTR)
#define GEMM_DSMEM (6 * TILE_B * 2)   // 61440 bytes

__global__ __launch_bounds__(256) void k_gemm(const __nv_bfloat16* __restrict__ A,
                                              const __nv_bfloat16* __restrict__ Bw,
                                              float* __restrict__ C,
                                              const float* __restrict__ xres,
                                              const float* __restrict__ bo,
                                              int finalmode) {
    extern __shared__ __nv_bfloat16 dyn[];
    int tid = threadIdx.x, lane = tid & 31, w = tid >> 5;
    int m0 = (w & 3) * 32, n0 = (w >> 2) * 64;
    int r0 = blockIdx.x * 128, e0 = blockIdx.y * 128;
    uint32_t sAu = smem_to_u32(dyn);
    uint32_t sBu = sAu + 3u * (TILE_B * 2);

    float acc[2][8][4];
#pragma unroll
    for (int i = 0; i < 2; i++)
#pragma unroll
        for (int j = 0; j < 8; j++)
#pragma unroll
            for (int l = 0; l < 4; l++) acc[i][j][l] = 0.f;

    int lrow = tid >> 1;
    int lcol = (tid & 1) << 4;
    const __nv_bfloat16* Arow = A + (size_t)(r0 + lrow) * K2 + lcol;
    const __nv_bfloat16* Brow = Bw + (size_t)(e0 + lrow) * K2 + lcol;
    uint32_t sAdst = sAu + (uint32_t)(lrow * ASTR + lcol) * 2;
    uint32_t sBdst = sBu + (uint32_t)(lrow * ASTR + lcol) * 2;

#define LOAD_TILE(buf, t) do {                                         \
    uint32_t _o = (uint32_t)(buf) * (TILE_B * 2);                      \
    const __nv_bfloat16* _a = Arow + (t) * 32;                         \
    const __nv_bfloat16* _b = Brow + (t) * 32;                         \
    CP_ASYNC16(sAdst + _o,      _a);                                   \
    CP_ASYNC16(sAdst + _o + 16, _a + 8);                               \
    CP_ASYNC16(sBdst + _o,      _b);                                   \
    CP_ASYNC16(sBdst + _o + 16, _b + 8);                               \
} while (0)

    LOAD_TILE(0, 0);
    CP_COMMIT();
    LOAD_TILE(1, 1);
    CP_COMMIT();

    const int NT = K2 / 32;   // 48
    int buf = 0;
#pragma unroll 1
    for (int t = 0; t < NT; ++t) {
        if (t + 1 < NT) CP_WAIT1(); else CP_WAIT0();
        __syncthreads();
        if (t + 2 < NT) {
            int nb = buf + 2; if (nb >= 3) nb -= 3;
            LOAD_TILE(nb, t + 2);
            CP_COMMIT();
        }
        uint32_t ab = sAu + (uint32_t)buf * (TILE_B * 2);
        uint32_t bb = sBu + (uint32_t)buf * (TILE_B * 2);
#pragma unroll
        for (int ks = 0; ks < 32; ks += 16) {
            uint32_t a[2][4];
#pragma unroll
            for (int mt = 0; mt < 2; mt++) {
                uint32_t addr = ab +
                    (uint32_t)((m0 + mt * 16 + (lane & 15)) * ASTR + ks + ((lane >> 4) << 3)) * 2;
                ldm_x4(a[mt][0], a[mt][1], a[mt][2], a[mt][3], addr);
            }
            uint32_t b[8][2];
#pragma unroll
            for (int p = 0; p < 4; p++) {
                int nA = n0 + p * 16;
                uint32_t addr = bb +
                    (uint32_t)((nA + (lane & 7) + ((lane >> 4) << 3)) * ASTR + ks + (lane & 8)) * 2;
                ldm_x4(b[2 * p][0], b[2 * p][1], b[2 * p + 1][0], b[2 * p + 1][1], addr);
            }
#pragma unroll
            for (int mt = 0; mt < 2; mt++)
#pragma unroll
                for (int nt = 0; nt < 8; nt++)
                    mma16816(acc[mt][nt], a[mt], b[nt]);
        }
        if (++buf == 3) buf = 0;
    }

    int gid = lane >> 2, tig = lane & 3;
#pragma unroll
    for (int mt = 0; mt < 2; mt++) {
#pragma unroll
        for (int nt = 0; nt < 8; nt++) {
            int r = r0 + m0 + mt * 16 + gid;
            int e = e0 + n0 + nt * 8 + tig * 2;
            float2 v01 = make_float2(acc[mt][nt][0], acc[mt][nt][1]);
            float2 v23 = make_float2(acc[mt][nt][2], acc[mt][nt][3]);
            if (!finalmode) {
                int b = r >> 12, n = r & 4095;
                int h = e >> 6, dh = e & 63;
                float* d0 = C + (((size_t)((b << 3) + h) * Nn + n) * DHd + dh);
                *(float2*)d0 = v01;
                *(float2*)(d0 + 8 * DHd) = v23;
            } else {
                size_t b0 = (size_t)r * Dd + e;
                float2 x0 = *(const float2*)(xres + b0);
                float2 x1 = *(const float2*)(xres + b0 + 8 * Dd);
                float2 bv = *(const float2*)(bo + e);
                *(float2*)(C + b0) = make_float2(x0.x + bv.x + v01.x, x0.y + bv.y + v01.y);
                *(float2*)(C + b0 + 8 * Dd) = make_float2(x1.x + bv.x + v23.x, x1.y + bv.y + v23.y);
            }
        }
    }
}

// -------------------- phi_k: td = (k*nrm)@proj^T -> g_kp, diag, per-head max -------
__global__ __launch_bounds__(256) void k_phi_k(const float* __restrict__ proj) {
    __shared__ float Ks[64][68];   // [dh][n]
    __shared__ float Ps[64][68];   // [dh][m]
    __shared__ float red[256];
    int tid = threadIdx.x;
    int n0 = blockIdx.x * 64;
    int m0 = blockIdx.y * 64;
    int bh = blockIdx.z;

#pragma unroll
    for (int i = 0; i < 4; i++) {
        int s = tid + i * 256;
        int row = s >> 4;
        int kc = (s & 15) << 2;
        float4 a = *(const float4*)(g_k + ((size_t)bh * Nn + n0 + row) * DHd + kc);
        Ks[kc + 0][row] = a.x * NORMALIZER; Ks[kc + 1][row] = a.y * NORMALIZER;
        Ks[kc + 2][row] = a.z * NORMALIZER; Ks[kc + 3][row] = a.w * NORMALIZER;
        float4 p = make_float4(0.f, 0.f, 0.f, 0.f);
        if (m0 + row < Mm) p = *(const float4*)(proj + (size_t)(m0 + row) * DHd + kc);
        Ps[kc + 0][row] = p.x; Ps[kc + 1][row] = p.y;
        Ps[kc + 2][row] = p.z; Ps[kc + 3][row] = p.w;
    }
    __syncthreads();

    if (m0 == 0 && tid < 64) {
        float ss = 0.f;
#pragma unroll
        for (int d = 0; d < 64; d++) { float q = Ks[d][tid]; ss += q * q; }
        g_diag[(size_t)bh * Nn + n0 + tid] = 0.5f * ss;
    }

    u64t acc2[2][4];
#pragma unroll
    for (int i = 0; i < 2; i++)
#pragma unroll
        for (int j = 0; j < 4; j++) acc2[i][j] = 0ull;
    int ty = tid >> 4, tx = tid & 15;
#pragma unroll
    for (int kk = 0; kk < 64; kk++) {
        float4 a = *(const float4*)&Ks[kk][ty * 4];
        float4 b = *(const float4*)&Ps[kk][tx * 4];
        F32X2_STEP(a, b);
    }

    float mymax = -3.0e38f;
#pragma unroll
    for (int i = 0; i < 4; i++) {
        int n = n0 + ty * 4 + i;
#pragma unroll
        for (int j = 0; j < 4; j++) {
            int m = m0 + tx * 4 + j;
            if (m < Mm) {
                float av = ACC2F(i, j);
                g_kp[((size_t)bh * Nn + n) * Mm + m] = av;
                mymax = fmaxf(mymax, av);
            }
        }
    }
    red[tid] = mymax;
    __syncthreads();
    for (int off = 128; off > 0; off >>= 1) {
        if (tid < off) red[tid] = fmaxf(red[tid], red[tid + off]);
        __syncthreads();
    }
    if (tid == 0) atomicMaxF(&g_kmax[bh], red[0]);
}

// -------------------- ctx fused: exp(td) in-fill (MLP-batched) + MMA + ksum --------
__global__ __launch_bounds__(256) void k_ctx() {
    __shared__ float Ksm[64][68];   // [n][m]  (kp values)
    __shared__ float Vs[64][68];    // [n][dh]
    __shared__ float diag_s[512];   // diag for the whole n-slab
    __shared__ float rsum[256];
    int tid = threadIdx.x;
    int m0 = blockIdx.x * 64;
    int nc = blockIdx.y * 512;
    int bh = blockIdx.z;
    float mx = g_kmax[bh];

    diag_s[tid]       = g_diag[(size_t)bh * Nn + nc + tid];
    diag_s[tid + 256] = g_diag[(size_t)bh * Nn + nc + 256 + tid];

    u64t acc2[2][4];
#pragma unroll
    for (int i = 0; i < 2; i++)
#pragma unroll
        for (int j = 0; j < 4; j++) acc2[i][j] = 0ull;
    int ty = tid >> 4, tx = tid & 15;

    int mmc = m0 + (tid & 63);       // this thread's kp column (constant across fill)
    bool mok = mmc < Mm;
    int nbase = tid >> 6;            // n offset within each group of 4
    float cs = 0.f;
    __syncthreads();

    for (int nt = 0; nt < 8; nt++) {
        int n0 = nc + nt * 64;
        // phase A: 16 independent td loads (MLP=16)
        float tdv[16];
        const float* kpb = g_kp + ((size_t)bh * Nn + n0 + nbase) * Mm + mmc;
#pragma unroll
        for (int i = 0; i < 16; i++)
            tdv[i] = mok ? kpb[(size_t)(i * 4) * Mm] : 0.f;
        // phase B: exp + store
#pragma unroll
        for (int i = 0; i < 16; i++) {
            int n = i * 4 + nbase;
            float v = 0.f;
            if (mok) {
                v = RATIO * (fast_exp(tdv[i] - diag_s[nt * 64 + n] - mx) + EPSF);
                cs += v;
            }
            Ksm[n][tid & 63] = v;
        }
#pragma unroll
        for (int i = 0; i < 4; i++) {
            int s = tid + i * 256;
            int n = s >> 4, c = (s & 15) << 2;
            float4 v = *(const float4*)(g_v + ((size_t)bh * Nn + n0 + n) * DHd + c);
            Vs[n][c] = v.x; Vs[n][c + 1] = v.y; Vs[n][c + 2] = v.z; Vs[n][c + 3] = v.w;
        }
        __syncthreads();
#pragma unroll
        for (int kk = 0; kk < 64; kk++) {
            float4 a = *(const float4*)&Ksm[kk][ty * 4];
            float4 b = *(const float4*)&Vs[kk][tx * 4];
            F32X2_STEP(a, b);
        }
        __syncthreads();
    }
#pragma unroll
    for (int i = 0; i < 4; i++) {
        int m = m0 + ty * 4 + i;
        if (m < Mm)
#pragma unroll
            for (int j = 0; j < 4; j++)
                atomicAdd(&g_ctx[((size_t)bh * Mm + m) * DHd + tx * 4 + j], ACC2F(i, j));
    }
    rsum[tid] = cs;
    __syncthreads();
    if (tid < 64) {
        int m = m0 + tid;
        if (m < Mm) {
            float t = rsum[tid] + rsum[tid + 64] + rsum[tid + 128] + rsum[tid + 192];
            atomicAdd(&g_ksum[bh * Mm + m], t);
        }
    }
}

// -------------------- phi_q fully fused: td -> rowmax -> exp -> qp + d_inv --------------------
#define QP_SMEM_FLOATS (4352 + 4352 + 17152 + MPAD + 64)
__global__ __launch_bounds__(256) void k_phi_q(const float* __restrict__ proj) {
    extern __shared__ float sm[];
    float* Qs     = sm;                       // 64*68  [dh][n]
    float* Ps     = sm + 4352;                // 64*68  [dh][m]
    float* tds    = sm + 8704;                // 64*MPAD
    float* ksum_s = sm + 8704 + 17152;        // MPAD
    float* diag_s = ksum_s + MPAD;            // 64

    int tid = threadIdx.x;
    int n0 = blockIdx.x * 64;
    int bh = blockIdx.y;

    for (int i = tid; i < Mm; i += 256) ksum_s[i] = g_ksum[bh * Mm + i];

#pragma unroll
    for (int i = 0; i < 4; i++) {
        int s = tid + i * 256;
        int row = s >> 4;
        int kc = (s & 15) << 2;
        float4 a = *(const float4*)(g_q + ((size_t)bh * Nn + n0 + row) * DHd + kc);
        Qs[(kc + 0) * 68 + row] = a.x * NORMALIZER;
        Qs[(kc + 1) * 68 + row] = a.y * NORMALIZER;
        Qs[(kc + 2) * 68 + row] = a.z * NORMALIZER;
        Qs[(kc + 3) * 68 + row] = a.w * NORMALIZER;
    }
    __syncthreads();
    if (tid < 64) {
        float ss = 0.f;
#pragma unroll
        for (int d = 0; d < 64; d++) { float q = Qs[d * 68 + tid]; ss += q * q; }
        diag_s[tid] = 0.5f * ss;
    }

    int ty = tid >> 4, tx = tid & 15;
    for (int mt = 0; mt < 5; mt++) {
        int m0 = mt * 64;
#pragma unroll
        for (int i = 0; i < 4; i++) {
            int s = tid + i * 256;
            int row = s >> 4;
            int kc = (s & 15) << 2;
            float4 p = make_float4(0.f, 0.f, 0.f, 0.f);
            if (m0 + row < Mm) p = *(const float4*)(proj + (size_t)(m0 + row) * DHd + kc);
            Ps[(kc + 0) * 68 + row] = p.x;
            Ps[(kc + 1) * 68 + row] = p.y;
            Ps[(kc + 2) * 68 + row] = p.z;
            Ps[(kc + 3) * 68 + row] = p.w;
        }
        __syncthreads();
        u64t acc2[2][4];
#pragma unroll
        for (int i = 0; i < 2; i++)
#pragma unroll
            for (int j = 0; j < 4; j++) acc2[i][j] = 0ull;
#pragma unroll
        for (int kk = 0; kk < 64; kk++) {
            float4 a = *(const float4*)&Qs[kk * 68 + ty * 4];
            float4 b = *(const float4*)&Ps[kk * 68 + tx * 4];
            F32X2_STEP(a, b);
        }
#pragma unroll
        for (int i = 0; i < 4; i++)
#pragma unroll
            for (int j = 0; j < 4; j++) {
                int m = m0 + tx * 4 + j;
                if (m < Mm) tds[(ty * 4 + i) * MPAD + m] = ACC2F(i, j);
            }
        __syncthreads();
    }

    int row = tid >> 2, lane = tid & 3;
    float pm = -3.0e38f;
    for (int m = lane; m < Mm; m += 4) pm = fmaxf(pm, tds[row * MPAD + m]);
    pm = fmaxf(pm, __shfl_xor_sync(0xffffffffu, pm, 1));
    pm = fmaxf(pm, __shfl_xor_sync(0xffffffffu, pm, 2));
    float dg = diag_s[row];
    float sum = 0.f;
    size_t gb = ((size_t)bh * Nn + n0 + row) * Mm;
    for (int m = lane; m < Mm; m += 4) {
        float v = RATIO * (fast_exp(tds[row * MPAD + m] - dg - pm) + EPSF);
        g_qp[gb + m] = v;
        sum += v * ksum_s[m];
    }
    sum += __shfl_xor_sync(0xffffffffu, sum, 1);
    sum += __shfl_xor_sync(0xffffffffu, sum, 2);
    if (lane == 0) g_dinv[(size_t)bh * Nn + n0 + row] = 1.0f / sum;
}

// -------------------- out: attn2 (split bf16) = d_inv[n] * sum_m qp[n,m]*ctx[m,dh] --------------------
__global__ __launch_bounds__(256) void k_out() {
    __shared__ float Qs[64][68];  // [k][n]
    __shared__ float Cs[64][68];  // [k][dh]
    int tid = threadIdx.x;
    int n0 = blockIdx.x * 64;
    int bh = blockIdx.y;
    u64t acc2[2][4];
#pragma unroll
    for (int i = 0; i < 2; i++)
#pragma unroll
        for (int j = 0; j < 4; j++) acc2[i][j] = 0ull;
    int ty = tid >> 4, tx = tid & 15;

    for (int c0 = 0; c0 < Mm; c0 += 64) {
#pragma unroll
        for (int i = 0; i < 16; i++) {
            int s = tid + i * 256;
            int r = s >> 6, kc = s & 63;
            Qs[kc][r] = (c0 + kc < Mm)
                            ? g_qp[((size_t)bh * Nn + n0 + r) * Mm + c0 + kc]
                            : 0.f;
        }
#pragma unroll
        for (int i = 0; i < 16; i++) {
            int s = tid + i * 256;
            int kk = s >> 6, dh = s & 63;
            Cs[kk][dh] = (c0 + kk < Mm)
                             ? g_ctx[((size_t)bh * Mm + c0 + kk) * DHd + dh]
                             : 0.f;
        }
        __syncthreads();
#pragma unroll
        for (int kk = 0; kk < 64; kk++) {
            float4 a = *(const float4*)&Qs[kk][ty * 4];
            float4 b = *(const float4*)&Cs[kk][tx * 4];
            F32X2_STEP(a, b);
        }
        __syncthreads();
    }
    int b = bh >> 3, h = bh & 7;
#pragma unroll
    for (int i = 0; i < 4; i++) {
        int n = n0 + ty * 4 + i;
        float dv = g_dinv[(size_t)bh * Nn + n];
        size_t rb = (size_t)(b * Nn + n) * K2 + h * 64 + tx * 4;
#pragma unroll
        for (int j = 0; j < 4; j++) {
            float val = ACC2F(i, j) * dv;
            __nv_bfloat16 hv = __float2bfloat16(val);
            __nv_bfloat16 lv = __float2bfloat16(val - __bfloat162float(hv));
            g_attn2[rb + j]        = hv;   // hi
            g_attn2[rb + 512 + j]  = lv;   // lo  (pairs with Wo hi)
            g_attn2[rb + 1024 + j] = hv;   // hi  (pairs with Wo lo)
        }
    }
}

// -------------------- launch --------------------
extern "C" void kernel_launch(void* const* d_in, const int* in_sizes, int n_in,
                              void* d_out, int out_size) {
    const float* x    = (const float*)d_in[0];
    const float* Wq   = (const float*)d_in[1];
    const float* Wk   = (const float*)d_in[2];
    const float* Wv   = (const float*)d_in[3];
    const float* Wo   = (const float*)d_in[4];
    const float* bo   = (const float*)d_in[5];
    const float* proj = (const float*)d_in[6];
    float* out = (float*)d_out;
    (void)in_sizes; (void)n_in; (void)out_size;

    cudaFuncSetAttribute(k_phi_q, cudaFuncAttributeMaxDynamicSharedMemorySize,
                         QP_SMEM_FLOATS * (int)sizeof(float));
    cudaFuncSetAttribute(k_gemm, cudaFuncAttributeMaxDynamicSharedMemorySize, GEMM_DSMEM);

    __nv_bfloat16 *x2p, *wq2p, *wk2p, *wv2p, *wo2p, *attn2p;
    cudaGetSymbolAddress((void**)&x2p, g_x2);
    cudaGetSymbolAddress((void**)&wq2p, g_wq2);
    cudaGetSymbolAddress((void**)&wk2p, g_wk2);
    cudaGetSymbolAddress((void**)&wv2p, g_wv2);
    cudaGetSymbolAddress((void**)&wo2p, g_wo2);
    cudaGetSymbolAddress((void**)&attn2p, g_attn2);
    float *qp_, *kp_, *vp_;
    cudaGetSymbolAddress((void**)&qp_, g_q);
    cudaGetSymbolAddress((void**)&kp_, g_k);
    cudaGetSymbolAddress((void**)&vp_, g_v);

    k_init<<<(BHh * Mm * DHd + 255) / 256, 256>>>();
    k_split<<<(BNn * 128 + 255) / 256, 256>>>(x, x2p, BNn, 512, 1024);
    k_split<<<(Dd * 128 + 255) / 256, 256>>>(Wq, wq2p, Dd, 1024, 512);
    k_split<<<(Dd * 128 + 255) / 256, 256>>>(Wk, wk2p, Dd, 1024, 512);
    k_split<<<(Dd * 128 + 255) / 256, 256>>>(Wv, wv2p, Dd, 1024, 512);

    dim3 gG(BNn / 128, Dd / 128);
    k_gemm<<<gG, 256, GEMM_DSMEM>>>(x2p, wq2p, qp_, nullptr, nullptr, 0);
    k_gemm<<<gG, 256, GEMM_DSMEM>>>(x2p, wk2p, kp_, nullptr, nullptr, 0);
    k_gemm<<<gG, 256, GEMM_DSMEM>>>(x2p, wv2p, vp_, nullptr, nullptr, 0);

    k_split<<<(Dd * 128 + 255) / 256, 256>>>(Wo, wo2p, Dd, 1024, 512);

    k_phi_k<<<dim3(Nn / 64, 5, BHh), 256>>>(proj);
    k_ctx<<<dim3(5, Nn / 512, BHh), 256>>>();
    k_phi_q<<<dim3(Nn / 64, BHh), 256, QP_SMEM_FLOATS * (int)sizeof(float)>>>(proj);
    k_out<<<dim3(Nn / 64, BHh), 256>>>();

    k_gemm<<<gG, 256, GEMM_DSMEM>>>(attn2p, wo2p, out, x, bo, 1);
}

// round 13
// speedup vs baseline: 1.2545x; 1.0542x over previous
#include <cuda_runtime.h>
#include <cuda_bf16.h>
#include <stdint.h>
#include <math.h>

#define Bb   4
#define Nn   4096
#define Dd   512
#define Hh   8
#define DHd  64
#define Mm   266
#define BHh  32          // B*H
#define BNn  16384       // B*N
#define MPAD 269         // td row stride (4*269 mod 32 = 20 -> 2-way LDS conflicts)
#define K2   1536        // split-bf16 expanded K (hi|lo|hi)

// -------------------- scratch (static device memory; no allocs) --------------------
__device__ float g_q  [(size_t)BHh * Nn * DHd];
__device__ float g_k  [(size_t)BHh * Nn * DHd];
__device__ float g_v  [(size_t)BHh * Nn * DHd];
__device__ float g_kp [(size_t)BHh * Nn * Mm];   // holds td_k; exp applied inside k_ctx
__device__ float g_ctx [(size_t)BHh * Mm * DHd];
__device__ float g_ksum[(size_t)BHh * Mm];
__device__ float g_kmax[BHh];
__device__ float g_diag[(size_t)BHh * Nn];

__device__ __nv_bfloat16 g_x2   [(size_t)BNn * K2];
__device__ __nv_bfloat16 g_attn2[(size_t)BNn * K2];
__device__ __nv_bfloat16 g_wq2  [(size_t)Dd * K2];
__device__ __nv_bfloat16 g_wk2  [(size_t)Dd * K2];
__device__ __nv_bfloat16 g_wv2  [(size_t)Dd * K2];
__device__ __nv_bfloat16 g_wo2  [(size_t)Dd * K2];

// -------------------- helpers --------------------
typedef unsigned long long u64t;

__device__ __forceinline__ uint32_t smem_to_u32(const void* p) {
    uint32_t a;
    asm("{ .reg .u64 t; cvta.to.shared.u64 t, %1; cvt.u32.u64 %0, t; }"
        : "=r"(a) : "l"(p));
    return a;
}

#define CP_ASYNC16(dst, src) \
    asm volatile("cp.async.cg.shared.global [%0], [%1], 16;" \
                 :: "r"(dst), "l"(src) : "memory")
#define CP_COMMIT()  asm volatile("cp.async.commit_group;" ::: "memory")
#define CP_WAIT1()   asm volatile("cp.async.wait_group 1;" ::: "memory")
#define CP_WAIT0()   asm volatile("cp.async.wait_group 0;" ::: "memory")

__device__ __forceinline__ void ldm_x4(uint32_t& r0, uint32_t& r1,
                                       uint32_t& r2, uint32_t& r3, uint32_t addr) {
    asm volatile("ldmatrix.sync.aligned.m8n8.x4.shared.b16 {%0,%1,%2,%3}, [%4];"
                 : "=r"(r0), "=r"(r1), "=r"(r2), "=r"(r3) : "r"(addr));
}

__device__ __forceinline__ void mma16816(float* c, const uint32_t* a, const uint32_t* b) {
    asm volatile(
        "mma.sync.aligned.m16n8k16.row.col.f32.bf16.bf16.f32 "
        "{%0,%1,%2,%3}, {%4,%5,%6,%7}, {%8,%9}, {%0,%1,%2,%3};"
        : "+f"(c[0]), "+f"(c[1]), "+f"(c[2]), "+f"(c[3])
        : "r"(a[0]), "r"(a[1]), "r"(a[2]), "r"(a[3]), "r"(b[0]), "r"(b[1]));
}

// ---- packed fp32x2 FMA (Blackwell base ISA) ----
__device__ __forceinline__ u64t pack2(float x, float y) {
    u64t r;
    asm("mov.b64 %0, {%1, %2};" : "=l"(r) : "f"(x), "f"(y));
    return r;
}
__device__ __forceinline__ u64t bcast2(float v) {
    u64t r;
    asm("mov.b64 %0, {%1, %1};" : "=l"(r) : "f"(v));
    return r;
}
__device__ __forceinline__ void ffma2(u64t& c, u64t a, u64t b) {
    asm("fma.rn.f32x2 %0, %1, %2, %0;" : "+l"(c) : "l"(a), "l"(b));
}
__device__ __forceinline__ float lane0(u64t v) { float2 t; *(u64t*)&t = v; return t.x; }
__device__ __forceinline__ float lane1(u64t v) { float2 t; *(u64t*)&t = v; return t.y; }
#define ACC2F(i, j) (((i) & 1) ? lane1(acc2[(i) >> 1][j]) : lane0(acc2[(i) >> 1][j]))

#define F32X2_STEP(a4, b4) do {                                   \
    u64t a01 = pack2((a4).x, (a4).y), a23 = pack2((a4).z, (a4).w);\
    u64t bb0 = bcast2((b4).x), bb1 = bcast2((b4).y);              \
    u64t bb2 = bcast2((b4).z), bb3 = bcast2((b4).w);              \
    ffma2(acc2[0][0], a01, bb0); ffma2(acc2[0][1], a01, bb1);     \
    ffma2(acc2[0][2], a01, bb2); ffma2(acc2[0][3], a01, bb3);     \
    ffma2(acc2[1][0], a23, bb0); ffma2(acc2[1][1], a23, bb1);     \
    ffma2(acc2[1][2], a23, bb2); ffma2(acc2[1][3], a23, bb3);     \
} while (0)

__device__ __forceinline__ void atomicMaxF(float* addr, float val) {
    int* ai = (int*)addr;
    int old = *ai;
    while (__int_as_float(old) < val) {
        int assumed = old;
        old = atomicCAS(ai, assumed, __float_as_int(val));
        if (old == assumed) break;
    }
}

__device__ __forceinline__ float fast_exp(float x) {
    float y = fmaxf(x * 1.4426950408889634f, -126.0f);
    float r = rintf(y);
    float f = y - r;
    float p = 1.5403530e-4f;
    p = fmaf(p, f, 1.3333558e-3f);
    p = fmaf(p, f, 9.6181291e-3f);
    p = fmaf(p, f, 5.5504109e-2f);
    p = fmaf(p, f, 2.4022651e-1f);
    p = fmaf(p, f, 6.9314718e-1f);
    p = fmaf(p, f, 1.0f);
    int e = (int)r;
    float s = __int_as_float((e + 127) << 23);
    return p * s;
}

#define NORMALIZER 0.35355339059327373f   // 64^-0.25
#define RATIO      0.061313934f           // 266^-0.5
#define EPSF       1e-4f

// -------------------- init scratch accumulators --------------------
__global__ void k_init() {
    int i = blockIdx.x * 256 + threadIdx.x;
    if (i < BHh * Mm * DHd) g_ctx[i]  = 0.0f;
    if (i < BHh * Mm)       g_ksum[i] = 0.0f;
    if (i < BHh)            g_kmax[i] = -3.0e38f;
}

// -------------------- fp32 -> split bf16 (hi|lo|hi at given offsets) --------------------
__global__ __launch_bounds__(256) void k_split(const float* __restrict__ src,
                                               __nv_bfloat16* __restrict__ dst,
                                               int nrows, int loOff, int dupOff) {
    int i = blockIdx.x * 256 + threadIdx.x;
    int total = nrows * 128;   // 4 floats per thread
    if (i >= total) return;
    int r = i >> 7;
    int c = (i & 127) << 2;
    float4 v = *(const float4*)(src + (size_t)r * 512 + c);
    __nv_bfloat16 h0 = __float2bfloat16(v.x), h1 = __float2bfloat16(v.y);
    __nv_bfloat16 h2 = __float2bfloat16(v.z), h3 = __float2bfloat16(v.w);
    __nv_bfloat16 l0 = __float2bfloat16(v.x - __bfloat162float(h0));
    __nv_bfloat16 l1 = __float2bfloat16(v.y - __bfloat162float(h1));
    __nv_bfloat16 l2 = __float2bfloat16(v.z - __bfloat162float(h2));
    __nv_bfloat16 l3 = __float2bfloat16(v.w - __bfloat162float(h3));
    size_t rb = (size_t)r * K2;
    __nv_bfloat162 H01; H01.x = h0; H01.y = h1;
    __nv_bfloat162 H23; H23.x = h2; H23.y = h3;
    __nv_bfloat162 L01; L01.x = l0; L01.y = l1;
    __nv_bfloat162 L23; L23.x = l2; L23.y = l3;
    *(__nv_bfloat162*)(dst + rb + c)              = H01;
    *(__nv_bfloat162*)(dst + rb + c + 2)          = H23;
    *(__nv_bfloat162*)(dst + rb + loOff + c)      = L01;
    *(__nv_bfloat162*)(dst + rb + loOff + c + 2)  = L23;
    *(__nv_bfloat162*)(dst + rb + dupOff + c)     = H01;
    *(__nv_bfloat162*)(dst + rb + dupOff + c + 2) = H23;
}

// -------------------- mma.sync GEMM: C[16384,512] = A2[16384,K2] @ B2[512,K2]^T --------
#define ASTR 40
#define TILE_B (128 * ASTR)
#define GEMM_DSMEM (6 * TILE_B * 2)   // 61440 bytes

__global__ __launch_bounds__(256) void k_gemm(const __nv_bfloat16* __restrict__ A,
                                              const __nv_bfloat16* __restrict__ Bw,
                                              float* __restrict__ C,
                                              const float* __restrict__ xres,
                                              const float* __restrict__ bo,
                                              int finalmode) {
    extern __shared__ __nv_bfloat16 dyn[];
    int tid = threadIdx.x, lane = tid & 31, w = tid >> 5;
    int m0 = (w & 3) * 32, n0 = (w >> 2) * 64;
    int r0 = blockIdx.x * 128, e0 = blockIdx.y * 128;
    uint32_t sAu = smem_to_u32(dyn);
    uint32_t sBu = sAu + 3u * (TILE_B * 2);

    float acc[2][8][4];
#pragma unroll
    for (int i = 0; i < 2; i++)
#pragma unroll
        for (int j = 0; j < 8; j++)
#pragma unroll
            for (int l = 0; l < 4; l++) acc[i][j][l] = 0.f;

    int lrow = tid >> 1;
    int lcol = (tid & 1) << 4;
    const __nv_bfloat16* Arow = A + (size_t)(r0 + lrow) * K2 + lcol;
    const __nv_bfloat16* Brow = Bw + (size_t)(e0 + lrow) * K2 + lcol;
    uint32_t sAdst = sAu + (uint32_t)(lrow * ASTR + lcol) * 2;
    uint32_t sBdst = sBu + (uint32_t)(lrow * ASTR + lcol) * 2;

#define LOAD_TILE(buf, t) do {                                         \
    uint32_t _o = (uint32_t)(buf) * (TILE_B * 2);                      \
    const __nv_bfloat16* _a = Arow + (t) * 32;                         \
    const __nv_bfloat16* _b = Brow + (t) * 32;                         \
    CP_ASYNC16(sAdst + _o,      _a);                                   \
    CP_ASYNC16(sAdst + _o + 16, _a + 8);                               \
    CP_ASYNC16(sBdst + _o,      _b);                                   \
    CP_ASYNC16(sBdst + _o + 16, _b + 8);                               \
} while (0)

    LOAD_TILE(0, 0);
    CP_COMMIT();
    LOAD_TILE(1, 1);
    CP_COMMIT();

    const int NT = K2 / 32;   // 48
    int buf = 0;
#pragma unroll 1
    for (int t = 0; t < NT; ++t) {
        if (t + 1 < NT) CP_WAIT1(); else CP_WAIT0();
        __syncthreads();
        if (t + 2 < NT) {
            int nb = buf + 2; if (nb >= 3) nb -= 3;
            LOAD_TILE(nb, t + 2);
            CP_COMMIT();
        }
        uint32_t ab = sAu + (uint32_t)buf * (TILE_B * 2);
        uint32_t bb = sBu + (uint32_t)buf * (TILE_B * 2);
#pragma unroll
        for (int ks = 0; ks < 32; ks += 16) {
            uint32_t a[2][4];
#pragma unroll
            for (int mt = 0; mt < 2; mt++) {
                uint32_t addr = ab +
                    (uint32_t)((m0 + mt * 16 + (lane & 15)) * ASTR + ks + ((lane >> 4) << 3)) * 2;
                ldm_x4(a[mt][0], a[mt][1], a[mt][2], a[mt][3], addr);
            }
            uint32_t b[8][2];
#pragma unroll
            for (int p = 0; p < 4; p++) {
                int nA = n0 + p * 16;
                uint32_t addr = bb +
                    (uint32_t)((nA + (lane & 7) + ((lane >> 4) << 3)) * ASTR + ks + (lane & 8)) * 2;
                ldm_x4(b[2 * p][0], b[2 * p][1], b[2 * p + 1][0], b[2 * p + 1][1], addr);
            }
#pragma unroll
            for (int mt = 0; mt < 2; mt++)
#pragma unroll
                for (int nt = 0; nt < 8; nt++)
                    mma16816(acc[mt][nt], a[mt], b[nt]);
        }
        if (++buf == 3) buf = 0;
    }

    int gid = lane >> 2, tig = lane & 3;
#pragma unroll
    for (int mt = 0; mt < 2; mt++) {
#pragma unroll
        for (int nt = 0; nt < 8; nt++) {
            int r = r0 + m0 + mt * 16 + gid;
            int e = e0 + n0 + nt * 8 + tig * 2;
            float2 v01 = make_float2(acc[mt][nt][0], acc[mt][nt][1]);
            float2 v23 = make_float2(acc[mt][nt][2], acc[mt][nt][3]);
            if (!finalmode) {
                int b = r >> 12, n = r & 4095;
                int h = e >> 6, dh = e & 63;
                float* d0 = C + (((size_t)((b << 3) + h) * Nn + n) * DHd + dh);
                *(float2*)d0 = v01;
                *(float2*)(d0 + 8 * DHd) = v23;
            } else {
                size_t b0 = (size_t)r * Dd + e;
                float2 x0 = *(const float2*)(xres + b0);
                float2 x1 = *(const float2*)(xres + b0 + 8 * Dd);
                float2 bv = *(const float2*)(bo + e);
                *(float2*)(C + b0) = make_float2(x0.x + bv.x + v01.x, x0.y + bv.y + v01.y);
                *(float2*)(C + b0 + 8 * Dd) = make_float2(x1.x + bv.x + v23.x, x1.y + bv.y + v23.y);
            }
        }
    }
}

// -------------------- phi_k: td = (k*nrm)@proj^T -> g_kp, diag, per-head max -------
__global__ __launch_bounds__(256) void k_phi_k(const float* __restrict__ proj) {
    __shared__ float Ks[64][68];   // [dh][n]
    __shared__ float Ps[64][68];   // [dh][m]
    __shared__ float red[256];
    int tid = threadIdx.x;
    int n0 = blockIdx.x * 64;
    int m0 = blockIdx.y * 64;
    int bh = blockIdx.z;

#pragma unroll
    for (int i = 0; i < 4; i++) {
        int s = tid + i * 256;
        int row = s >> 4;
        int kc = (s & 15) << 2;
        float4 a = *(const float4*)(g_k + ((size_t)bh * Nn + n0 + row) * DHd + kc);
        Ks[kc + 0][row] = a.x * NORMALIZER; Ks[kc + 1][row] = a.y * NORMALIZER;
        Ks[kc + 2][row] = a.z * NORMALIZER; Ks[kc + 3][row] = a.w * NORMALIZER;
        float4 p = make_float4(0.f, 0.f, 0.f, 0.f);
        if (m0 + row < Mm) p = *(const float4*)(proj + (size_t)(m0 + row) * DHd + kc);
        Ps[kc + 0][row] = p.x; Ps[kc + 1][row] = p.y;
        Ps[kc + 2][row] = p.z; Ps[kc + 3][row] = p.w;
    }
    __syncthreads();

    if (m0 == 0 && tid < 64) {
        float ss = 0.f;
#pragma unroll
        for (int d = 0; d < 64; d++) { float q = Ks[d][tid]; ss += q * q; }
        g_diag[(size_t)bh * Nn + n0 + tid] = 0.5f * ss;
    }

    u64t acc2[2][4];
#pragma unroll
    for (int i = 0; i < 2; i++)
#pragma unroll
        for (int j = 0; j < 4; j++) acc2[i][j] = 0ull;
    int ty = tid >> 4, tx = tid & 15;
#pragma unroll
    for (int kk = 0; kk < 64; kk++) {
        float4 a = *(const float4*)&Ks[kk][ty * 4];
        float4 b = *(const float4*)&Ps[kk][tx * 4];
        F32X2_STEP(a, b);
    }

    float mymax = -3.0e38f;
#pragma unroll
    for (int i = 0; i < 4; i++) {
        int n = n0 + ty * 4 + i;
#pragma unroll
        for (int j = 0; j < 4; j++) {
            int m = m0 + tx * 4 + j;
            if (m < Mm) {
                float av = ACC2F(i, j);
                g_kp[((size_t)bh * Nn + n) * Mm + m] = av;
                mymax = fmaxf(mymax, av);
            }
        }
    }
    red[tid] = mymax;
    __syncthreads();
    for (int off = 128; off > 0; off >>= 1) {
        if (tid < off) red[tid] = fmaxf(red[tid], red[tid + off]);
        __syncthreads();
    }
    if (tid == 0) atomicMaxF(&g_kmax[bh], red[0]);
}

// -------------------- ctx fused: exp(td) in-fill (MLP-batched) + MMA + ksum --------
__global__ __launch_bounds__(256) void k_ctx() {
    __shared__ float Ksm[64][68];   // [n][m]  (kp values)
    __shared__ float Vs[64][68];    // [n][dh]
    __shared__ float diag_s[512];   // diag for the whole n-slab
    __shared__ float rsum[256];
    int tid = threadIdx.x;
    int m0 = blockIdx.x * 64;
    int nc = blockIdx.y * 512;
    int bh = blockIdx.z;
    float mx = g_kmax[bh];

    diag_s[tid]       = g_diag[(size_t)bh * Nn + nc + tid];
    diag_s[tid + 256] = g_diag[(size_t)bh * Nn + nc + 256 + tid];

    u64t acc2[2][4];
#pragma unroll
    for (int i = 0; i < 2; i++)
#pragma unroll
        for (int j = 0; j < 4; j++) acc2[i][j] = 0ull;
    int ty = tid >> 4, tx = tid & 15;

    int mmc = m0 + (tid & 63);
    bool mok = mmc < Mm;
    int nbase = tid >> 6;
    float cs = 0.f;
    __syncthreads();

    for (int nt = 0; nt < 8; nt++) {
        int n0 = nc + nt * 64;
        float tdv[16];
        const float* kpb = g_kp + ((size_t)bh * Nn + n0 + nbase) * Mm + mmc;
#pragma unroll
        for (int i = 0; i < 16; i++)
            tdv[i] = mok ? kpb[(size_t)(i * 4) * Mm] : 0.f;
#pragma unroll
        for (int i = 0; i < 16; i++) {
            int n = i * 4 + nbase;
            float v = 0.f;
            if (mok) {
                v = RATIO * (fast_exp(tdv[i] - diag_s[nt * 64 + n] - mx) + EPSF);
                cs += v;
            }
            Ksm[n][tid & 63] = v;
        }
#pragma unroll
        for (int i = 0; i < 4; i++) {
            int s = tid + i * 256;
            int n = s >> 4, c = (s & 15) << 2;
            float4 v = *(const float4*)(g_v + ((size_t)bh * Nn + n0 + n) * DHd + c);
            Vs[n][c] = v.x; Vs[n][c + 1] = v.y; Vs[n][c + 2] = v.z; Vs[n][c + 3] = v.w;
        }
        __syncthreads();
#pragma unroll
        for (int kk = 0; kk < 64; kk++) {
            float4 a = *(const float4*)&Ksm[kk][ty * 4];
            float4 b = *(const float4*)&Vs[kk][tx * 4];
            F32X2_STEP(a, b);
        }
        __syncthreads();
    }
#pragma unroll
    for (int i = 0; i < 4; i++) {
        int m = m0 + ty * 4 + i;
        if (m < Mm)
#pragma unroll
            for (int j = 0; j < 4; j++)
                atomicAdd(&g_ctx[((size_t)bh * Mm + m) * DHd + tx * 4 + j], ACC2F(i, j));
    }
    rsum[tid] = cs;
    __syncthreads();
    if (tid < 64) {
        int m = m0 + tid;
        if (m < Mm) {
            float t = rsum[tid] + rsum[tid + 64] + rsum[tid + 128] + rsum[tid + 192];
            atomicAdd(&g_ksum[bh * Mm + m], t);
        }
    }
}

// ------------- phi_q + out FUSED: td -> exp (smem) -> out GEMM -> attn2 -------------
// qp never touches HBM. smem: Qs 4352 | Ps/Cs 4352 | tds 64*MPAD | ksum MPAD | diag 64 | dinv 64
#define QO_SMEM_FLOATS (4352 + 4352 + 64 * MPAD + MPAD + 64 + 64)
__global__ __launch_bounds__(256) void k_phi_q_out(const float* __restrict__ proj) {
    extern __shared__ float sm[];
    float* Qs     = sm;                        // [dh][n] 64*68
    float* Ps     = sm + 4352;                 // proj tiles; reused as Cs [kk][dh] 64*68
    float* tds    = sm + 8704;                 // [n][MPAD]; td then qp in place
    float* ksum_s = sm + 8704 + 64 * MPAD;     // MPAD
    float* diag_s = ksum_s + MPAD;             // 64
    float* dinv_s = diag_s + 64;               // 64

    int tid = threadIdx.x;
    int n0 = blockIdx.x * 64;
    int bh = blockIdx.y;

    for (int i = tid; i < Mm; i += 256) ksum_s[i] = g_ksum[bh * Mm + i];

#pragma unroll
    for (int i = 0; i < 4; i++) {
        int s = tid + i * 256;
        int row = s >> 4;
        int kc = (s & 15) << 2;
        float4 a = *(const float4*)(g_q + ((size_t)bh * Nn + n0 + row) * DHd + kc);
        Qs[(kc + 0) * 68 + row] = a.x * NORMALIZER;
        Qs[(kc + 1) * 68 + row] = a.y * NORMALIZER;
        Qs[(kc + 2) * 68 + row] = a.z * NORMALIZER;
        Qs[(kc + 3) * 68 + row] = a.w * NORMALIZER;
    }
    __syncthreads();
    if (tid < 64) {
        float ss = 0.f;
#pragma unroll
        for (int d = 0; d < 64; d++) { float q = Qs[d * 68 + tid]; ss += q * q; }
        diag_s[tid] = 0.5f * ss;
    }

    int ty = tid >> 4, tx = tid & 15;
    // ---- phase 1: td = (q*nrm) @ proj^T into tds ----
    for (int mt = 0; mt < 5; mt++) {
        int m0 = mt * 64;
#pragma unroll
        for (int i = 0; i < 4; i++) {
            int s = tid + i * 256;
            int row = s >> 4;
            int kc = (s & 15) << 2;
            float4 p = make_float4(0.f, 0.f, 0.f, 0.f);
            if (m0 + row < Mm) p = *(const float4*)(proj + (size_t)(m0 + row) * DHd + kc);
            Ps[(kc + 0) * 68 + row] = p.x;
            Ps[(kc + 1) * 68 + row] = p.y;
            Ps[(kc + 2) * 68 + row] = p.z;
            Ps[(kc + 3) * 68 + row] = p.w;
        }
        __syncthreads();
        u64t acc2[2][4];
#pragma unroll
        for (int i = 0; i < 2; i++)
#pragma unroll
            for (int j = 0; j < 4; j++) acc2[i][j] = 0ull;
#pragma unroll
        for (int kk = 0; kk < 64; kk++) {
            float4 a = *(const float4*)&Qs[kk * 68 + ty * 4];
            float4 b = *(const float4*)&Ps[kk * 68 + tx * 4];
            F32X2_STEP(a, b);
        }
#pragma unroll
        for (int i = 0; i < 4; i++)
#pragma unroll
            for (int j = 0; j < 4; j++) {
                int m = m0 + tx * 4 + j;
                if (m < Mm) tds[(ty * 4 + i) * MPAD + m] = ACC2F(i, j);
            }
        __syncthreads();
    }

    // ---- phase 2: rowmax, exp (qp overwrites td in place), dinv ----
    {
        int row = tid >> 2, lane = tid & 3;
        float pm = -3.0e38f;
        for (int m = lane; m < Mm; m += 4) pm = fmaxf(pm, tds[row * MPAD + m]);
        pm = fmaxf(pm, __shfl_xor_sync(0xffffffffu, pm, 1));
        pm = fmaxf(pm, __shfl_xor_sync(0xffffffffu, pm, 2));
        float dg = diag_s[row];
        float sum = 0.f;
        for (int m = lane; m < Mm; m += 4) {
            float v = RATIO * (fast_exp(tds[row * MPAD + m] - dg - pm) + EPSF);
            tds[row * MPAD + m] = v;
            sum += v * ksum_s[m];
        }
        sum += __shfl_xor_sync(0xffffffffu, sum, 1);
        sum += __shfl_xor_sync(0xffffffffu, sum, 2);
        if (lane == 0) dinv_s[row] = 1.0f / sum;
    }
    __syncthreads();

    // ---- phase 3: out = qp @ ctx, scaled by dinv, write attn2 split-bf16 ----
    u64t acc2[2][4];
#pragma unroll
    for (int i = 0; i < 2; i++)
#pragma unroll
        for (int j = 0; j < 4; j++) acc2[i][j] = 0ull;

#pragma unroll 1
    for (int ch = 0; ch < 5; ch++) {
        int c0 = ch * 64;
        int kmax = (ch < 4) ? 64 : (Mm - 256);   // 10 on the tail
        // fill Cs (Ps region) [kk][dh]
#pragma unroll
        for (int i = 0; i < 16; i++) {
            int s = tid + i * 256;
            int kk = s >> 6, dh = s & 63;
            Ps[kk * 68 + dh] = (c0 + kk < Mm)
                                   ? g_ctx[((size_t)bh * Mm + c0 + kk) * DHd + dh]
                                   : 0.f;
        }
        __syncthreads();
        if (ch < 4) {
#pragma unroll
            for (int kk = 0; kk < 64; kk++) {
                float4 a = make_float4(tds[(ty * 4 + 0) * MPAD + c0 + kk],
                                       tds[(ty * 4 + 1) * MPAD + c0 + kk],
                                       tds[(ty * 4 + 2) * MPAD + c0 + kk],
                                       tds[(ty * 4 + 3) * MPAD + c0 + kk]);
                float4 b = *(const float4*)&Ps[kk * 68 + tx * 4];
                F32X2_STEP(a, b);
            }
        } else {
#pragma unroll
            for (int kk = 0; kk < 10; kk++) {
                float4 a = make_float4(tds[(ty * 4 + 0) * MPAD + c0 + kk],
                                       tds[(ty * 4 + 1) * MPAD + c0 + kk],
                                       tds[(ty * 4 + 2) * MPAD + c0 + kk],
                                       tds[(ty * 4 + 3) * MPAD + c0 + kk]);
                float4 b = *(const float4*)&Ps[kk * 68 + tx * 4];
                F32X2_STEP(a, b);
            }
        }
        __syncthreads();
        (void)kmax;
    }

    int b = bh >> 3, h = bh & 7;
#pragma unroll
    for (int i = 0; i < 4; i++) {
        int n = n0 + ty * 4 + i;
        float dv = dinv_s[ty * 4 + i];
        size_t rb = (size_t)(b * Nn + n) * K2 + h * 64 + tx * 4;
        float v0 = ACC2F(i, 0) * dv, v1 = ACC2F(i, 1) * dv;
        float v2 = ACC2F(i, 2) * dv, v3 = ACC2F(i, 3) * dv;
        __nv_bfloat162 H01, L01, H23, L23;
        H01.x = __float2bfloat16(v0); L01.x = __float2bfloat16(v0 - __bfloat162float(H01.x));
        H01.y = __float2bfloat16(v1); L01.y = __float2bfloat16(v1 - __bfloat162float(H01.y));
        H23.x = __float2bfloat16(v2); L23.x = __float2bfloat16(v2 - __bfloat162float(H23.x));
        H23.y = __float2bfloat16(v3); L23.y = __float2bfloat16(v3 - __bfloat162float(H23.y));
        *(__nv_bfloat162*)(g_attn2 + rb)            = H01;
        *(__nv_bfloat162*)(g_attn2 + rb + 2)        = H23;
        *(__nv_bfloat162*)(g_attn2 + rb + 512)      = L01;
        *(__nv_bfloat162*)(g_attn2 + rb + 512 + 2)  = L23;
        *(__nv_bfloat162*)(g_attn2 + rb + 1024)     = H01;
        *(__nv_bfloat162*)(g_attn2 + rb + 1024 + 2) = H23;
    }
}

// -------------------- launch --------------------
extern "C" void kernel_launch(void* const* d_in, const int* in_sizes, int n_in,
                              void* d_out, int out_size) {
    const float* x    = (const float*)d_in[0];
    const float* Wq   = (const float*)d_in[1];
    const float* Wk   = (const float*)d_in[2];
    const float* Wv   = (const float*)d_in[3];
    const float* Wo   = (const float*)d_in[4];
    const float* bo   = (const float*)d_in[5];
    const float* proj = (const float*)d_in[6];
    float* out = (float*)d_out;
    (void)in_sizes; (void)n_in; (void)out_size;

    cudaFuncSetAttribute(k_phi_q_out, cudaFuncAttributeMaxDynamicSharedMemorySize,
                         QO_SMEM_FLOATS * (int)sizeof(float));
    cudaFuncSetAttribute(k_gemm, cudaFuncAttributeMaxDynamicSharedMemorySize, GEMM_DSMEM);

    __nv_bfloat16 *x2p, *wq2p, *wk2p, *wv2p, *wo2p, *attn2p;
    cudaGetSymbolAddress((void**)&x2p, g_x2);
    cudaGetSymbolAddress((void**)&wq2p, g_wq2);
    cudaGetSymbolAddress((void**)&wk2p, g_wk2);
    cudaGetSymbolAddress((void**)&wv2p, g_wv2);
    cudaGetSymbolAddress((void**)&wo2p, g_wo2);
    cudaGetSymbolAddress((void**)&attn2p, g_attn2);
    float *qp_, *kp_, *vp_;
    cudaGetSymbolAddress((void**)&qp_, g_q);
    cudaGetSymbolAddress((void**)&kp_, g_k);
    cudaGetSymbolAddress((void**)&vp_, g_v);

    k_init<<<(BHh * Mm * DHd + 255) / 256, 256>>>();
    k_split<<<(BNn * 128 + 255) / 256, 256>>>(x, x2p, BNn, 512, 1024);
    k_split<<<(Dd * 128 + 255) / 256, 256>>>(Wq, wq2p, Dd, 1024, 512);
    k_split<<<(Dd * 128 + 255) / 256, 256>>>(Wk, wk2p, Dd, 1024, 512);
    k_split<<<(Dd * 128 + 255) / 256, 256>>>(Wv, wv2p, Dd, 1024, 512);

    dim3 gG(BNn / 128, Dd / 128);
    k_gemm<<<gG, 256, GEMM_DSMEM>>>(x2p, wq2p, qp_, nullptr, nullptr, 0);
    k_gemm<<<gG, 256, GEMM_DSMEM>>>(x2p, wk2p, kp_, nullptr, nullptr, 0);
    k_gemm<<<gG, 256, GEMM_DSMEM>>>(x2p, wv2p, vp_, nullptr, nullptr, 0);

    k_split<<<(Dd * 128 + 255) / 256, 256>>>(Wo, wo2p, Dd, 1024, 512);

    k_phi_k<<<dim3(Nn / 64, 5, BHh), 256>>>(proj);
    k_ctx<<<dim3(5, Nn / 512, BHh), 256>>>();
    k_phi_q_out<<<dim3(Nn / 64, BHh), 256, QO_SMEM_FLOATS * (int)sizeof(float)>>>(proj);

    k_gemm<<<gG, 256, GEMM_DSMEM>>>(attn2p, wo2p, out, x, bo, 1);
}

// round 14
// speedup vs baseline: 1.4391x; 1.1471x over previous
#include <cuda_runtime.h>
#include <cuda_bf16.h>
#include <stdint.h>
#include <math.h>

#define Bb   4
#define Nn   4096
#define Dd   512
#define Hh   8
#define DHd  64
#define Mm   266
#define BHh  32          // B*H
#define BNn  16384       // B*N
#define MPAD 269         // td row stride
#define K2   1024        // split-2 bf16 expanded K: A=[hi|lo], W=[hi|hi]

// -------------------- scratch (static device memory; no allocs) --------------------
__device__ float g_q  [(size_t)BHh * Nn * DHd];
__device__ float g_k  [(size_t)BHh * Nn * DHd];
__device__ float g_v  [(size_t)BHh * Nn * DHd];
__device__ float g_kp [(size_t)BHh * Nn * Mm];   // holds td_k; exp applied inside k_ctx
__device__ float g_ctx [(size_t)BHh * Mm * DHd];
__device__ float g_ksum[(size_t)BHh * Mm];
__device__ float g_kmax[BHh];
__device__ float g_diag[(size_t)BHh * Nn];

__device__ __nv_bfloat16 g_x2   [(size_t)BNn * K2];
__device__ __nv_bfloat16 g_attn2[(size_t)BNn * K2];
__device__ __nv_bfloat16 g_wq2  [(size_t)Dd * K2];
__device__ __nv_bfloat16 g_wk2  [(size_t)Dd * K2];
__device__ __nv_bfloat16 g_wv2  [(size_t)Dd * K2];
__device__ __nv_bfloat16 g_wo2  [(size_t)Dd * K2];

// -------------------- helpers --------------------
typedef unsigned long long u64t;

__device__ __forceinline__ uint32_t smem_to_u32(const void* p) {
    uint32_t a;
    asm("{ .reg .u64 t; cvta.to.shared.u64 t, %1; cvt.u32.u64 %0, t; }"
        : "=r"(a) : "l"(p));
    return a;
}

#define CP_ASYNC16(dst, src) \
    asm volatile("cp.async.cg.shared.global [%0], [%1], 16;" \
                 :: "r"(dst), "l"(src) : "memory")
#define CP_COMMIT()  asm volatile("cp.async.commit_group;" ::: "memory")
#define CP_WAIT1()   asm volatile("cp.async.wait_group 1;" ::: "memory")
#define CP_WAIT0()   asm volatile("cp.async.wait_group 0;" ::: "memory")

__device__ __forceinline__ void ldm_x4(uint32_t& r0, uint32_t& r1,
                                       uint32_t& r2, uint32_t& r3, uint32_t addr) {
    asm volatile("ldmatrix.sync.aligned.m8n8.x4.shared.b16 {%0,%1,%2,%3}, [%4];"
                 : "=r"(r0), "=r"(r1), "=r"(r2), "=r"(r3) : "r"(addr));
}

__device__ __forceinline__ void mma16816(float* c, const uint32_t* a, const uint32_t* b) {
    asm volatile(
        "mma.sync.aligned.m16n8k16.row.col.f32.bf16.bf16.f32 "
        "{%0,%1,%2,%3}, {%4,%5,%6,%7}, {%8,%9}, {%0,%1,%2,%3};"
        : "+f"(c[0]), "+f"(c[1]), "+f"(c[2]), "+f"(c[3])
        : "r"(a[0]), "r"(a[1]), "r"(a[2]), "r"(a[3]), "r"(b[0]), "r"(b[1]));
}

// ---- packed fp32x2 FMA (Blackwell base ISA) ----
__device__ __forceinline__ u64t pack2(float x, float y) {
    u64t r;
    asm("mov.b64 %0, {%1, %2};" : "=l"(r) : "f"(x), "f"(y));
    return r;
}
__device__ __forceinline__ u64t bcast2(float v) {
    u64t r;
    asm("mov.b64 %0, {%1, %1};" : "=l"(r) : "f"(v));
    return r;
}
__device__ __forceinline__ void ffma2(u64t& c, u64t a, u64t b) {
    asm("fma.rn.f32x2 %0, %1, %2, %0;" : "+l"(c) : "l"(a), "l"(b));
}
__device__ __forceinline__ float lane0(u64t v) { float2 t; *(u64t*)&t = v; return t.x; }
__device__ __forceinline__ float lane1(u64t v) { float2 t; *(u64t*)&t = v; return t.y; }
#define ACC2F(i, j) (((i) & 1) ? lane1(acc2[(i) >> 1][j]) : lane0(acc2[(i) >> 1][j]))

#define F32X2_STEP(a4, b4) do {                                   \
    u64t a01 = pack2((a4).x, (a4).y), a23 = pack2((a4).z, (a4).w);\
    u64t bb0 = bcast2((b4).x), bb1 = bcast2((b4).y);              \
    u64t bb2 = bcast2((b4).z), bb3 = bcast2((b4).w);              \
    ffma2(acc2[0][0], a01, bb0); ffma2(acc2[0][1], a01, bb1);     \
    ffma2(acc2[0][2], a01, bb2); ffma2(acc2[0][3], a01, bb3);     \
    ffma2(acc2[1][0], a23, bb0); ffma2(acc2[1][1], a23, bb1);     \
    ffma2(acc2[1][2], a23, bb2); ffma2(acc2[1][3], a23, bb3);     \
} while (0)

__device__ __forceinline__ void atomicMaxF(float* addr, float val) {
    int* ai = (int*)addr;
    int old = *ai;
    while (__int_as_float(old) < val) {
        int assumed = old;
        old = atomicCAS(ai, assumed, __float_as_int(val));
        if (old == assumed) break;
    }
}

__device__ __forceinline__ float fast_exp(float x) {
    float y = fmaxf(x * 1.4426950408889634f, -126.0f);
    float r = rintf(y);
    float f = y - r;
    float p = 1.5403530e-4f;
    p = fmaf(p, f, 1.3333558e-3f);
    p = fmaf(p, f, 9.6181291e-3f);
    p = fmaf(p, f, 5.5504109e-2f);
    p = fmaf(p, f, 2.4022651e-1f);
    p = fmaf(p, f, 6.9314718e-1f);
    p = fmaf(p, f, 1.0f);
    int e = (int)r;
    float s = __int_as_float((e + 127) << 23);
    return p * s;
}

#define NORMALIZER 0.35355339059327373f   // 64^-0.25
#define RATIO      0.061313934f           // 266^-0.5
#define EPSF       1e-4f

// -------------------- init scratch accumulators --------------------
__global__ void k_init() {
    int i = blockIdx.x * 256 + threadIdx.x;
    if (i < BHh * Mm * DHd) g_ctx[i]  = 0.0f;
    if (i < BHh * Mm)       g_ksum[i] = 0.0f;
    if (i < BHh)            g_kmax[i] = -3.0e38f;
}

// ------------- fp32 -> split-2 bf16: A-layout [hi|lo] (loOff=512), W-layout [hi|hi] (dupOff=512)
__global__ __launch_bounds__(256) void k_split(const float* __restrict__ src,
                                               __nv_bfloat16* __restrict__ dst,
                                               int nrows, int loOff, int dupOff) {
    int i = blockIdx.x * 256 + threadIdx.x;
    int total = nrows * 128;   // 4 floats per thread
    if (i >= total) return;
    int r = i >> 7;
    int c = (i & 127) << 2;
    float4 v = *(const float4*)(src + (size_t)r * 512 + c);
    __nv_bfloat16 h0 = __float2bfloat16(v.x), h1 = __float2bfloat16(v.y);
    __nv_bfloat16 h2 = __float2bfloat16(v.z), h3 = __float2bfloat16(v.w);
    size_t rb = (size_t)r * K2;
    __nv_bfloat162 H01; H01.x = h0; H01.y = h1;
    __nv_bfloat162 H23; H23.x = h2; H23.y = h3;
    *(__nv_bfloat162*)(dst + rb + c)     = H01;
    *(__nv_bfloat162*)(dst + rb + c + 2) = H23;
    if (loOff) {
        __nv_bfloat162 L01, L23;
        L01.x = __float2bfloat16(v.x - __bfloat162float(h0));
        L01.y = __float2bfloat16(v.y - __bfloat162float(h1));
        L23.x = __float2bfloat16(v.z - __bfloat162float(h2));
        L23.y = __float2bfloat16(v.w - __bfloat162float(h3));
        *(__nv_bfloat162*)(dst + rb + loOff + c)     = L01;
        *(__nv_bfloat162*)(dst + rb + loOff + c + 2) = L23;
    }
    if (dupOff) {
        *(__nv_bfloat162*)(dst + rb + dupOff + c)     = H01;
        *(__nv_bfloat162*)(dst + rb + dupOff + c + 2) = H23;
    }
}

// -------------------- mma.sync GEMM: C[16384,512] = A2[16384,K2] @ B2[512,K2]^T --------
#define ASTR 40
#define TILE_B (128 * ASTR)
#define GEMM_DSMEM (6 * TILE_B * 2)   // 61440 bytes

__global__ __launch_bounds__(256) void k_gemm(const __nv_bfloat16* __restrict__ A,
                                              const __nv_bfloat16* __restrict__ Bw,
                                              float* __restrict__ C,
                                              const float* __restrict__ xres,
                                              const float* __restrict__ bo,
                                              int finalmode) {
    extern __shared__ __nv_bfloat16 dyn[];
    int tid = threadIdx.x, lane = tid & 31, w = tid >> 5;
    int m0 = (w & 3) * 32, n0 = (w >> 2) * 64;
    int r0 = blockIdx.x * 128, e0 = blockIdx.y * 128;
    uint32_t sAu = smem_to_u32(dyn);
    uint32_t sBu = sAu + 3u * (TILE_B * 2);

    float acc[2][8][4];
#pragma unroll
    for (int i = 0; i < 2; i++)
#pragma unroll
        for (int j = 0; j < 8; j++)
#pragma unroll
            for (int l = 0; l < 4; l++) acc[i][j][l] = 0.f;

    int lrow = tid >> 1;
    int lcol = (tid & 1) << 4;
    const __nv_bfloat16* Arow = A + (size_t)(r0 + lrow) * K2 + lcol;
    const __nv_bfloat16* Brow = Bw + (size_t)(e0 + lrow) * K2 + lcol;
    uint32_t sAdst = sAu + (uint32_t)(lrow * ASTR + lcol) * 2;
    uint32_t sBdst = sBu + (uint32_t)(lrow * ASTR + lcol) * 2;

#define LOAD_TILE(buf, t) do {                                         \
    uint32_t _o = (uint32_t)(buf) * (TILE_B * 2);                      \
    const __nv_bfloat16* _a = Arow + (t) * 32;                         \
    const __nv_bfloat16* _b = Brow + (t) * 32;                         \
    CP_ASYNC16(sAdst + _o,      _a);                                   \
    CP_ASYNC16(sAdst + _o + 16, _a + 8);                               \
    CP_ASYNC16(sBdst + _o,      _b);                                   \
    CP_ASYNC16(sBdst + _o + 16, _b + 8);                               \
} while (0)

    LOAD_TILE(0, 0);
    CP_COMMIT();
    LOAD_TILE(1, 1);
    CP_COMMIT();

    const int NT = K2 / 32;   // 32
    int buf = 0;
#pragma unroll 1
    for (int t = 0; t < NT; ++t) {
        if (t + 1 < NT) CP_WAIT1(); else CP_WAIT0();
        __syncthreads();
        if (t + 2 < NT) {
            int nb = buf + 2; if (nb >= 3) nb -= 3;
            LOAD_TILE(nb, t + 2);
            CP_COMMIT();
        }
        uint32_t ab = sAu + (uint32_t)buf * (TILE_B * 2);
        uint32_t bb = sBu + (uint32_t)buf * (TILE_B * 2);
#pragma unroll
        for (int ks = 0; ks < 32; ks += 16) {
            uint32_t a[2][4];
#pragma unroll
            for (int mt = 0; mt < 2; mt++) {
                uint32_t addr = ab +
                    (uint32_t)((m0 + mt * 16 + (lane & 15)) * ASTR + ks + ((lane >> 4) << 3)) * 2;
                ldm_x4(a[mt][0], a[mt][1], a[mt][2], a[mt][3], addr);
            }
            uint32_t b[8][2];
#pragma unroll
            for (int p = 0; p < 4; p++) {
                int nA = n0 + p * 16;
                uint32_t addr = bb +
                    (uint32_t)((nA + (lane & 7) + ((lane >> 4) << 3)) * ASTR + ks + (lane & 8)) * 2;
                ldm_x4(b[2 * p][0], b[2 * p][1], b[2 * p + 1][0], b[2 * p + 1][1], addr);
            }
#pragma unroll
            for (int mt = 0; mt < 2; mt++)
#pragma unroll
                for (int nt = 0; nt < 8; nt++)
                    mma16816(acc[mt][nt], a[mt], b[nt]);
        }
        if (++buf == 3) buf = 0;
    }

    int gid = lane >> 2, tig = lane & 3;
#pragma unroll
    for (int mt = 0; mt < 2; mt++) {
#pragma unroll
        for (int nt = 0; nt < 8; nt++) {
            int r = r0 + m0 + mt * 16 + gid;
            int e = e0 + n0 + nt * 8 + tig * 2;
            float2 v01 = make_float2(acc[mt][nt][0], acc[mt][nt][1]);
            float2 v23 = make_float2(acc[mt][nt][2], acc[mt][nt][3]);
            if (!finalmode) {
                int b = r >> 12, n = r & 4095;
                int h = e >> 6, dh = e & 63;
                float* d0 = C + (((size_t)((b << 3) + h) * Nn + n) * DHd + dh);
                *(float2*)d0 = v01;
                *(float2*)(d0 + 8 * DHd) = v23;
            } else {
                size_t b0 = (size_t)r * Dd + e;
                float2 x0 = *(const float2*)(xres + b0);
                float2 x1 = *(const float2*)(xres + b0 + 8 * Dd);
                float2 bv = *(const float2*)(bo + e);
                *(float2*)(C + b0) = make_float2(x0.x + bv.x + v01.x, x0.y + bv.y + v01.y);
                *(float2*)(C + b0 + 8 * Dd) = make_float2(x1.x + bv.x + v23.x, x1.y + bv.y + v23.y);
            }
        }
    }
}

// -------------------- phi_k: td = (k*nrm)@proj^T -> g_kp, diag, per-head max -------
__global__ __launch_bounds__(256) void k_phi_k(const float* __restrict__ proj) {
    __shared__ float Ks[64][68];   // [dh][n]
    __shared__ float Ps[64][68];   // [dh][m]
    __shared__ float red[256];
    int tid = threadIdx.x;
    int n0 = blockIdx.x * 64;
    int m0 = blockIdx.y * 64;
    int bh = blockIdx.z;

#pragma unroll
    for (int i = 0; i < 4; i++) {
        int s = tid + i * 256;
        int row = s >> 4;
        int kc = (s & 15) << 2;
        float4 a = *(const float4*)(g_k + ((size_t)bh * Nn + n0 + row) * DHd + kc);
        Ks[kc + 0][row] = a.x * NORMALIZER; Ks[kc + 1][row] = a.y * NORMALIZER;
        Ks[kc + 2][row] = a.z * NORMALIZER; Ks[kc + 3][row] = a.w * NORMALIZER;
        float4 p = make_float4(0.f, 0.f, 0.f, 0.f);
        if (m0 + row < Mm) p = *(const float4*)(proj + (size_t)(m0 + row) * DHd + kc);
        Ps[kc + 0][row] = p.x; Ps[kc + 1][row] = p.y;
        Ps[kc + 2][row] = p.z; Ps[kc + 3][row] = p.w;
    }
    __syncthreads();

    if (m0 == 0 && tid < 64) {
        float ss = 0.f;
#pragma unroll
        for (int d = 0; d < 64; d++) { float q = Ks[d][tid]; ss += q * q; }
        g_diag[(size_t)bh * Nn + n0 + tid] = 0.5f * ss;
    }

    u64t acc2[2][4];
#pragma unroll
    for (int i = 0; i < 2; i++)
#pragma unroll
        for (int j = 0; j < 4; j++) acc2[i][j] = 0ull;
    int ty = tid >> 4, tx = tid & 15;
#pragma unroll
    for (int kk = 0; kk < 64; kk++) {
        float4 a = *(const float4*)&Ks[kk][ty * 4];
        float4 b = *(const float4*)&Ps[kk][tx * 4];
        F32X2_STEP(a, b);
    }

    float mymax = -3.0e38f;
#pragma unroll
    for (int i = 0; i < 4; i++) {
        int n = n0 + ty * 4 + i;
#pragma unroll
        for (int j = 0; j < 4; j++) {
            int m = m0 + tx * 4 + j;
            if (m < Mm) {
                float av = ACC2F(i, j);
                g_kp[((size_t)bh * Nn + n) * Mm + m] = av;
                mymax = fmaxf(mymax, av);
            }
        }
    }
    red[tid] = mymax;
    __syncthreads();
    for (int off = 128; off > 0; off >>= 1) {
        if (tid < off) red[tid] = fmaxf(red[tid], red[tid + off]);
        __syncthreads();
    }
    if (tid == 0) atomicMaxF(&g_kmax[bh], red[0]);
}

// -------------------- ctx fused: exp(td) in-fill (MLP-batched) + MMA + ksum --------
__global__ __launch_bounds__(256) void k_ctx() {
    __shared__ float Ksm[64][68];   // [n][m]  (kp values)
    __shared__ float Vs[64][68];    // [n][dh]
    __shared__ float diag_s[512];   // diag for the whole n-slab
    __shared__ float rsum[256];
    int tid = threadIdx.x;
    int m0 = blockIdx.x * 64;
    int nc = blockIdx.y * 512;
    int bh = blockIdx.z;
    float mx = g_kmax[bh];

    diag_s[tid]       = g_diag[(size_t)bh * Nn + nc + tid];
    diag_s[tid + 256] = g_diag[(size_t)bh * Nn + nc + 256 + tid];

    u64t acc2[2][4];
#pragma unroll
    for (int i = 0; i < 2; i++)
#pragma unroll
        for (int j = 0; j < 4; j++) acc2[i][j] = 0ull;
    int ty = tid >> 4, tx = tid & 15;

    int mmc = m0 + (tid & 63);
    bool mok = mmc < Mm;
    int nbase = tid >> 6;
    float cs = 0.f;
    __syncthreads();

    for (int nt = 0; nt < 8; nt++) {
        int n0 = nc + nt * 64;
        float tdv[16];
        const float* kpb = g_kp + ((size_t)bh * Nn + n0 + nbase) * Mm + mmc;
#pragma unroll
        for (int i = 0; i < 16; i++)
            tdv[i] = mok ? kpb[(size_t)(i * 4) * Mm] : 0.f;
#pragma unroll
        for (int i = 0; i < 16; i++) {
            int n = i * 4 + nbase;
            float v = 0.f;
            if (mok) {
                v = RATIO * (fast_exp(tdv[i] - diag_s[nt * 64 + n] - mx) + EPSF);
                cs += v;
            }
            Ksm[n][tid & 63] = v;
        }
#pragma unroll
        for (int i = 0; i < 4; i++) {
            int s = tid + i * 256;
            int n = s >> 4, c = (s & 15) << 2;
            float4 v = *(const float4*)(g_v + ((size_t)bh * Nn + n0 + n) * DHd + c);
            Vs[n][c] = v.x; Vs[n][c + 1] = v.y; Vs[n][c + 2] = v.z; Vs[n][c + 3] = v.w;
        }
        __syncthreads();
#pragma unroll
        for (int kk = 0; kk < 64; kk++) {
            float4 a = *(const float4*)&Ksm[kk][ty * 4];
            float4 b = *(const float4*)&Vs[kk][tx * 4];
            F32X2_STEP(a, b);
        }
        __syncthreads();
    }
#pragma unroll
    for (int i = 0; i < 4; i++) {
        int m = m0 + ty * 4 + i;
        if (m < Mm)
#pragma unroll
            for (int j = 0; j < 4; j++)
                atomicAdd(&g_ctx[((size_t)bh * Mm + m) * DHd + tx * 4 + j], ACC2F(i, j));
    }
    rsum[tid] = cs;
    __syncthreads();
    if (tid < 64) {
        int m = m0 + tid;
        if (m < Mm) {
            float t = rsum[tid] + rsum[tid + 64] + rsum[tid + 128] + rsum[tid + 192];
            atomicAdd(&g_ksum[bh * Mm + m], t);
        }
    }
}

// ------------- phi_q + out FUSED: td -> exp (smem) -> out GEMM -> attn2 -------------
#define QO_SMEM_FLOATS (4352 + 4352 + 64 * MPAD + MPAD + 64 + 64)
__global__ __launch_bounds__(256) void k_phi_q_out(const float* __restrict__ proj) {
    extern __shared__ float sm[];
    float* Qs     = sm;                        // [dh][n] 64*68
    float* Ps     = sm + 4352;                 // proj tiles; reused as Cs [kk][dh] 64*68
    float* tds    = sm + 8704;                 // [n][MPAD]; td then qp in place
    float* ksum_s = sm + 8704 + 64 * MPAD;     // MPAD
    float* diag_s = ksum_s + MPAD;             // 64
    float* dinv_s = diag_s + 64;               // 64

    int tid = threadIdx.x;
    int n0 = blockIdx.x * 64;
    int bh = blockIdx.y;

    for (int i = tid; i < Mm; i += 256) ksum_s[i] = g_ksum[bh * Mm + i];

#pragma unroll
    for (int i = 0; i < 4; i++) {
        int s = tid + i * 256;
        int row = s >> 4;
        int kc = (s & 15) << 2;
        float4 a = *(const float4*)(g_q + ((size_t)bh * Nn + n0 + row) * DHd + kc);
        Qs[(kc + 0) * 68 + row] = a.x * NORMALIZER;
        Qs[(kc + 1) * 68 + row] = a.y * NORMALIZER;
        Qs[(kc + 2) * 68 + row] = a.z * NORMALIZER;
        Qs[(kc + 3) * 68 + row] = a.w * NORMALIZER;
    }
    __syncthreads();
    if (tid < 64) {
        float ss = 0.f;
#pragma unroll
        for (int d = 0; d < 64; d++) { float q = Qs[d * 68 + tid]; ss += q * q; }
        diag_s[tid] = 0.5f * ss;
    }

    int ty = tid >> 4, tx = tid & 15;
    // ---- phase 1: td = (q*nrm) @ proj^T into tds ----
    for (int mt = 0; mt < 5; mt++) {
        int m0 = mt * 64;
#pragma unroll
        for (int i = 0; i < 4; i++) {
            int s = tid + i * 256;
            int row = s >> 4;
            int kc = (s & 15) << 2;
            float4 p = make_float4(0.f, 0.f, 0.f, 0.f);
            if (m0 + row < Mm) p = *(const float4*)(proj + (size_t)(m0 + row) * DHd + kc);
            Ps[(kc + 0) * 68 + row] = p.x;
            Ps[(kc + 1) * 68 + row] = p.y;
            Ps[(kc + 2) * 68 + row] = p.z;
            Ps[(kc + 3) * 68 + row] = p.w;
        }
        __syncthreads();
        u64t acc2[2][4];
#pragma unroll
        for (int i = 0; i < 2; i++)
#pragma unroll
            for (int j = 0; j < 4; j++) acc2[i][j] = 0ull;
#pragma unroll
        for (int kk = 0; kk < 64; kk++) {
            float4 a = *(const float4*)&Qs[kk * 68 + ty * 4];
            float4 b = *(const float4*)&Ps[kk * 68 + tx * 4];
            F32X2_STEP(a, b);
        }
#pragma unroll
        for (int i = 0; i < 4; i++)
#pragma unroll
            for (int j = 0; j < 4; j++) {
                int m = m0 + tx * 4 + j;
                if (m < Mm) tds[(ty * 4 + i) * MPAD + m] = ACC2F(i, j);
            }
        __syncthreads();
    }

    // ---- phase 2: rowmax, exp (qp overwrites td in place), dinv ----
    {
        int row = tid >> 2, lane = tid & 3;
        float pm = -3.0e38f;
        for (int m = lane; m < Mm; m += 4) pm = fmaxf(pm, tds[row * MPAD + m]);
        pm = fmaxf(pm, __shfl_xor_sync(0xffffffffu, pm, 1));
        pm = fmaxf(pm, __shfl_xor_sync(0xffffffffu, pm, 2));
        float dg = diag_s[row];
        float sum = 0.f;
        for (int m = lane; m < Mm; m += 4) {
            float v = RATIO * (fast_exp(tds[row * MPAD + m] - dg - pm) + EPSF);
            tds[row * MPAD + m] = v;
            sum += v * ksum_s[m];
        }
        sum += __shfl_xor_sync(0xffffffffu, sum, 1);
        sum += __shfl_xor_sync(0xffffffffu, sum, 2);
        if (lane == 0) dinv_s[row] = 1.0f / sum;
    }
    __syncthreads();

    // ---- phase 3: out = qp @ ctx, scaled by dinv, write attn2 split-2 bf16 ----
    u64t acc2[2][4];
#pragma unroll
    for (int i = 0; i < 2; i++)
#pragma unroll
        for (int j = 0; j < 4; j++) acc2[i][j] = 0ull;

#pragma unroll 1
    for (int ch = 0; ch < 5; ch++) {
        int c0 = ch * 64;
#pragma unroll
        for (int i = 0; i < 16; i++) {
            int s = tid + i * 256;
            int kk = s >> 6, dh = s & 63;
            Ps[kk * 68 + dh] = (c0 + kk < Mm)
                                   ? g_ctx[((size_t)bh * Mm + c0 + kk) * DHd + dh]
                                   : 0.f;
        }
        __syncthreads();
        if (ch < 4) {
#pragma unroll
            for (int kk = 0; kk < 64; kk++) {
                float4 a = make_float4(tds[(ty * 4 + 0) * MPAD + c0 + kk],
                                       tds[(ty * 4 + 1) * MPAD + c0 + kk],
                                       tds[(ty * 4 + 2) * MPAD + c0 + kk],
                                       tds[(ty * 4 + 3) * MPAD + c0 + kk]);
                float4 b = *(const float4*)&Ps[kk * 68 + tx * 4];
                F32X2_STEP(a, b);
            }
        } else {
#pragma unroll
            for (int kk = 0; kk < 10; kk++) {
                float4 a = make_float4(tds[(ty * 4 + 0) * MPAD + c0 + kk],
                                       tds[(ty * 4 + 1) * MPAD + c0 + kk],
                                       tds[(ty * 4 + 2) * MPAD + c0 + kk],
                                       tds[(ty * 4 + 3) * MPAD + c0 + kk]);
                float4 b = *(const float4*)&Ps[kk * 68 + tx * 4];
                F32X2_STEP(a, b);
            }
        }
        __syncthreads();
    }

    int b = bh >> 3, h = bh & 7;
#pragma unroll
    for (int i = 0; i < 4; i++) {
        int n = n0 + ty * 4 + i;
        float dv = dinv_s[ty * 4 + i];
        size_t rb = (size_t)(b * Nn + n) * K2 + h * 64 + tx * 4;
        float v0 = ACC2F(i, 0) * dv, v1 = ACC2F(i, 1) * dv;
        float v2 = ACC2F(i, 2) * dv, v3 = ACC2F(i, 3) * dv;
        __nv_bfloat162 H01, L01, H23, L23;
        H01.x = __float2bfloat16(v0); L01.x = __float2bfloat16(v0 - __bfloat162float(H01.x));
        H01.y = __float2bfloat16(v1); L01.y = __float2bfloat16(v1 - __bfloat162float(H01.y));
        H23.x = __float2bfloat16(v2); L23.x = __float2bfloat16(v2 - __bfloat162float(H23.x));
        H23.y = __float2bfloat16(v3); L23.y = __float2bfloat16(v3 - __bfloat162float(H23.y));
        *(__nv_bfloat162*)(g_attn2 + rb)           = H01;
        *(__nv_bfloat162*)(g_attn2 + rb + 2)       = H23;
        *(__nv_bfloat162*)(g_attn2 + rb + 512)     = L01;
        *(__nv_bfloat162*)(g_attn2 + rb + 512 + 2) = L23;
    }
}

// -------------------- launch --------------------
extern "C" void kernel_launch(void* const* d_in, const int* in_sizes, int n_in,
                              void* d_out, int out_size) {
    const float* x    = (const float*)d_in[0];
    const float* Wq   = (const float*)d_in[1];
    const float* Wk   = (const float*)d_in[2];
    const float* Wv   = (const float*)d_in[3];
    const float* Wo   = (const float*)d_in[4];
    const float* bo   = (const float*)d_in[5];
    const float* proj = (const float*)d_in[6];
    float* out = (float*)d_out;
    (void)in_sizes; (void)n_in; (void)out_size;

    cudaFuncSetAttribute(k_phi_q_out, cudaFuncAttributeMaxDynamicSharedMemorySize,
                         QO_SMEM_FLOATS * (int)sizeof(float));
    cudaFuncSetAttribute(k_gemm, cudaFuncAttributeMaxDynamicSharedMemorySize, GEMM_DSMEM);

    __nv_bfloat16 *x2p, *wq2p, *wk2p, *wv2p, *wo2p, *attn2p;
    cudaGetSymbolAddress((void**)&x2p, g_x2);
    cudaGetSymbolAddress((void**)&wq2p, g_wq2);
    cudaGetSymbolAddress((void**)&wk2p, g_wk2);
    cudaGetSymbolAddress((void**)&wv2p, g_wv2);
    cudaGetSymbolAddress((void**)&wo2p, g_wo2);
    cudaGetSymbolAddress((void**)&attn2p, g_attn2);
    float *qp_, *kp_, *vp_;
    cudaGetSymbolAddress((void**)&qp_, g_q);
    cudaGetSymbolAddress((void**)&kp_, g_k);
    cudaGetSymbolAddress((void**)&vp_, g_v);

    k_init<<<(BHh * Mm * DHd + 255) / 256, 256>>>();
    // A-layouts: [hi|lo]; W-layouts: [hi|hi]
    k_split<<<(BNn * 128 + 255) / 256, 256>>>(x, x2p, BNn, 512, 0);
    k_split<<<(Dd * 128 + 255) / 256, 256>>>(Wq, wq2p, Dd, 0, 512);
    k_split<<<(Dd * 128 + 255) / 256, 256>>>(Wk, wk2p, Dd, 0, 512);
    k_split<<<(Dd * 128 + 255) / 256, 256>>>(Wv, wv2p, Dd, 0, 512);

    dim3 gG(BNn / 128, Dd / 128);
    k_gemm<<<gG, 256, GEMM_DSMEM>>>(x2p, wq2p, qp_, nullptr, nullptr, 0);
    k_gemm<<<gG, 256, GEMM_DSMEM>>>(x2p, wk2p, kp_, nullptr, nullptr, 0);
    k_gemm<<<gG, 256, GEMM_DSMEM>>>(x2p, wv2p, vp_, nullptr, nullptr, 0);

    k_split<<<(Dd * 128 + 255) / 256, 256>>>(Wo, wo2p, Dd, 0, 512);

    k_phi_k<<<dim3(Nn / 64, 5, BHh), 256>>>(proj);
    k_ctx<<<dim3(5, Nn / 512, BHh), 256>>>();
    k_phi_q_out<<<dim3(Nn / 64, BHh), 256, QO_SMEM_FLOATS * (int)sizeof(float)>>>(proj);

    k_gemm<<<gG, 256, GEMM_DSMEM>>>(attn2p, wo2p, out, x, bo, 1);
}

// round 15
// speedup vs baseline: 1.6700x; 1.1605x over previous
#include <cuda_runtime.h>
#include <cuda_fp16.h>
#include <stdint.h>
#include <math.h>

#define Bb   4
#define Nn   4096
#define Dd   512
#define Hh   8
#define DHd  64
#define Mm   266
#define BHh  32          // B*H
#define BNn  16384       // B*N
#define MPAD 269         // td row stride
#define K2   512         // plain fp16 GEMM K (no split)

// -------------------- scratch (static device memory; no allocs) --------------------
__device__ float g_q  [(size_t)BHh * Nn * DHd];
__device__ float g_k  [(size_t)BHh * Nn * DHd];
__device__ float g_v  [(size_t)BHh * Nn * DHd];
__device__ float g_kp [(size_t)BHh * Nn * Mm];   // holds td_k; exp applied inside k_ctx
__device__ float g_ctx [(size_t)BHh * Mm * DHd];
__device__ float g_ksum[(size_t)BHh * Mm];
__device__ float g_kmax[BHh];
__device__ float g_diag[(size_t)BHh * Nn];

__device__ __half g_x2   [(size_t)BNn * K2];
__device__ __half g_attn2[(size_t)BNn * K2];
__device__ __half g_wq2  [(size_t)Dd * K2];
__device__ __half g_wk2  [(size_t)Dd * K2];
__device__ __half g_wv2  [(size_t)Dd * K2];
__device__ __half g_wo2  [(size_t)Dd * K2];

// -------------------- helpers --------------------
typedef unsigned long long u64t;

__device__ __forceinline__ uint32_t smem_to_u32(const void* p) {
    uint32_t a;
    asm("{ .reg .u64 t; cvta.to.shared.u64 t, %1; cvt.u32.u64 %0, t; }"
        : "=r"(a) : "l"(p));
    return a;
}

#define CP_ASYNC16(dst, src) \
    asm volatile("cp.async.cg.shared.global [%0], [%1], 16;" \
                 :: "r"(dst), "l"(src) : "memory")
#define CP_COMMIT()  asm volatile("cp.async.commit_group;" ::: "memory")
#define CP_WAIT1()   asm volatile("cp.async.wait_group 1;" ::: "memory")
#define CP_WAIT0()   asm volatile("cp.async.wait_group 0;" ::: "memory")

__device__ __forceinline__ void ldm_x4(uint32_t& r0, uint32_t& r1,
                                       uint32_t& r2, uint32_t& r3, uint32_t addr) {
    asm volatile("ldmatrix.sync.aligned.m8n8.x4.shared.b16 {%0,%1,%2,%3}, [%4];"
                 : "=r"(r0), "=r"(r1), "=r"(r2), "=r"(r3) : "r"(addr));
}

__device__ __forceinline__ void mma16816(float* c, const uint32_t* a, const uint32_t* b) {
    asm volatile(
        "mma.sync.aligned.m16n8k16.row.col.f32.f16.f16.f32 "
        "{%0,%1,%2,%3}, {%4,%5,%6,%7}, {%8,%9}, {%0,%1,%2,%3};"
        : "+f"(c[0]), "+f"(c[1]), "+f"(c[2]), "+f"(c[3])
        : "r"(a[0]), "r"(a[1]), "r"(a[2]), "r"(a[3]), "r"(b[0]), "r"(b[1]));
}

// ---- packed fp32x2 FMA (Blackwell base ISA) ----
__device__ __forceinline__ u64t pack2(float x, float y) {
    u64t r;
    asm("mov.b64 %0, {%1, %2};" : "=l"(r) : "f"(x), "f"(y));
    return r;
}
__device__ __forceinline__ u64t bcast2(float v) {
    u64t r;
    asm("mov.b64 %0, {%1, %1};" : "=l"(r) : "f"(v));
    return r;
}
__device__ __forceinline__ void ffma2(u64t& c, u64t a, u64t b) {
    asm("fma.rn.f32x2 %0, %1, %2, %0;" : "+l"(c) : "l"(a), "l"(b));
}
__device__ __forceinline__ float lane0(u64t v) { float2 t; *(u64t*)&t = v; return t.x; }
__device__ __forceinline__ float lane1(u64t v) { float2 t; *(u64t*)&t = v; return t.y; }
#define ACC2F(i, j) (((i) & 1) ? lane1(acc2[(i) >> 1][j]) : lane0(acc2[(i) >> 1][j]))

#define F32X2_STEP(a4, b4) do {                                   \
    u64t a01 = pack2((a4).x, (a4).y), a23 = pack2((a4).z, (a4).w);\
    u64t bb0 = bcast2((b4).x), bb1 = bcast2((b4).y);              \
    u64t bb2 = bcast2((b4).z), bb3 = bcast2((b4).w);              \
    ffma2(acc2[0][0], a01, bb0); ffma2(acc2[0][1], a01, bb1);     \
    ffma2(acc2[0][2], a01, bb2); ffma2(acc2[0][3], a01, bb3);     \
    ffma2(acc2[1][0], a23, bb0); ffma2(acc2[1][1], a23, bb1);     \
    ffma2(acc2[1][2], a23, bb2); ffma2(acc2[1][3], a23, bb3);     \
} while (0)

__device__ __forceinline__ void atomicMaxF(float* addr, float val) {
    int* ai = (int*)addr;
    int old = *ai;
    while (__int_as_float(old) < val) {
        int assumed = old;
        old = atomicCAS(ai, assumed, __float_as_int(val));
        if (old == assumed) break;
    }
}

__device__ __forceinline__ float fast_exp(float x) {
    float y = fmaxf(x * 1.4426950408889634f, -126.0f);
    float r = rintf(y);
    float f = y - r;
    float p = 1.5403530e-4f;
    p = fmaf(p, f, 1.3333558e-3f);
    p = fmaf(p, f, 9.6181291e-3f);
    p = fmaf(p, f, 5.5504109e-2f);
    p = fmaf(p, f, 2.4022651e-1f);
    p = fmaf(p, f, 6.9314718e-1f);
    p = fmaf(p, f, 1.0f);
    int e = (int)r;
    float s = __int_as_float((e + 127) << 23);
    return p * s;
}

#define NORMALIZER 0.35355339059327373f   // 64^-0.25
#define RATIO      0.061313934f           // 266^-0.5
#define EPSF       1e-4f

// -------------------- init scratch accumulators --------------------
__global__ void k_init() {
    int i = blockIdx.x * 256 + threadIdx.x;
    if (i < BHh * Mm * DHd) g_ctx[i]  = 0.0f;
    if (i < BHh * Mm)       g_ksum[i] = 0.0f;
    if (i < BHh)            g_kmax[i] = -3.0e38f;
}

// -------------------- fp32 -> fp16 convert --------------------
__global__ __launch_bounds__(256) void k_half(const float* __restrict__ src,
                                              __half* __restrict__ dst, int nrows) {
    int i = blockIdx.x * 256 + threadIdx.x;
    if (i >= nrows * 128) return;
    int r = i >> 7;
    int c = (i & 127) << 2;
    float4 v = *(const float4*)(src + (size_t)r * 512 + c);
    __half2 h01 = __floats2half2_rn(v.x, v.y);
    __half2 h23 = __floats2half2_rn(v.z, v.w);
    size_t rb = (size_t)r * K2 + c;
    *(__half2*)(dst + rb)     = h01;
    *(__half2*)(dst + rb + 2) = h23;
}

// -------------------- mma.sync GEMM: C[16384,512] = A2[16384,512] @ B2[512,512]^T --------
#define ASTR 40
#define TILE_B (128 * ASTR)
#define GEMM_DSMEM (6 * TILE_B * 2)   // 61440 bytes

__global__ __launch_bounds__(256) void k_gemm(const __half* __restrict__ A,
                                              const __half* __restrict__ Bw,
                                              float* __restrict__ C,
                                              const float* __restrict__ xres,
                                              const float* __restrict__ bo,
                                              int finalmode) {
    extern __shared__ __half dyn[];
    int tid = threadIdx.x, lane = tid & 31, w = tid >> 5;
    int m0 = (w & 3) * 32, n0 = (w >> 2) * 64;
    int r0 = blockIdx.x * 128, e0 = blockIdx.y * 128;
    uint32_t sAu = smem_to_u32(dyn);
    uint32_t sBu = sAu + 3u * (TILE_B * 2);

    float acc[2][8][4];
#pragma unroll
    for (int i = 0; i < 2; i++)
#pragma unroll
        for (int j = 0; j < 8; j++)
#pragma unroll
            for (int l = 0; l < 4; l++) acc[i][j][l] = 0.f;

    int lrow = tid >> 1;
    int lcol = (tid & 1) << 4;
    const __half* Arow = A + (size_t)(r0 + lrow) * K2 + lcol;
    const __half* Brow = Bw + (size_t)(e0 + lrow) * K2 + lcol;
    uint32_t sAdst = sAu + (uint32_t)(lrow * ASTR + lcol) * 2;
    uint32_t sBdst = sBu + (uint32_t)(lrow * ASTR + lcol) * 2;

#define LOAD_TILE(buf, t) do {                                         \
    uint32_t _o = (uint32_t)(buf) * (TILE_B * 2);                      \
    const __half* _a = Arow + (t) * 32;                                \
    const __half* _b = Brow + (t) * 32;                                \
    CP_ASYNC16(sAdst + _o,      _a);                                   \
    CP_ASYNC16(sAdst + _o + 16, _a + 8);                               \
    CP_ASYNC16(sBdst + _o,      _b);                                   \
    CP_ASYNC16(sBdst + _o + 16, _b + 8);                               \
} while (0)

    LOAD_TILE(0, 0);
    CP_COMMIT();
    LOAD_TILE(1, 1);
    CP_COMMIT();

    const int NT = K2 / 32;   // 16
    int buf = 0;
#pragma unroll 1
    for (int t = 0; t < NT; ++t) {
        if (t + 1 < NT) CP_WAIT1(); else CP_WAIT0();
        __syncthreads();
        if (t + 2 < NT) {
            int nb = buf + 2; if (nb >= 3) nb -= 3;
            LOAD_TILE(nb, t + 2);
            CP_COMMIT();
        }
        uint32_t ab = sAu + (uint32_t)buf * (TILE_B * 2);
        uint32_t bb = sBu + (uint32_t)buf * (TILE_B * 2);
#pragma unroll
        for (int ks = 0; ks < 32; ks += 16) {
            uint32_t a[2][4];
#pragma unroll
            for (int mt = 0; mt < 2; mt++) {
                uint32_t addr = ab +
                    (uint32_t)((m0 + mt * 16 + (lane & 15)) * ASTR + ks + ((lane >> 4) << 3)) * 2;
                ldm_x4(a[mt][0], a[mt][1], a[mt][2], a[mt][3], addr);
            }
            uint32_t b[8][2];
#pragma unroll
            for (int p = 0; p < 4; p++) {
                int nA = n0 + p * 16;
                uint32_t addr = bb +
                    (uint32_t)((nA + (lane & 7) + ((lane >> 4) << 3)) * ASTR + ks + (lane & 8)) * 2;
                ldm_x4(b[2 * p][0], b[2 * p][1], b[2 * p + 1][0], b[2 * p + 1][1], addr);
            }
#pragma unroll
            for (int mt = 0; mt < 2; mt++)
#pragma unroll
                for (int nt = 0; nt < 8; nt++)
                    mma16816(acc[mt][nt], a[mt], b[nt]);
        }
        if (++buf == 3) buf = 0;
    }

    int gid = lane >> 2, tig = lane & 3;
#pragma unroll
    for (int mt = 0; mt < 2; mt++) {
#pragma unroll
        for (int nt = 0; nt < 8; nt++) {
            int r = r0 + m0 + mt * 16 + gid;
            int e = e0 + n0 + nt * 8 + tig * 2;
            float2 v01 = make_float2(acc[mt][nt][0], acc[mt][nt][1]);
            float2 v23 = make_float2(acc[mt][nt][2], acc[mt][nt][3]);
            if (!finalmode) {
                int b = r >> 12, n = r & 4095;
                int h = e >> 6, dh = e & 63;
                float* d0 = C + (((size_t)((b << 3) + h) * Nn + n) * DHd + dh);
                *(float2*)d0 = v01;
                *(float2*)(d0 + 8 * DHd) = v23;
            } else {
                size_t b0 = (size_t)r * Dd + e;
                float2 x0 = *(const float2*)(xres + b0);
                float2 x1 = *(const float2*)(xres + b0 + 8 * Dd);
                float2 bv = *(const float2*)(bo + e);
                *(float2*)(C + b0) = make_float2(x0.x + bv.x + v01.x, x0.y + bv.y + v01.y);
                *(float2*)(C + b0 + 8 * Dd) = make_float2(x1.x + bv.x + v23.x, x1.y + bv.y + v23.y);
            }
        }
    }
}

// -------------------- phi_k: td = (k*nrm)@proj^T -> g_kp, diag, per-head max -------
__global__ __launch_bounds__(256) void k_phi_k(const float* __restrict__ proj) {
    __shared__ float Ks[64][68];   // [dh][n]
    __shared__ float Ps[64][68];   // [dh][m]
    __shared__ float red[256];
    int tid = threadIdx.x;
    int n0 = blockIdx.x * 64;
    int m0 = blockIdx.y * 64;
    int bh = blockIdx.z;

#pragma unroll
    for (int i = 0; i < 4; i++) {
        int s = tid + i * 256;
        int row = s >> 4;
        int kc = (s & 15) << 2;
        float4 a = *(const float4*)(g_k + ((size_t)bh * Nn + n0 + row) * DHd + kc);
        Ks[kc + 0][row] = a.x * NORMALIZER; Ks[kc + 1][row] = a.y * NORMALIZER;
        Ks[kc + 2][row] = a.z * NORMALIZER; Ks[kc + 3][row] = a.w * NORMALIZER;
        float4 p = make_float4(0.f, 0.f, 0.f, 0.f);
        if (m0 + row < Mm) p = *(const float4*)(proj + (size_t)(m0 + row) * DHd + kc);
        Ps[kc + 0][row] = p.x; Ps[kc + 1][row] = p.y;
        Ps[kc + 2][row] = p.z; Ps[kc + 3][row] = p.w;
    }
    __syncthreads();

    if (m0 == 0 && tid < 64) {
        float ss = 0.f;
#pragma unroll
        for (int d = 0; d < 64; d++) { float q = Ks[d][tid]; ss += q * q; }
        g_diag[(size_t)bh * Nn + n0 + tid] = 0.5f * ss;
    }

    u64t acc2[2][4];
#pragma unroll
    for (int i = 0; i < 2; i++)
#pragma unroll
        for (int j = 0; j < 4; j++) acc2[i][j] = 0ull;
    int ty = tid >> 4, tx = tid & 15;
#pragma unroll
    for (int kk = 0; kk < 64; kk++) {
        float4 a = *(const float4*)&Ks[kk][ty * 4];
        float4 b = *(const float4*)&Ps[kk][tx * 4];
        F32X2_STEP(a, b);
    }

    float mymax = -3.0e38f;
#pragma unroll
    for (int i = 0; i < 4; i++) {
        int n = n0 + ty * 4 + i;
#pragma unroll
        for (int j = 0; j < 4; j++) {
            int m = m0 + tx * 4 + j;
            if (m < Mm) {
                float av = ACC2F(i, j);
                g_kp[((size_t)bh * Nn + n) * Mm + m] = av;
                mymax = fmaxf(mymax, av);
            }
        }
    }
    red[tid] = mymax;
    __syncthreads();
    for (int off = 128; off > 0; off >>= 1) {
        if (tid < off) red[tid] = fmaxf(red[tid], red[tid + off]);
        __syncthreads();
    }
    if (tid == 0) atomicMaxF(&g_kmax[bh], red[0]);
}

// -------------------- ctx fused: exp(td) in-fill (MLP-batched) + MMA + ksum --------
__global__ __launch_bounds__(256) void k_ctx() {
    __shared__ float Ksm[64][68];   // [n][m]  (kp values)
    __shared__ float Vs[64][68];    // [n][dh]
    __shared__ float diag_s[512];   // diag for the whole n-slab
    __shared__ float rsum[256];
    int tid = threadIdx.x;
    int m0 = blockIdx.x * 64;
    int nc = blockIdx.y * 512;
    int bh = blockIdx.z;
    float mx = g_kmax[bh];

    diag_s[tid]       = g_diag[(size_t)bh * Nn + nc + tid];
    diag_s[tid + 256] = g_diag[(size_t)bh * Nn + nc + 256 + tid];

    u64t acc2[2][4];
#pragma unroll
    for (int i = 0; i < 2; i++)
#pragma unroll
        for (int j = 0; j < 4; j++) acc2[i][j] = 0ull;
    int ty = tid >> 4, tx = tid & 15;

    int mmc = m0 + (tid & 63);
    bool mok = mmc < Mm;
    int nbase = tid >> 6;
    float cs = 0.f;
    __syncthreads();

    for (int nt = 0; nt < 8; nt++) {
        int n0 = nc + nt * 64;
        float tdv[16];
        const float* kpb = g_kp + ((size_t)bh * Nn + n0 + nbase) * Mm + mmc;
#pragma unroll
        for (int i = 0; i < 16; i++)
            tdv[i] = mok ? kpb[(size_t)(i * 4) * Mm] : 0.f;
#pragma unroll
        for (int i = 0; i < 16; i++) {
            int n = i * 4 + nbase;
            float v = 0.f;
            if (mok) {
                v = RATIO * (fast_exp(tdv[i] - diag_s[nt * 64 + n] - mx) + EPSF);
                cs += v;
            }
            Ksm[n][tid & 63] = v;
        }
#pragma unroll
        for (int i = 0; i < 4; i++) {
            int s = tid + i * 256;
            int n = s >> 4, c = (s & 15) << 2;
            float4 v = *(const float4*)(g_v + ((size_t)bh * Nn + n0 + n) * DHd + c);
            Vs[n][c] = v.x; Vs[n][c + 1] = v.y; Vs[n][c + 2] = v.z; Vs[n][c + 3] = v.w;
        }
        __syncthreads();
#pragma unroll
        for (int kk = 0; kk < 64; kk++) {
            float4 a = *(const float4*)&Ksm[kk][ty * 4];
            float4 b = *(const float4*)&Vs[kk][tx * 4];
            F32X2_STEP(a, b);
        }
        __syncthreads();
    }
#pragma unroll
    for (int i = 0; i < 4; i++) {
        int m = m0 + ty * 4 + i;
        if (m < Mm)
#pragma unroll
            for (int j = 0; j < 4; j++)
                atomicAdd(&g_ctx[((size_t)bh * Mm + m) * DHd + tx * 4 + j], ACC2F(i, j));
    }
    rsum[tid] = cs;
    __syncthreads();
    if (tid < 64) {
        int m = m0 + tid;
        if (m < Mm) {
            float t = rsum[tid] + rsum[tid + 64] + rsum[tid + 128] + rsum[tid + 192];
            atomicAdd(&g_ksum[bh * Mm + m], t);
        }
    }
}

// ------------- phi_q + out FUSED: td -> exp (smem) -> out GEMM -> attn2 -------------
#define QO_SMEM_FLOATS (4352 + 4352 + 64 * MPAD + MPAD + 64 + 64)
__global__ __launch_bounds__(256) void k_phi_q_out(const float* __restrict__ proj) {
    extern __shared__ float sm[];
    float* Qs     = sm;                        // [dh][n] 64*68
    float* Ps     = sm + 4352;                 // proj tiles; reused as Cs [kk][dh] 64*68
    float* tds    = sm + 8704;                 // [n][MPAD]; td then qp in place
    float* ksum_s = sm + 8704 + 64 * MPAD;     // MPAD
    float* diag_s = ksum_s + MPAD;             // 64
    float* dinv_s = diag_s + 64;               // 64

    int tid = threadIdx.x;
    int n0 = blockIdx.x * 64;
    int bh = blockIdx.y;

    for (int i = tid; i < Mm; i += 256) ksum_s[i] = g_ksum[bh * Mm + i];

#pragma unroll
    for (int i = 0; i < 4; i++) {
        int s = tid + i * 256;
        int row = s >> 4;
        int kc = (s & 15) << 2;
        float4 a = *(const float4*)(g_q + ((size_t)bh * Nn + n0 + row) * DHd + kc);
        Qs[(kc + 0) * 68 + row] = a.x * NORMALIZER;
        Qs[(kc + 1) * 68 + row] = a.y * NORMALIZER;
        Qs[(kc + 2) * 68 + row] = a.z * NORMALIZER;
        Qs[(kc + 3) * 68 + row] = a.w * NORMALIZER;
    }
    __syncthreads();
    if (tid < 64) {
        float ss = 0.f;
#pragma unroll
        for (int d = 0; d < 64; d++) { float q = Qs[d * 68 + tid]; ss += q * q; }
        diag_s[tid] = 0.5f * ss;
    }

    int ty = tid >> 4, tx = tid & 15;
    // ---- phase 1: td = (q*nrm) @ proj^T into tds ----
    for (int mt = 0; mt < 5; mt++) {
        int m0 = mt * 64;
#pragma unroll
        for (int i = 0; i < 4; i++) {
            int s = tid + i * 256;
            int row = s >> 4;
            int kc = (s & 15) << 2;
            float4 p = make_float4(0.f, 0.f, 0.f, 0.f);
            if (m0 + row < Mm) p = *(const float4*)(proj + (size_t)(m0 + row) * DHd + kc);
            Ps[(kc + 0) * 68 + row] = p.x;
            Ps[(kc + 1) * 68 + row] = p.y;
            Ps[(kc + 2) * 68 + row] = p.z;
            Ps[(kc + 3) * 68 + row] = p.w;
        }
        __syncthreads();
        u64t acc2[2][4];
#pragma unroll
        for (int i = 0; i < 2; i++)
#pragma unroll
            for (int j = 0; j < 4; j++) acc2[i][j] = 0ull;
#pragma unroll
        for (int kk = 0; kk < 64; kk++) {
            float4 a = *(const float4*)&Qs[kk * 68 + ty * 4];
            float4 b = *(const float4*)&Ps[kk * 68 + tx * 4];
            F32X2_STEP(a, b);
        }
#pragma unroll
        for (int i = 0; i < 4; i++)
#pragma unroll
            for (int j = 0; j < 4; j++) {
                int m = m0 + tx * 4 + j;
                if (m < Mm) tds[(ty * 4 + i) * MPAD + m] = ACC2F(i, j);
            }
        __syncthreads();
    }

    // ---- phase 2: rowmax, exp (qp overwrites td in place), dinv ----
    {
        int row = tid >> 2, lane = tid & 3;
        float pm = -3.0e38f;
        for (int m = lane; m < Mm; m += 4) pm = fmaxf(pm, tds[row * MPAD + m]);
        pm = fmaxf(pm, __shfl_xor_sync(0xffffffffu, pm, 1));
        pm = fmaxf(pm, __shfl_xor_sync(0xffffffffu, pm, 2));
        float dg = diag_s[row];
        float sum = 0.f;
        for (int m = lane; m < Mm; m += 4) {
            float v = RATIO * (fast_exp(tds[row * MPAD + m] - dg - pm) + EPSF);
            tds[row * MPAD + m] = v;
            sum += v * ksum_s[m];
        }
        sum += __shfl_xor_sync(0xffffffffu, sum, 1);
        sum += __shfl_xor_sync(0xffffffffu, sum, 2);
        if (lane == 0) dinv_s[row] = 1.0f / sum;
    }
    __syncthreads();

    // ---- phase 3: out = qp @ ctx, scaled by dinv, write attn2 fp16 ----
    u64t acc2[2][4];
#pragma unroll
    for (int i = 0; i < 2; i++)
#pragma unroll
        for (int j = 0; j < 4; j++) acc2[i][j] = 0ull;

#pragma unroll 1
    for (int ch = 0; ch < 5; ch++) {
        int c0 = ch * 64;
#pragma unroll
        for (int i = 0; i < 16; i++) {
            int s = tid + i * 256;
            int kk = s >> 6, dh = s & 63;
            Ps[kk * 68 + dh] = (c0 + kk < Mm)
                                   ? g_ctx[((size_t)bh * Mm + c0 + kk) * DHd + dh]
                                   : 0.f;
        }
        __syncthreads();
        if (ch < 4) {
#pragma unroll
            for (int kk = 0; kk < 64; kk++) {
                float4 a = make_float4(tds[(ty * 4 + 0) * MPAD + c0 + kk],
                                       tds[(ty * 4 + 1) * MPAD + c0 + kk],
                                       tds[(ty * 4 + 2) * MPAD + c0 + kk],
                                       tds[(ty * 4 + 3) * MPAD + c0 + kk]);
                float4 b = *(const float4*)&Ps[kk * 68 + tx * 4];
                F32X2_STEP(a, b);
            }
        } else {
#pragma unroll
            for (int kk = 0; kk < 10; kk++) {
                float4 a = make_float4(tds[(ty * 4 + 0) * MPAD + c0 + kk],
                                       tds[(ty * 4 + 1) * MPAD + c0 + kk],
                                       tds[(ty * 4 + 2) * MPAD + c0 + kk],
                                       tds[(ty * 4 + 3) * MPAD + c0 + kk]);
                float4 b = *(const float4*)&Ps[kk * 68 + tx * 4];
                F32X2_STEP(a, b);
            }
        }
        __syncthreads();
    }

    int b = bh >> 3, h = bh & 7;
#pragma unroll
    for (int i = 0; i < 4; i++) {
        int n = n0 + ty * 4 + i;
        float dv = dinv_s[ty * 4 + i];
        size_t rb = (size_t)(b * Nn + n) * K2 + h * 64 + tx * 4;
        float v0 = ACC2F(i, 0) * dv, v1 = ACC2F(i, 1) * dv;
        float v2 = ACC2F(i, 2) * dv, v3 = ACC2F(i, 3) * dv;
        *(__half2*)(g_attn2 + rb)     = __floats2half2_rn(v0, v1);
        *(__half2*)(g_attn2 + rb + 2) = __floats2half2_rn(v2, v3);
    }
}

// -------------------- launch --------------------
extern "C" void kernel_launch(void* const* d_in, const int* in_sizes, int n_in,
                              void* d_out, int out_size) {
    const float* x    = (const float*)d_in[0];
    const float* Wq   = (const float*)d_in[1];
    const float* Wk   = (const float*)d_in[2];
    const float* Wv   = (const float*)d_in[3];
    const float* Wo   = (const float*)d_in[4];
    const float* bo   = (const float*)d_in[5];
    const float* proj = (const float*)d_in[6];
    float* out = (float*)d_out;
    (void)in_sizes; (void)n_in; (void)out_size;

    cudaFuncSetAttribute(k_phi_q_out, cudaFuncAttributeMaxDynamicSharedMemorySize,
                         QO_SMEM_FLOATS * (int)sizeof(float));
    cudaFuncSetAttribute(k_gemm, cudaFuncAttributeMaxDynamicSharedMemorySize, GEMM_DSMEM);

    __half *x2p, *wq2p, *wk2p, *wv2p, *wo2p, *attn2p;
    cudaGetSymbolAddress((void**)&x2p, g_x2);
    cudaGetSymbolAddress((void**)&wq2p, g_wq2);
    cudaGetSymbolAddress((void**)&wk2p, g_wk2);
    cudaGetSymbolAddress((void**)&wv2p, g_wv2);
    cudaGetSymbolAddress((void**)&wo2p, g_wo2);
    cudaGetSymbolAddress((void**)&attn2p, g_attn2);
    float *qp_, *kp_, *vp_;
    cudaGetSymbolAddress((void**)&qp_, g_q);
    cudaGetSymbolAddress((void**)&kp_, g_k);
    cudaGetSymbolAddress((void**)&vp_, g_v);

    k_init<<<(BHh * Mm * DHd + 255) / 256, 256>>>();
    k_half<<<(BNn * 128 + 255) / 256, 256>>>(x, x2p, BNn);
    k_half<<<(Dd * 128 + 255) / 256, 256>>>(Wq, wq2p, Dd);
    k_half<<<(Dd * 128 + 255) / 256, 256>>>(Wk, wk2p, Dd);
    k_half<<<(Dd * 128 + 255) / 256, 256>>>(Wv, wv2p, Dd);

    dim3 gG(BNn / 128, Dd / 128);
    k_gemm<<<gG, 256, GEMM_DSMEM>>>(x2p, wq2p, qp_, nullptr, nullptr, 0);
    k_gemm<<<gG, 256, GEMM_DSMEM>>>(x2p, wk2p, kp_, nullptr, nullptr, 0);
    k_gemm<<<gG, 256, GEMM_DSMEM>>>(x2p, wv2p, vp_, nullptr, nullptr, 0);

    k_half<<<(Dd * 128 + 255) / 256, 256>>>(Wo, wo2p, Dd);

    k_phi_k<<<dim3(Nn / 64, 5, BHh), 256>>>(proj);
    k_ctx<<<dim3(5, Nn / 512, BHh), 256>>>();
    k_phi_q_out<<<dim3(Nn / 64, BHh), 256, QO_SMEM_FLOATS * (int)sizeof(float)>>>(proj);

    k_gemm<<<gG, 256, GEMM_DSMEM>>>(attn2p, wo2p, out, x, bo, 1);
}

// round 16
// speedup vs baseline: 2.1211x; 1.2701x over previous
#include <cuda_runtime.h>
#include <cuda_fp16.h>
#include <stdint.h>
#include <math.h>

#define Bb   4
#define Nn   4096
#define Dd   512
#define Hh   8
#define DHd  64
#define Mm   266
#define BHh  32          // B*H
#define BNn  16384       // B*N
#define K2   512         // plain fp16 GEMM K
#define MQ   272         // qp/ctx k extent (m padded to x16)
#define QSTR 280         // fp16 row stride for qph/Ch
#define PSTR 72          // fp16 row stride for Qh/Ph

// -------------------- scratch (static device memory; no allocs) --------------------
__device__ float g_q  [(size_t)BHh * Nn * DHd];
__device__ float g_k  [(size_t)BHh * Nn * DHd];
__device__ float g_v  [(size_t)BHh * Nn * DHd];
__device__ float g_kp [(size_t)BHh * Nn * Mm];   // holds td_k; exp applied inside k_ctx
__device__ float g_ctx [(size_t)BHh * Mm * DHd];
__device__ float g_ksum[(size_t)BHh * Mm];
__device__ float g_kmax[BHh];
__device__ float g_diag[(size_t)BHh * Nn];

__device__ __half g_x2   [(size_t)BNn * K2];
__device__ __half g_attn2[(size_t)BNn * K2];
__device__ __half g_wq2  [(size_t)Dd * K2];
__device__ __half g_wk2  [(size_t)Dd * K2];
__device__ __half g_wv2  [(size_t)Dd * K2];
__device__ __half g_wo2  [(size_t)Dd * K2];
__device__ __half g_projh[320 * 64];

// -------------------- helpers --------------------
typedef unsigned long long u64t;

__device__ __forceinline__ uint32_t smem_to_u32(const void* p) {
    uint32_t a;
    asm("{ .reg .u64 t; cvta.to.shared.u64 t, %1; cvt.u32.u64 %0, t; }"
        : "=r"(a) : "l"(p));
    return a;
}

#define CP_ASYNC16(dst, src) \
    asm volatile("cp.async.cg.shared.global [%0], [%1], 16;" \
                 :: "r"(dst), "l"(src) : "memory")
#define CP_COMMIT()  asm volatile("cp.async.commit_group;" ::: "memory")
#define CP_WAIT1()   asm volatile("cp.async.wait_group 1;" ::: "memory")
#define CP_WAIT0()   asm volatile("cp.async.wait_group 0;" ::: "memory")

__device__ __forceinline__ void ldm_x4(uint32_t& r0, uint32_t& r1,
                                       uint32_t& r2, uint32_t& r3, uint32_t addr) {
    asm volatile("ldmatrix.sync.aligned.m8n8.x4.shared.b16 {%0,%1,%2,%3}, [%4];"
                 : "=r"(r0), "=r"(r1), "=r"(r2), "=r"(r3) : "r"(addr));
}

__device__ __forceinline__ void mma16816(float* c, const uint32_t* a, const uint32_t* b) {
    asm volatile(
        "mma.sync.aligned.m16n8k16.row.col.f32.f16.f16.f32 "
        "{%0,%1,%2,%3}, {%4,%5,%6,%7}, {%8,%9}, {%0,%1,%2,%3};"
        : "+f"(c[0]), "+f"(c[1]), "+f"(c[2]), "+f"(c[3])
        : "r"(a[0]), "r"(a[1]), "r"(a[2]), "r"(a[3]), "r"(b[0]), "r"(b[1]));
}

// ---- packed fp32x2 FMA (Blackwell base ISA) ----
__device__ __forceinline__ u64t pack2(float x, float y) {
    u64t r;
    asm("mov.b64 %0, {%1, %2};" : "=l"(r) : "f"(x), "f"(y));
    return r;
}
__device__ __forceinline__ u64t bcast2(float v) {
    u64t r;
    asm("mov.b64 %0, {%1, %1};" : "=l"(r) : "f"(v));
    return r;
}
__device__ __forceinline__ void ffma2(u64t& c, u64t a, u64t b) {
    asm("fma.rn.f32x2 %0, %1, %2, %0;" : "+l"(c) : "l"(a), "l"(b));
}
__device__ __forceinline__ float lane0(u64t v) { float2 t; *(u64t*)&t = v; return t.x; }
__device__ __forceinline__ float lane1(u64t v) { float2 t; *(u64t*)&t = v; return t.y; }
#define ACC2F(i, j) (((i) & 1) ? lane1(acc2[(i) >> 1][j]) : lane0(acc2[(i) >> 1][j]))

#define F32X2_STEP(a4, b4) do {                                   \
    u64t a01 = pack2((a4).x, (a4).y), a23 = pack2((a4).z, (a4).w);\
    u64t bb0 = bcast2((b4).x), bb1 = bcast2((b4).y);              \
    u64t bb2 = bcast2((b4).z), bb3 = bcast2((b4).w);              \
    ffma2(acc2[0][0], a01, bb0); ffma2(acc2[0][1], a01, bb1);     \
    ffma2(acc2[0][2], a01, bb2); ffma2(acc2[0][3], a01, bb3);     \
    ffma2(acc2[1][0], a23, bb0); ffma2(acc2[1][1], a23, bb1);     \
    ffma2(acc2[1][2], a23, bb2); ffma2(acc2[1][3], a23, bb3);     \
} while (0)

__device__ __forceinline__ void atomicMaxF(float* addr, float val) {
    int* ai = (int*)addr;
    int old = *ai;
    while (__int_as_float(old) < val) {
        int assumed = old;
        old = atomicCAS(ai, assumed, __float_as_int(val));
        if (old == assumed) break;
    }
}

__device__ __forceinline__ float fast_exp(float x) {
    float y = fmaxf(x * 1.4426950408889634f, -126.0f);
    float r = rintf(y);
    float f = y - r;
    float p = 1.5403530e-4f;
    p = fmaf(p, f, 1.3333558e-3f);
    p = fmaf(p, f, 9.6181291e-3f);
    p = fmaf(p, f, 5.5504109e-2f);
    p = fmaf(p, f, 2.4022651e-1f);
    p = fmaf(p, f, 6.9314718e-1f);
    p = fmaf(p, f, 1.0f);
    int e = (int)r;
    float s = __int_as_float((e + 127) << 23);
    return p * s;
}

#define NORMALIZER 0.35355339059327373f   // 64^-0.25
#define RATIO      0.061313934f           // 266^-0.5
#define EPSF       1e-4f

// -------------------- init --------------------
__global__ void k_init() {
    int i = blockIdx.x * 256 + threadIdx.x;
    if (i < BHh * Mm * DHd) g_ctx[i]  = 0.0f;
    if (i < BHh * Mm)       g_ksum[i] = 0.0f;
    if (i < BHh)            g_kmax[i] = -3.0e38f;
}

// -------------------- fp32 -> fp16 convert --------------------
__global__ __launch_bounds__(256) void k_half(const float* __restrict__ src,
                                              __half* __restrict__ dst, int nrows) {
    int i = blockIdx.x * 256 + threadIdx.x;
    if (i >= nrows * 128) return;
    int r = i >> 7;
    int c = (i & 127) << 2;
    float4 v = *(const float4*)(src + (size_t)r * 512 + c);
    size_t rb = (size_t)r * K2 + c;
    *(__half2*)(dst + rb)     = __floats2half2_rn(v.x, v.y);
    *(__half2*)(dst + rb + 2) = __floats2half2_rn(v.z, v.w);
}

// -------------------- proj -> fp16 [320][64] zero-padded --------------------
__global__ __launch_bounds__(256) void k_projh(const float* __restrict__ proj) {
    int i = blockIdx.x * 256 + threadIdx.x;
    if (i >= 320 * 64) return;
    int m = i >> 6, c = i & 63;
    float v = (m < Mm) ? proj[m * 64 + c] : 0.f;
    g_projh[i] = __float2half(v);
}

// -------------------- mma.sync GEMM: C[16384,512] = A2 @ B2^T (fp16) --------
#define ASTR 40
#define TILE_B (128 * ASTR)
#define GEMM_DSMEM (6 * TILE_B * 2)

__global__ __launch_bounds__(256) void k_gemm(const __half* __restrict__ A,
                                              const __half* __restrict__ Bw,
                                              float* __restrict__ C,
                                              const float* __restrict__ xres,
                                              const float* __restrict__ bo,
                                              int finalmode) {
    extern __shared__ __half dyn[];
    int tid = threadIdx.x, lane = tid & 31, w = tid >> 5;
    int m0 = (w & 3) * 32, n0 = (w >> 2) * 64;
    int r0 = blockIdx.x * 128, e0 = blockIdx.y * 128;
    uint32_t sAu = smem_to_u32(dyn);
    uint32_t sBu = sAu + 3u * (TILE_B * 2);

    float acc[2][8][4];
#pragma unroll
    for (int i = 0; i < 2; i++)
#pragma unroll
        for (int j = 0; j < 8; j++)
#pragma unroll
            for (int l = 0; l < 4; l++) acc[i][j][l] = 0.f;

    int lrow = tid >> 1;
    int lcol = (tid & 1) << 4;
    const __half* Arow = A + (size_t)(r0 + lrow) * K2 + lcol;
    const __half* Brow = Bw + (size_t)(e0 + lrow) * K2 + lcol;
    uint32_t sAdst = sAu + (uint32_t)(lrow * ASTR + lcol) * 2;
    uint32_t sBdst = sBu + (uint32_t)(lrow * ASTR + lcol) * 2;

#define LOAD_TILE(buf, t) do {                                         \
    uint32_t _o = (uint32_t)(buf) * (TILE_B * 2);                      \
    const __half* _a = Arow + (t) * 32;                                \
    const __half* _b = Brow + (t) * 32;                                \
    CP_ASYNC16(sAdst + _o,      _a);                                   \
    CP_ASYNC16(sAdst + _o + 16, _a + 8);                               \
    CP_ASYNC16(sBdst + _o,      _b);                                   \
    CP_ASYNC16(sBdst + _o + 16, _b + 8);                               \
} while (0)

    LOAD_TILE(0, 0);
    CP_COMMIT();
    LOAD_TILE(1, 1);
    CP_COMMIT();

    const int NT = K2 / 32;   // 16
    int buf = 0;
#pragma unroll 1
    for (int t = 0; t < NT; ++t) {
        if (t + 1 < NT) CP_WAIT1(); else CP_WAIT0();
        __syncthreads();
        if (t + 2 < NT) {
            int nb = buf + 2; if (nb >= 3) nb -= 3;
            LOAD_TILE(nb, t + 2);
            CP_COMMIT();
        }
        uint32_t ab = sAu + (uint32_t)buf * (TILE_B * 2);
        uint32_t bb = sBu + (uint32_t)buf * (TILE_B * 2);
#pragma unroll
        for (int ks = 0; ks < 32; ks += 16) {
            uint32_t a[2][4];
#pragma unroll
            for (int mt = 0; mt < 2; mt++) {
                uint32_t addr = ab +
                    (uint32_t)((m0 + mt * 16 + (lane & 15)) * ASTR + ks + ((lane >> 4) << 3)) * 2;
                ldm_x4(a[mt][0], a[mt][1], a[mt][2], a[mt][3], addr);
            }
            uint32_t b[8][2];
#pragma unroll
            for (int p = 0; p < 4; p++) {
                int nA = n0 + p * 16;
                uint32_t addr = bb +
                    (uint32_t)((nA + (lane & 7) + ((lane >> 4) << 3)) * ASTR + ks + (lane & 8)) * 2;
                ldm_x4(b[2 * p][0], b[2 * p][1], b[2 * p + 1][0], b[2 * p + 1][1], addr);
            }
#pragma unroll
            for (int mt = 0; mt < 2; mt++)
#pragma unroll
                for (int nt = 0; nt < 8; nt++)
                    mma16816(acc[mt][nt], a[mt], b[nt]);
        }
        if (++buf == 3) buf = 0;
    }

    int gid = lane >> 2, tig = lane & 3;
#pragma unroll
    for (int mt = 0; mt < 2; mt++) {
#pragma unroll
        for (int nt = 0; nt < 8; nt++) {
            int r = r0 + m0 + mt * 16 + gid;
            int e = e0 + n0 + nt * 8 + tig * 2;
            float2 v01 = make_float2(acc[mt][nt][0], acc[mt][nt][1]);
            float2 v23 = make_float2(acc[mt][nt][2], acc[mt][nt][3]);
            if (!finalmode) {
                int b = r >> 12, n = r & 4095;
                int h = e >> 6, dh = e & 63;
                float* d0 = C + (((size_t)((b << 3) + h) * Nn + n) * DHd + dh);
                *(float2*)d0 = v01;
                *(float2*)(d0 + 8 * DHd) = v23;
            } else {
                size_t b0 = (size_t)r * Dd + e;
                float2 x0 = *(const float2*)(xres + b0);
                float2 x1 = *(const float2*)(xres + b0 + 8 * Dd);
                float2 bv = *(const float2*)(bo + e);
                *(float2*)(C + b0) = make_float2(x0.x + bv.x + v01.x, x0.y + bv.y + v01.y);
                *(float2*)(C + b0 + 8 * Dd) = make_float2(x1.x + bv.x + v23.x, x1.y + bv.y + v23.y);
            }
        }
    }
}

// -------------------- phi_k: td = (k*nrm)@proj^T -> g_kp, diag, per-head max -------
__global__ __launch_bounds__(256) void k_phi_k(const float* __restrict__ proj) {
    __shared__ float Ks[64][68];
    __shared__ float Ps[64][68];
    __shared__ float red[256];
    int tid = threadIdx.x;
    int n0 = blockIdx.x * 64;
    int m0 = blockIdx.y * 64;
    int bh = blockIdx.z;

#pragma unroll
    for (int i = 0; i < 4; i++) {
        int s = tid + i * 256;
        int row = s >> 4;
        int kc = (s & 15) << 2;
        float4 a = *(const float4*)(g_k + ((size_t)bh * Nn + n0 + row) * DHd + kc);
        Ks[kc + 0][row] = a.x * NORMALIZER; Ks[kc + 1][row] = a.y * NORMALIZER;
        Ks[kc + 2][row] = a.z * NORMALIZER; Ks[kc + 3][row] = a.w * NORMALIZER;
        float4 p = make_float4(0.f, 0.f, 0.f, 0.f);
        if (m0 + row < Mm) p = *(const float4*)(proj + (size_t)(m0 + row) * DHd + kc);
        Ps[kc + 0][row] = p.x; Ps[kc + 1][row] = p.y;
        Ps[kc + 2][row] = p.z; Ps[kc + 3][row] = p.w;
    }
    __syncthreads();

    if (m0 == 0 && tid < 64) {
        float ss = 0.f;
#pragma unroll
        for (int d = 0; d < 64; d++) { float q = Ks[d][tid]; ss += q * q; }
        g_diag[(size_t)bh * Nn + n0 + tid] = 0.5f * ss;
    }

    u64t acc2[2][4];
#pragma unroll
    for (int i = 0; i < 2; i++)
#pragma unroll
        for (int j = 0; j < 4; j++) acc2[i][j] = 0ull;
    int ty = tid >> 4, tx = tid & 15;
#pragma unroll
    for (int kk = 0; kk < 64; kk++) {
        float4 a = *(const float4*)&Ks[kk][ty * 4];
        float4 b = *(const float4*)&Ps[kk][tx * 4];
        F32X2_STEP(a, b);
    }

    float mymax = -3.0e38f;
#pragma unroll
    for (int i = 0; i < 4; i++) {
        int n = n0 + ty * 4 + i;
#pragma unroll
        for (int j = 0; j < 4; j++) {
            int m = m0 + tx * 4 + j;
            if (m < Mm) {
                float av = ACC2F(i, j);
                g_kp[((size_t)bh * Nn + n) * Mm + m] = av;
                mymax = fmaxf(mymax, av);
            }
        }
    }
    red[tid] = mymax;
    __syncthreads();
    for (int off = 128; off > 0; off >>= 1) {
        if (tid < off) red[tid] = fmaxf(red[tid], red[tid + off]);
        __syncthreads();
    }
    if (tid == 0) atomicMaxF(&g_kmax[bh], red[0]);
}

// -------------------- ctx fused: exp(td) in-fill (MLP-batched) + MMA + ksum --------
__global__ __launch_bounds__(256) void k_ctx() {
    __shared__ float Ksm[64][68];
    __shared__ float Vs[64][68];
    __shared__ float diag_s[512];
    __shared__ float rsum[256];
    int tid = threadIdx.x;
    int m0 = blockIdx.x * 64;
    int nc = blockIdx.y * 512;
    int bh = blockIdx.z;
    float mx = g_kmax[bh];

    diag_s[tid]       = g_diag[(size_t)bh * Nn + nc + tid];
    diag_s[tid + 256] = g_diag[(size_t)bh * Nn + nc + 256 + tid];

    u64t acc2[2][4];
#pragma unroll
    for (int i = 0; i < 2; i++)
#pragma unroll
        for (int j = 0; j < 4; j++) acc2[i][j] = 0ull;
    int ty = tid >> 4, tx = tid & 15;

    int mmc = m0 + (tid & 63);
    bool mok = mmc < Mm;
    int nbase = tid >> 6;
    float cs = 0.f;
    __syncthreads();

    for (int nt = 0; nt < 8; nt++) {
        int n0 = nc + nt * 64;
        float tdv[16];
        const float* kpb = g_kp + ((size_t)bh * Nn + n0 + nbase) * Mm + mmc;
#pragma unroll
        for (int i = 0; i < 16; i++)
            tdv[i] = mok ? kpb[(size_t)(i * 4) * Mm] : 0.f;
#pragma unroll
        for (int i = 0; i < 16; i++) {
            int n = i * 4 + nbase;
            float v = 0.f;
            if (mok) {
                v = RATIO * (fast_exp(tdv[i] - diag_s[nt * 64 + n] - mx) + EPSF);
                cs += v;
            }
            Ksm[n][tid & 63] = v;
        }
#pragma unroll
        for (int i = 0; i < 4; i++) {
            int s = tid + i * 256;
            int n = s >> 4, c = (s & 15) << 2;
            float4 v = *(const float4*)(g_v + ((size_t)bh * Nn + n0 + n) * DHd + c);
            Vs[n][c] = v.x; Vs[n][c + 1] = v.y; Vs[n][c + 2] = v.z; Vs[n][c + 3] = v.w;
        }
        __syncthreads();
#pragma unroll
        for (int kk = 0; kk < 64; kk++) {
            float4 a = *(const float4*)&Ksm[kk][ty * 4];
            float4 b = *(const float4*)&Vs[kk][tx * 4];
            F32X2_STEP(a, b);
        }
        __syncthreads();
    }
#pragma unroll
    for (int i = 0; i < 4; i++) {
        int m = m0 + ty * 4 + i;
        if (m < Mm)
#pragma unroll
            for (int j = 0; j < 4; j++)
                atomicAdd(&g_ctx[((size_t)bh * Mm + m) * DHd + tx * 4 + j], ACC2F(i, j));
    }
    rsum[tid] = cs;
    __syncthreads();
    if (tid < 64) {
        int m = m0 + tid;
        if (m < Mm) {
            float t = rsum[tid] + rsum[tid + 64] + rsum[tid + 128] + rsum[tid + 192];
            atomicAdd(&g_ksum[bh * Mm + m], t);
        }
    }
}

// ------------- phi_q + out FUSED, fp16 HMMA both phases; qp never touches HBM -------
#define QO_SMEM_BYTES 92736
__global__ __launch_bounds__(256) void k_phi_q_out() {
    extern __shared__ char smraw[];
    __half* Qh   = (__half*)smraw;                       // [64][PSTR]
    __half* Ph   = (__half*)(smraw + 9216);              // [64][PSTR]
    __half* qph  = (__half*)(smraw + 18432);             // [64][QSTR]
    __half* Ch   = (__half*)(smraw + 54272);             // [64][QSTR]  (dh rows, m cols)
    float* ksum_s = (float*)(smraw + 90112);             // [MQ]
    float* diag_s = (float*)(smraw + 91200);             // [64]
    float* dinv_s = (float*)(smraw + 91456);             // [64]
    float* rmax   = (float*)(smraw + 91712);             // [64][2]
    float* rsum   = (float*)(smraw + 92224);             // [64][2]
    uint32_t QhU = smem_to_u32(Qh), PhU = smem_to_u32(Ph);
    uint32_t qphU = smem_to_u32(qph), ChU = smem_to_u32(Ch);

    int tid = threadIdx.x, lane = tid & 31, w = tid >> 5;
    int wy = w & 3, wx = w >> 2;       // n-subtile (16 rows), m/dh-subtile (32 cols)
    int gid = lane >> 2, tig = lane & 3;
    int n0 = blockIdx.x * 64;
    int bh = blockIdx.y;

    // ---- fill Qh (q*nrm fp16) + ksum_s ----
    for (int i = tid; i < MQ; i += 256) ksum_s[i] = (i < Mm) ? g_ksum[bh * Mm + i] : 0.f;
#pragma unroll
    for (int i = 0; i < 2; i++) {
        int s = tid + i * 256;          // 512 chunks of 8 cols
        int row = s >> 3, c8 = (s & 7) * 8;
        const float* src = g_q + ((size_t)bh * Nn + n0 + row) * DHd + c8;
        float4 a = *(const float4*)src;
        float4 b = *(const float4*)(src + 4);
        __half* d = Qh + row * PSTR + c8;
        *(__half2*)(d + 0) = __floats2half2_rn(a.x * NORMALIZER, a.y * NORMALIZER);
        *(__half2*)(d + 2) = __floats2half2_rn(a.z * NORMALIZER, a.w * NORMALIZER);
        *(__half2*)(d + 4) = __floats2half2_rn(b.x * NORMALIZER, b.y * NORMALIZER);
        *(__half2*)(d + 6) = __floats2half2_rn(b.z * NORMALIZER, b.w * NORMALIZER);
    }
    __syncthreads();
    if (tid < 64) {     // diag from the SAME fp16-rounded q (consistent with td)
        float ss = 0.f;
        const __half2* qr = (const __half2*)(Qh + tid * PSTR);
#pragma unroll
        for (int d = 0; d < 32; d++) {
            float2 t = __half22float2(qr[d]);
            ss += t.x * t.x + t.y * t.y;
        }
        diag_s[tid] = 0.5f * ss;
    }

    // ---- phase 1: td = q @ proj^T via HMMA, kept in registers ----
    float td[5][4][4];
#pragma unroll
    for (int mt = 0; mt < 5; mt++)
#pragma unroll
        for (int bt = 0; bt < 4; bt++)
#pragma unroll
            for (int c = 0; c < 4; c++) td[mt][bt][c] = 0.f;

#pragma unroll 1
    for (int mt = 0; mt < 5; mt++) {
        // fill Ph from g_projh rows mt*64..+63 (fp16, zero-padded rows)
#pragma unroll
        for (int i = 0; i < 2; i++) {
            int s = tid + i * 256;
            int row = s >> 3, c8 = (s & 7) * 8;
            *(uint4*)(Ph + row * PSTR + c8) =
                *(const uint4*)(g_projh + (size_t)(mt * 64 + row) * 64 + c8);
        }
        __syncthreads();
#pragma unroll
        for (int k = 0; k < 4; k++) {
            uint32_t a[4];
            uint32_t aaddr = QhU +
                (uint32_t)((wy * 16 + (lane & 15)) * PSTR + k * 16 + ((lane >> 4) << 3)) * 2;
            ldm_x4(a[0], a[1], a[2], a[3], aaddr);
            uint32_t b[4][2];
#pragma unroll
            for (int p = 0; p < 2; p++) {
                uint32_t baddr = PhU +
                    (uint32_t)((wx * 32 + p * 16 + (lane & 7) + ((lane >> 4) << 3)) * PSTR +
                               k * 16 + (lane & 8)) * 2;
                ldm_x4(b[2 * p][0], b[2 * p][1], b[2 * p + 1][0], b[2 * p + 1][1], baddr);
            }
#pragma unroll
            for (int bt = 0; bt < 4; bt++)
                mma16816(td[mt][bt], a, b[bt]);
        }
        __syncthreads();
    }

    // ---- phase 2: rowmax -> exp -> qph fp16, dinv ----
    int r1 = wy * 16 + gid, r2 = r1 + 8;
    float mx1 = -3.0e38f, mx2 = -3.0e38f;
#pragma unroll
    for (int mt = 0; mt < 5; mt++)
#pragma unroll
        for (int bt = 0; bt < 4; bt++) {
            int mb = mt * 64 + wx * 32 + bt * 8 + tig * 2;
            if (mb < Mm)     { mx1 = fmaxf(mx1, td[mt][bt][0]); mx2 = fmaxf(mx2, td[mt][bt][2]); }
            if (mb + 1 < Mm) { mx1 = fmaxf(mx1, td[mt][bt][1]); mx2 = fmaxf(mx2, td[mt][bt][3]); }
        }
    mx1 = fmaxf(mx1, __shfl_xor_sync(0xffffffffu, mx1, 1));
    mx1 = fmaxf(mx1, __shfl_xor_sync(0xffffffffu, mx1, 2));
    mx2 = fmaxf(mx2, __shfl_xor_sync(0xffffffffu, mx2, 1));
    mx2 = fmaxf(mx2, __shfl_xor_sync(0xffffffffu, mx2, 2));
    if (tig == 0) { rmax[r1 * 2 + wx] = mx1; rmax[r2 * 2 + wx] = mx2; }
    __syncthreads();
    mx1 = fmaxf(rmax[r1 * 2], rmax[r1 * 2 + 1]);
    mx2 = fmaxf(rmax[r2 * 2], rmax[r2 * 2 + 1]);
    float dg1 = diag_s[r1], dg2 = diag_s[r2];
    float s1 = 0.f, s2 = 0.f;
#pragma unroll
    for (int mt = 0; mt < 5; mt++)
#pragma unroll
        for (int bt = 0; bt < 4; bt++) {
            int mb = mt * 64 + wx * 32 + bt * 8 + tig * 2;
            float v0 = 0.f, v1 = 0.f, v2 = 0.f, v3 = 0.f;
            if (mb < Mm) {
                v0 = RATIO * (fast_exp(td[mt][bt][0] - dg1 - mx1) + EPSF);
                v2 = RATIO * (fast_exp(td[mt][bt][2] - dg2 - mx2) + EPSF);
                s1 += v0 * ksum_s[mb];
                s2 += v2 * ksum_s[mb];
            }
            if (mb + 1 < Mm) {
                v1 = RATIO * (fast_exp(td[mt][bt][1] - dg1 - mx1) + EPSF);
                v3 = RATIO * (fast_exp(td[mt][bt][3] - dg2 - mx2) + EPSF);
                s1 += v1 * ksum_s[mb + 1];
                s2 += v3 * ksum_s[mb + 1];
            }
            if (mb < MQ) {
                *(__half2*)(qph + r1 * QSTR + mb) = __floats2half2_rn(v0, v1);
                *(__half2*)(qph + r2 * QSTR + mb) = __floats2half2_rn(v2, v3);
            }
        }
    s1 += __shfl_xor_sync(0xffffffffu, s1, 1);
    s1 += __shfl_xor_sync(0xffffffffu, s1, 2);
    s2 += __shfl_xor_sync(0xffffffffu, s2, 1);
    s2 += __shfl_xor_sync(0xffffffffu, s2, 2);
    if (tig == 0) { rsum[r1 * 2 + wx] = s1; rsum[r2 * 2 + wx] = s2; }
    __syncthreads();
    if (tid < 64) dinv_s[tid] = 1.0f / (rsum[tid * 2] + rsum[tid * 2 + 1]);

    // ---- Ch fill: ctx transposed to [dh][m] fp16, zero-padded m ----
#pragma unroll
    for (int i = 0; i < 68; i++) {
        int s = tid + i * 256;          // 64*272 = 17408 = 68*256
        int dh = s & 63, m = s >> 6;
        float cv = (m < Mm) ? g_ctx[((size_t)bh * Mm + m) * DHd + dh] : 0.f;
        Ch[dh * QSTR + m] = __float2half(cv);
    }
    __syncthreads();

    // ---- phase 3: out = qp @ ctx via HMMA, x dinv, -> attn2 fp16 ----
    float oacc[4][4];
#pragma unroll
    for (int bt = 0; bt < 4; bt++)
#pragma unroll
        for (int c = 0; c < 4; c++) oacc[bt][c] = 0.f;

#pragma unroll 1
    for (int k = 0; k < 17; k++) {
        uint32_t a[4];
        uint32_t aaddr = qphU +
            (uint32_t)((wy * 16 + (lane & 15)) * QSTR + k * 16 + ((lane >> 4) << 3)) * 2;
        ldm_x4(a[0], a[1], a[2], a[3], aaddr);
        uint32_t b[4][2];
#pragma unroll
        for (int p = 0; p < 2; p++) {
            uint32_t baddr = ChU +
                (uint32_t)((wx * 32 + p * 16 + (lane & 7) + ((lane >> 4) << 3)) * QSTR +
                           k * 16 + (lane & 8)) * 2;
            ldm_x4(b[2 * p][0], b[2 * p][1], b[2 * p + 1][0], b[2 * p + 1][1], baddr);
        }
#pragma unroll
        for (int bt = 0; bt < 4; bt++)
            mma16816(oacc[bt], a, b[bt]);
    }

    int b = bh >> 3, h = bh & 7;
    float dv1 = dinv_s[r1], dv2 = dinv_s[r2];
    size_t rb1 = (size_t)(b * Nn + n0 + r1) * K2 + h * 64;
    size_t rb2 = (size_t)(b * Nn + n0 + r2) * K2 + h * 64;
#pragma unroll
    for (int bt = 0; bt < 4; bt++) {
        int dh = wx * 32 + bt * 8 + tig * 2;
        *(__half2*)(g_attn2 + rb1 + dh) =
            __floats2half2_rn(oacc[bt][0] * dv1, oacc[bt][1] * dv1);
        *(__half2*)(g_attn2 + rb2 + dh) =
            __floats2half2_rn(oacc[bt][2] * dv2, oacc[bt][3] * dv2);
    }
}

// -------------------- launch --------------------
extern "C" void kernel_launch(void* const* d_in, const int* in_sizes, int n_in,
                              void* d_out, int out_size) {
    const float* x    = (const float*)d_in[0];
    const float* Wq   = (const float*)d_in[1];
    const float* Wk   = (const float*)d_in[2];
    const float* Wv   = (const float*)d_in[3];
    const float* Wo   = (const float*)d_in[4];
    const float* bo   = (const float*)d_in[5];
    const float* proj = (const float*)d_in[6];
    float* out = (float*)d_out;
    (void)in_sizes; (void)n_in; (void)out_size;

    cudaFuncSetAttribute(k_phi_q_out, cudaFuncAttributeMaxDynamicSharedMemorySize,
                         QO_SMEM_BYTES);
    cudaFuncSetAttribute(k_gemm, cudaFuncAttributeMaxDynamicSharedMemorySize, GEMM_DSMEM);

    __half *x2p, *wq2p, *wk2p, *wv2p, *wo2p, *attn2p;
    cudaGetSymbolAddress((void**)&x2p, g_x2);
    cudaGetSymbolAddress((void**)&wq2p, g_wq2);
    cudaGetSymbolAddress((void**)&wk2p, g_wk2);
    cudaGetSymbolAddress((void**)&wv2p, g_wv2);
    cudaGetSymbolAddress((void**)&wo2p, g_wo2);
    cudaGetSymbolAddress((void**)&attn2p, g_attn2);
    float *qp_, *kp_, *vp_;
    cudaGetSymbolAddress((void**)&qp_, g_q);
    cudaGetSymbolAddress((void**)&kp_, g_k);
    cudaGetSymbolAddress((void**)&vp_, g_v);

    k_init<<<(BHh * Mm * DHd + 255) / 256, 256>>>();
    k_half<<<(BNn * 128 + 255) / 256, 256>>>(x, x2p, BNn);
    k_half<<<(Dd * 128 + 255) / 256, 256>>>(Wq, wq2p, Dd);
    k_half<<<(Dd * 128 + 255) / 256, 256>>>(Wk, wk2p, Dd);
    k_half<<<(Dd * 128 + 255) / 256, 256>>>(Wv, wv2p, Dd);

    dim3 gG(BNn / 128, Dd / 128);
    k_gemm<<<gG, 256, GEMM_DSMEM>>>(x2p, wq2p, qp_, nullptr, nullptr, 0);
    k_gemm<<<gG, 256, GEMM_DSMEM>>>(x2p, wk2p, kp_, nullptr, nullptr, 0);
    k_gemm<<<gG, 256, GEMM_DSMEM>>>(x2p, wv2p, vp_, nullptr, nullptr, 0);

    k_half<<<(Dd * 128 + 255) / 256, 256>>>(Wo, wo2p, Dd);
    k_projh<<<(320 * 64 + 255) / 256, 256>>>(proj);

    k_phi_k<<<dim3(Nn / 64, 5, BHh), 256>>>(proj);
    k_ctx<<<dim3(5, Nn / 512, BHh), 256>>>();
    k_phi_q_out<<<dim3(Nn / 64, BHh), 256, QO_SMEM_BYTES>>>();

    k_gemm<<<gG, 256, GEMM_DSMEM>>>(attn2p, wo2p, out, x, bo, 1);
}

// round 17
// speedup vs baseline: 2.6867x; 1.2667x over previous
#include <cuda_runtime.h>
#include <cuda_fp16.h>
#include <stdint.h>
#include <math.h>

#define Bb   4
#define Nn   4096
#define Dd   512
#define Hh   8
#define DHd  64
#define Mm   266
#define BHh  32          // B*H
#define BNn  16384       // B*N
#define K2   512         // plain fp16 GEMM K
#define MQ   272         // qp/ctx k extent (m padded to x16)
#define QSTR 280         // fp16 row stride for qph/Ch
#define PSTR 72          // fp16 row stride for Qh/Ph/Kh

// -------------------- scratch (static device memory; no allocs) --------------------
__device__ float g_q  [(size_t)BHh * Nn * DHd];
__device__ float g_k  [(size_t)BHh * Nn * DHd];
__device__ float g_v  [(size_t)BHh * Nn * DHd];
__device__ float g_kp [(size_t)BHh * Nn * Mm];   // holds td_k; exp applied inside k_ctx
__device__ float g_ctx [(size_t)BHh * Mm * DHd];
__device__ float g_ksum[(size_t)BHh * Mm];
__device__ float g_kmax[BHh];
__device__ float g_diag[(size_t)BHh * Nn];

__device__ __half g_x2   [(size_t)BNn * K2];
__device__ __half g_attn2[(size_t)BNn * K2];
__device__ __half g_wq2  [(size_t)Dd * K2];
__device__ __half g_wk2  [(size_t)Dd * K2];
__device__ __half g_wv2  [(size_t)Dd * K2];
__device__ __half g_wo2  [(size_t)Dd * K2];
__device__ __half g_projh[320 * 64];

// -------------------- helpers --------------------
typedef unsigned long long u64t;

__device__ __forceinline__ uint32_t smem_to_u32(const void* p) {
    uint32_t a;
    asm("{ .reg .u64 t; cvta.to.shared.u64 t, %1; cvt.u32.u64 %0, t; }"
        : "=r"(a) : "l"(p));
    return a;
}

#define CP_ASYNC16(dst, src) \
    asm volatile("cp.async.cg.shared.global [%0], [%1], 16;" \
                 :: "r"(dst), "l"(src) : "memory")
#define CP_COMMIT()  asm volatile("cp.async.commit_group;" ::: "memory")
#define CP_WAIT1()   asm volatile("cp.async.wait_group 1;" ::: "memory")
#define CP_WAIT0()   asm volatile("cp.async.wait_group 0;" ::: "memory")

__device__ __forceinline__ void ldm_x4(uint32_t& r0, uint32_t& r1,
                                       uint32_t& r2, uint32_t& r3, uint32_t addr) {
    asm volatile("ldmatrix.sync.aligned.m8n8.x4.shared.b16 {%0,%1,%2,%3}, [%4];"
                 : "=r"(r0), "=r"(r1), "=r"(r2), "=r"(r3) : "r"(addr));
}

__device__ __forceinline__ void mma16816(float* c, const uint32_t* a, const uint32_t* b) {
    asm volatile(
        "mma.sync.aligned.m16n8k16.row.col.f32.f16.f16.f32 "
        "{%0,%1,%2,%3}, {%4,%5,%6,%7}, {%8,%9}, {%0,%1,%2,%3};"
        : "+f"(c[0]), "+f"(c[1]), "+f"(c[2]), "+f"(c[3])
        : "r"(a[0]), "r"(a[1]), "r"(a[2]), "r"(a[3]), "r"(b[0]), "r"(b[1]));
}

// ---- packed fp32x2 FMA (Blackwell base ISA) ----
__device__ __forceinline__ u64t pack2(float x, float y) {
    u64t r;
    asm("mov.b64 %0, {%1, %2};" : "=l"(r) : "f"(x), "f"(y));
    return r;
}
__device__ __forceinline__ u64t bcast2(float v) {
    u64t r;
    asm("mov.b64 %0, {%1, %1};" : "=l"(r) : "f"(v));
    return r;
}
__device__ __forceinline__ void ffma2(u64t& c, u64t a, u64t b) {
    asm("fma.rn.f32x2 %0, %1, %2, %0;" : "+l"(c) : "l"(a), "l"(b));
}
__device__ __forceinline__ float lane0(u64t v) { float2 t; *(u64t*)&t = v; return t.x; }
__device__ __forceinline__ float lane1(u64t v) { float2 t; *(u64t*)&t = v; return t.y; }
#define ACC2F(i, j) (((i) & 1) ? lane1(acc2[(i) >> 1][j]) : lane0(acc2[(i) >> 1][j]))

#define F32X2_STEP(a4, b4) do {                                   \
    u64t a01 = pack2((a4).x, (a4).y), a23 = pack2((a4).z, (a4).w);\
    u64t bb0 = bcast2((b4).x), bb1 = bcast2((b4).y);              \
    u64t bb2 = bcast2((b4).z), bb3 = bcast2((b4).w);              \
    ffma2(acc2[0][0], a01, bb0); ffma2(acc2[0][1], a01, bb1);     \
    ffma2(acc2[0][2], a01, bb2); ffma2(acc2[0][3], a01, bb3);     \
    ffma2(acc2[1][0], a23, bb0); ffma2(acc2[1][1], a23, bb1);     \
    ffma2(acc2[1][2], a23, bb2); ffma2(acc2[1][3], a23, bb3);     \
} while (0)

__device__ __forceinline__ void atomicMaxF(float* addr, float val) {
    int* ai = (int*)addr;
    int old = *ai;
    while (__int_as_float(old) < val) {
        int assumed = old;
        old = atomicCAS(ai, assumed, __float_as_int(val));
        if (old == assumed) break;
    }
}

__device__ __forceinline__ float fast_exp(float x) {
    float y = fmaxf(x * 1.4426950408889634f, -126.0f);
    float r = rintf(y);
    float f = y - r;
    float p = 1.5403530e-4f;
    p = fmaf(p, f, 1.3333558e-3f);
    p = fmaf(p, f, 9.6181291e-3f);
    p = fmaf(p, f, 5.5504109e-2f);
    p = fmaf(p, f, 2.4022651e-1f);
    p = fmaf(p, f, 6.9314718e-1f);
    p = fmaf(p, f, 1.0f);
    int e = (int)r;
    float s = __int_as_float((e + 127) << 23);
    return p * s;
}

#define NORMALIZER 0.35355339059327373f   // 64^-0.25
#define RATIO      0.061313934f           // 266^-0.5
#define EPSF       1e-4f

// -------------------- init --------------------
__global__ void k_init() {
    int i = blockIdx.x * 256 + threadIdx.x;
    if (i < BHh * Mm * DHd) g_ctx[i]  = 0.0f;
    if (i < BHh * Mm)       g_ksum[i] = 0.0f;
    if (i < BHh)            g_kmax[i] = -3.0e38f;
}

// -------------------- fp32 -> fp16 convert --------------------
__global__ __launch_bounds__(256) void k_half(const float* __restrict__ src,
                                              __half* __restrict__ dst, int nrows) {
    int i = blockIdx.x * 256 + threadIdx.x;
    if (i >= nrows * 128) return;
    int r = i >> 7;
    int c = (i & 127) << 2;
    float4 v = *(const float4*)(src + (size_t)r * 512 + c);
    size_t rb = (size_t)r * K2 + c;
    *(__half2*)(dst + rb)     = __floats2half2_rn(v.x, v.y);
    *(__half2*)(dst + rb + 2) = __floats2half2_rn(v.z, v.w);
}

// -------------------- proj -> fp16 [320][64] zero-padded --------------------
__global__ __launch_bounds__(256) void k_projh(const float* __restrict__ proj) {
    int i = blockIdx.x * 256 + threadIdx.x;
    if (i >= 320 * 64) return;
    int m = i >> 6, c = i & 63;
    float v = (m < Mm) ? proj[m * 64 + c] : 0.f;
    g_projh[i] = __float2half(v);
}

// -------------------- mma.sync GEMM: C[16384,512] = A2 @ B2^T (fp16) --------
#define ASTR 40
#define TILE_B (128 * ASTR)
#define GEMM_DSMEM (6 * TILE_B * 2)

__global__ __launch_bounds__(256) void k_gemm(const __half* __restrict__ A,
                                              const __half* __restrict__ Bw,
                                              float* __restrict__ C,
                                              const float* __restrict__ xres,
                                              const float* __restrict__ bo,
                                              int finalmode) {
    extern __shared__ __half dyn[];
    int tid = threadIdx.x, lane = tid & 31, w = tid >> 5;
    int m0 = (w & 3) * 32, n0 = (w >> 2) * 64;
    int r0 = blockIdx.x * 128, e0 = blockIdx.y * 128;
    uint32_t sAu = smem_to_u32(dyn);
    uint32_t sBu = sAu + 3u * (TILE_B * 2);

    float acc[2][8][4];
#pragma unroll
    for (int i = 0; i < 2; i++)
#pragma unroll
        for (int j = 0; j < 8; j++)
#pragma unroll
            for (int l = 0; l < 4; l++) acc[i][j][l] = 0.f;

    int lrow = tid >> 1;
    int lcol = (tid & 1) << 4;
    const __half* Arow = A + (size_t)(r0 + lrow) * K2 + lcol;
    const __half* Brow = Bw + (size_t)(e0 + lrow) * K2 + lcol;
    uint32_t sAdst = sAu + (uint32_t)(lrow * ASTR + lcol) * 2;
    uint32_t sBdst = sBu + (uint32_t)(lrow * ASTR + lcol) * 2;

#define LOAD_TILE(buf, t) do {                                         \
    uint32_t _o = (uint32_t)(buf) * (TILE_B * 2);                      \
    const __half* _a = Arow + (t) * 32;                                \
    const __half* _b = Brow + (t) * 32;                                \
    CP_ASYNC16(sAdst + _o,      _a);                                   \
    CP_ASYNC16(sAdst + _o + 16, _a + 8);                               \
    CP_ASYNC16(sBdst + _o,      _b);                                   \
    CP_ASYNC16(sBdst + _o + 16, _b + 8);                               \
} while (0)

    LOAD_TILE(0, 0);
    CP_COMMIT();
    LOAD_TILE(1, 1);
    CP_COMMIT();

    const int NT = K2 / 32;   // 16
    int buf = 0;
#pragma unroll 1
    for (int t = 0; t < NT; ++t) {
        if (t + 1 < NT) CP_WAIT1(); else CP_WAIT0();
        __syncthreads();
        if (t + 2 < NT) {
            int nb = buf + 2; if (nb >= 3) nb -= 3;
            LOAD_TILE(nb, t + 2);
            CP_COMMIT();
        }
        uint32_t ab = sAu + (uint32_t)buf * (TILE_B * 2);
        uint32_t bb = sBu + (uint32_t)buf * (TILE_B * 2);
#pragma unroll
        for (int ks = 0; ks < 32; ks += 16) {
            uint32_t a[2][4];
#pragma unroll
            for (int mt = 0; mt < 2; mt++) {
                uint32_t addr = ab +
                    (uint32_t)((m0 + mt * 16 + (lane & 15)) * ASTR + ks + ((lane >> 4) << 3)) * 2;
                ldm_x4(a[mt][0], a[mt][1], a[mt][2], a[mt][3], addr);
            }
            uint32_t b[8][2];
#pragma unroll
            for (int p = 0; p < 4; p++) {
                int nA = n0 + p * 16;
                uint32_t addr = bb +
                    (uint32_t)((nA + (lane & 7) + ((lane >> 4) << 3)) * ASTR + ks + (lane & 8)) * 2;
                ldm_x4(b[2 * p][0], b[2 * p][1], b[2 * p + 1][0], b[2 * p + 1][1], addr);
            }
#pragma unroll
            for (int mt = 0; mt < 2; mt++)
#pragma unroll
                for (int nt = 0; nt < 8; nt++)
                    mma16816(acc[mt][nt], a[mt], b[nt]);
        }
        if (++buf == 3) buf = 0;
    }

    int gid = lane >> 2, tig = lane & 3;
#pragma unroll
    for (int mt = 0; mt < 2; mt++) {
#pragma unroll
        for (int nt = 0; nt < 8; nt++) {
            int r = r0 + m0 + mt * 16 + gid;
            int e = e0 + n0 + nt * 8 + tig * 2;
            float2 v01 = make_float2(acc[mt][nt][0], acc[mt][nt][1]);
            float2 v23 = make_float2(acc[mt][nt][2], acc[mt][nt][3]);
            if (!finalmode) {
                int b = r >> 12, n = r & 4095;
                int h = e >> 6, dh = e & 63;
                float* d0 = C + (((size_t)((b << 3) + h) * Nn + n) * DHd + dh);
                *(float2*)d0 = v01;
                *(float2*)(d0 + 8 * DHd) = v23;
            } else {
                size_t b0 = (size_t)r * Dd + e;
                float2 x0 = *(const float2*)(xres + b0);
                float2 x1 = *(const float2*)(xres + b0 + 8 * Dd);
                float2 bv = *(const float2*)(bo + e);
                *(float2*)(C + b0) = make_float2(x0.x + bv.x + v01.x, x0.y + bv.y + v01.y);
                *(float2*)(C + b0 + 8 * Dd) = make_float2(x1.x + bv.x + v23.x, x1.y + bv.y + v23.y);
            }
        }
    }
}

// ------------- phi_k via fp16 HMMA: td = k@proj^T -> g_kp fp32, diag, per-head max ----
__global__ __launch_bounds__(256) void k_phi_k() {
    __shared__ __half Kh[64 * PSTR];
    __shared__ __half Ph[64 * PSTR];
    __shared__ float red[256];
    uint32_t KhU = smem_to_u32(Kh), PhU = smem_to_u32(Ph);

    int tid = threadIdx.x, lane = tid & 31, w = tid >> 5;
    int wy = w & 3, wx = w >> 2;
    int gid = lane >> 2, tig = lane & 3;
    int n0 = blockIdx.x * 64;
    int bh = blockIdx.y;

    // fill Kh = k * NORMALIZER (fp16)
#pragma unroll
    for (int i = 0; i < 2; i++) {
        int s = tid + i * 256;
        int row = s >> 3, c8 = (s & 7) * 8;
        const float* src = g_k + ((size_t)bh * Nn + n0 + row) * DHd + c8;
        float4 a = *(const float4*)src;
        float4 b = *(const float4*)(src + 4);
        __half* d = Kh + row * PSTR + c8;
        *(__half2*)(d + 0) = __floats2half2_rn(a.x * NORMALIZER, a.y * NORMALIZER);
        *(__half2*)(d + 2) = __floats2half2_rn(a.z * NORMALIZER, a.w * NORMALIZER);
        *(__half2*)(d + 4) = __floats2half2_rn(b.x * NORMALIZER, b.y * NORMALIZER);
        *(__half2*)(d + 6) = __floats2half2_rn(b.z * NORMALIZER, b.w * NORMALIZER);
    }
    __syncthreads();
    if (tid < 64) {     // diag from the SAME fp16-rounded k (consistent with td)
        float ss = 0.f;
        const __half2* kr = (const __half2*)(Kh + tid * PSTR);
#pragma unroll
        for (int d = 0; d < 32; d++) {
            float2 t = __half22float2(kr[d]);
            ss += t.x * t.x + t.y * t.y;
        }
        g_diag[(size_t)bh * Nn + n0 + tid] = 0.5f * ss;
    }

    int r1 = wy * 16 + gid, r2 = r1 + 8;
    size_t kb1 = ((size_t)bh * Nn + n0 + r1) * Mm;
    size_t kb2 = ((size_t)bh * Nn + n0 + r2) * Mm;
    float mymax = -3.0e38f;

#pragma unroll 1
    for (int mt = 0; mt < 5; mt++) {
#pragma unroll
        for (int i = 0; i < 2; i++) {
            int s = tid + i * 256;
            int row = s >> 3, c8 = (s & 7) * 8;
            *(uint4*)(Ph + row * PSTR + c8) =
                *(const uint4*)(g_projh + (size_t)(mt * 64 + row) * 64 + c8);
        }
        __syncthreads();
        float td[4][4];
#pragma unroll
        for (int bt = 0; bt < 4; bt++)
#pragma unroll
            for (int c = 0; c < 4; c++) td[bt][c] = 0.f;
#pragma unroll
        for (int k = 0; k < 4; k++) {
            uint32_t a[4];
            uint32_t aaddr = KhU +
                (uint32_t)((wy * 16 + (lane & 15)) * PSTR + k * 16 + ((lane >> 4) << 3)) * 2;
            ldm_x4(a[0], a[1], a[2], a[3], aaddr);
            uint32_t b[4][2];
#pragma unroll
            for (int p = 0; p < 2; p++) {
                uint32_t baddr = PhU +
                    (uint32_t)((wx * 32 + p * 16 + (lane & 7) + ((lane >> 4) << 3)) * PSTR +
                               k * 16 + (lane & 8)) * 2;
                ldm_x4(b[2 * p][0], b[2 * p][1], b[2 * p + 1][0], b[2 * p + 1][1], baddr);
            }
#pragma unroll
            for (int bt = 0; bt < 4; bt++)
                mma16816(td[bt], a, b[bt]);
        }
        // store td (fp32) + track max; mb always even, mb<Mm => mb+1<Mm (Mm even)
#pragma unroll
        for (int bt = 0; bt < 4; bt++) {
            int mb = mt * 64 + wx * 32 + bt * 8 + tig * 2;
            if (mb < Mm) {
                *(float2*)(g_kp + kb1 + mb) = make_float2(td[bt][0], td[bt][1]);
                *(float2*)(g_kp + kb2 + mb) = make_float2(td[bt][2], td[bt][3]);
                mymax = fmaxf(mymax, fmaxf(fmaxf(td[bt][0], td[bt][1]),
                                           fmaxf(td[bt][2], td[bt][3])));
            }
        }
        __syncthreads();
    }

    red[tid] = mymax;
    __syncthreads();
    for (int off = 128; off > 0; off >>= 1) {
        if (tid < off) red[tid] = fmaxf(red[tid], red[tid + off]);
        __syncthreads();
    }
    if (tid == 0) atomicMaxF(&g_kmax[bh], red[0]);
}

// -------------------- ctx fused: exp(td) in-fill (MLP-batched) + MMA + ksum --------
__global__ __launch_bounds__(256) void k_ctx() {
    __shared__ float Ksm[64][68];
    __shared__ float Vs[64][68];
    __shared__ float diag_s[512];
    __shared__ float rsum[256];
    int tid = threadIdx.x;
    int m0 = blockIdx.x * 64;
    int nc = blockIdx.y * 512;
    int bh = blockIdx.z;
    float mx = g_kmax[bh];

    diag_s[tid]       = g_diag[(size_t)bh * Nn + nc + tid];
    diag_s[tid + 256] = g_diag[(size_t)bh * Nn + nc + 256 + tid];

    u64t acc2[2][4];
#pragma unroll
    for (int i = 0; i < 2; i++)
#pragma unroll
        for (int j = 0; j < 4; j++) acc2[i][j] = 0ull;
    int ty = tid >> 4, tx = tid & 15;

    int mmc = m0 + (tid & 63);
    bool mok = mmc < Mm;
    int nbase = tid >> 6;
    float cs = 0.f;
    __syncthreads();

    for (int nt = 0; nt < 8; nt++) {
        int n0 = nc + nt * 64;
        float tdv[16];
        const float* kpb = g_kp + ((size_t)bh * Nn + n0 + nbase) * Mm + mmc;
#pragma unroll
        for (int i = 0; i < 16; i++)
            tdv[i] = mok ? kpb[(size_t)(i * 4) * Mm] : 0.f;
#pragma unroll
        for (int i = 0; i < 16; i++) {
            int n = i * 4 + nbase;
            float v = 0.f;
            if (mok) {
                v = RATIO * (fast_exp(tdv[i] - diag_s[nt * 64 + n] - mx) + EPSF);
                cs += v;
            }
            Ksm[n][tid & 63] = v;
        }
#pragma unroll
        for (int i = 0; i < 4; i++) {
            int s = tid + i * 256;
            int n = s >> 4, c = (s & 15) << 2;
            float4 v = *(const float4*)(g_v + ((size_t)bh * Nn + n0 + n) * DHd + c);
            Vs[n][c] = v.x; Vs[n][c + 1] = v.y; Vs[n][c + 2] = v.z; Vs[n][c + 3] = v.w;
        }
        __syncthreads();
#pragma unroll
        for (int kk = 0; kk < 64; kk++) {
            float4 a = *(const float4*)&Ksm[kk][ty * 4];
            float4 b = *(const float4*)&Vs[kk][tx * 4];
            F32X2_STEP(a, b);
        }
        __syncthreads();
    }
#pragma unroll
    for (int i = 0; i < 4; i++) {
        int m = m0 + ty * 4 + i;
        if (m < Mm)
#pragma unroll
            for (int j = 0; j < 4; j++)
                atomicAdd(&g_ctx[((size_t)bh * Mm + m) * DHd + tx * 4 + j], ACC2F(i, j));
    }
    rsum[tid] = cs;
    __syncthreads();
    if (tid < 64) {
        int m = m0 + tid;
        if (m < Mm) {
            float t = rsum[tid] + rsum[tid + 64] + rsum[tid + 128] + rsum[tid + 192];
            atomicAdd(&g_ksum[bh * Mm + m], t);
        }
    }
}

// ------------- phi_q + out FUSED, fp16 HMMA both phases; qp never touches HBM -------
#define QO_SMEM_BYTES 92736
__global__ __launch_bounds__(256) void k_phi_q_out() {
    extern __shared__ char smraw[];
    __half* Qh   = (__half*)smraw;                       // [64][PSTR]
    __half* Ph   = (__half*)(smraw + 9216);              // [64][PSTR]
    __half* qph  = (__half*)(smraw + 18432);             // [64][QSTR]
    __half* Ch   = (__half*)(smraw + 54272);             // [64][QSTR]
    float* ksum_s = (float*)(smraw + 90112);             // [MQ]
    float* diag_s = (float*)(smraw + 91200);             // [64]
    float* dinv_s = (float*)(smraw + 91456);             // [64]
    float* rmax   = (float*)(smraw + 91712);             // [64][2]
    float* rsum   = (float*)(smraw + 92224);             // [64][2]
    uint32_t QhU = smem_to_u32(Qh), PhU = smem_to_u32(Ph);
    uint32_t qphU = smem_to_u32(qph), ChU = smem_to_u32(Ch);

    int tid = threadIdx.x, lane = tid & 31, w = tid >> 5;
    int wy = w & 3, wx = w >> 2;
    int gid = lane >> 2, tig = lane & 3;
    int n0 = blockIdx.x * 64;
    int bh = blockIdx.y;

    for (int i = tid; i < MQ; i += 256) ksum_s[i] = (i < Mm) ? g_ksum[bh * Mm + i] : 0.f;
#pragma unroll
    for (int i = 0; i < 2; i++) {
        int s = tid + i * 256;
        int row = s >> 3, c8 = (s & 7) * 8;
        const float* src = g_q + ((size_t)bh * Nn + n0 + row) * DHd + c8;
        float4 a = *(const float4*)src;
        float4 b = *(const float4*)(src + 4);
        __half* d = Qh + row * PSTR + c8;
        *(__half2*)(d + 0) = __floats2half2_rn(a.x * NORMALIZER, a.y * NORMALIZER);
        *(__half2*)(d + 2) = __floats2half2_rn(a.z * NORMALIZER, a.w * NORMALIZER);
        *(__half2*)(d + 4) = __floats2half2_rn(b.x * NORMALIZER, b.y * NORMALIZER);
        *(__half2*)(d + 6) = __floats2half2_rn(b.z * NORMALIZER, b.w * NORMALIZER);
    }
    __syncthreads();
    if (tid < 64) {
        float ss = 0.f;
        const __half2* qr = (const __half2*)(Qh + tid * PSTR);
#pragma unroll
        for (int d = 0; d < 32; d++) {
            float2 t = __half22float2(qr[d]);
            ss += t.x * t.x + t.y * t.y;
        }
        diag_s[tid] = 0.5f * ss;
    }

    float td[5][4][4];
#pragma unroll
    for (int mt = 0; mt < 5; mt++)
#pragma unroll
        for (int bt = 0; bt < 4; bt++)
#pragma unroll
            for (int c = 0; c < 4; c++) td[mt][bt][c] = 0.f;

#pragma unroll 1
    for (int mt = 0; mt < 5; mt++) {
#pragma unroll
        for (int i = 0; i < 2; i++) {
            int s = tid + i * 256;
            int row = s >> 3, c8 = (s & 7) * 8;
            *(uint4*)(Ph + row * PSTR + c8) =
                *(const uint4*)(g_projh + (size_t)(mt * 64 + row) * 64 + c8);
        }
        __syncthreads();
#pragma unroll
        for (int k = 0; k < 4; k++) {
            uint32_t a[4];
            uint32_t aaddr = QhU +
                (uint32_t)((wy * 16 + (lane & 15)) * PSTR + k * 16 + ((lane >> 4) << 3)) * 2;
            ldm_x4(a[0], a[1], a[2], a[3], aaddr);
            uint32_t b[4][2];
#pragma unroll
            for (int p = 0; p < 2; p++) {
                uint32_t baddr = PhU +
                    (uint32_t)((wx * 32 + p * 16 + (lane & 7) + ((lane >> 4) << 3)) * PSTR +
                               k * 16 + (lane & 8)) * 2;
                ldm_x4(b[2 * p][0], b[2 * p][1], b[2 * p + 1][0], b[2 * p + 1][1], baddr);
            }
#pragma unroll
            for (int bt = 0; bt < 4; bt++)
                mma16816(td[mt][bt], a, b[bt]);
        }
        __syncthreads();
    }

    int r1 = wy * 16 + gid, r2 = r1 + 8;
    float mx1 = -3.0e38f, mx2 = -3.0e38f;
#pragma unroll
    for (int mt = 0; mt < 5; mt++)
#pragma unroll
        for (int bt = 0; bt < 4; bt++) {
            int mb = mt * 64 + wx * 32 + bt * 8 + tig * 2;
            if (mb < Mm)     { mx1 = fmaxf(mx1, td[mt][bt][0]); mx2 = fmaxf(mx2, td[mt][bt][2]); }
            if (mb + 1 < Mm) { mx1 = fmaxf(mx1, td[mt][bt][1]); mx2 = fmaxf(mx2, td[mt][bt][3]); }
        }
    mx1 = fmaxf(mx1, __shfl_xor_sync(0xffffffffu, mx1, 1));
    mx1 = fmaxf(mx1, __shfl_xor_sync(0xffffffffu, mx1, 2));
    mx2 = fmaxf(mx2, __shfl_xor_sync(0xffffffffu, mx2, 1));
    mx2 = fmaxf(mx2, __shfl_xor_sync(0xffffffffu, mx2, 2));
    if (tig == 0) { rmax[r1 * 2 + wx] = mx1; rmax[r2 * 2 + wx] = mx2; }
    __syncthreads();
    mx1 = fmaxf(rmax[r1 * 2], rmax[r1 * 2 + 1]);
    mx2 = fmaxf(rmax[r2 * 2], rmax[r2 * 2 + 1]);
    float dg1 = diag_s[r1], dg2 = diag_s[r2];
    float s1 = 0.f, s2 = 0.f;
#pragma unroll
    for (int mt = 0; mt < 5; mt++)
#pragma unroll
        for (int bt = 0; bt < 4; bt++) {
            int mb = mt * 64 + wx * 32 + bt * 8 + tig * 2;
            float v0 = 0.f, v1 = 0.f, v2 = 0.f, v3 = 0.f;
            if (mb < Mm) {
                v0 = RATIO * (fast_exp(td[mt][bt][0] - dg1 - mx1) + EPSF);
                v2 = RATIO * (fast_exp(td[mt][bt][2] - dg2 - mx2) + EPSF);
                s1 += v0 * ksum_s[mb];
                s2 += v2 * ksum_s[mb];
            }
            if (mb + 1 < Mm) {
                v1 = RATIO * (fast_exp(td[mt][bt][1] - dg1 - mx1) + EPSF);
                v3 = RATIO * (fast_exp(td[mt][bt][3] - dg2 - mx2) + EPSF);
                s1 += v1 * ksum_s[mb + 1];
                s2 += v3 * ksum_s[mb + 1];
            }
            if (mb < MQ) {
                *(__half2*)(qph + r1 * QSTR + mb) = __floats2half2_rn(v0, v1);
                *(__half2*)(qph + r2 * QSTR + mb) = __floats2half2_rn(v2, v3);
            }
        }
    s1 += __shfl_xor_sync(0xffffffffu, s1, 1);
    s1 += __shfl_xor_sync(0xffffffffu, s1, 2);
    s2 += __shfl_xor_sync(0xffffffffu, s2, 1);
    s2 += __shfl_xor_sync(0xffffffffu, s2, 2);
    if (tig == 0) { rsum[r1 * 2 + wx] = s1; rsum[r2 * 2 + wx] = s2; }
    __syncthreads();
    if (tid < 64) dinv_s[tid] = 1.0f / (rsum[tid * 2] + rsum[tid * 2 + 1]);

#pragma unroll
    for (int i = 0; i < 68; i++) {
        int s = tid + i * 256;
        int dh = s & 63, m = s >> 6;
        float cv = (m < Mm) ? g_ctx[((size_t)bh * Mm + m) * DHd + dh] : 0.f;
        Ch[dh * QSTR + m] = __float2half(cv);
    }
    __syncthreads();

    float oacc[4][4];
#pragma unroll
    for (int bt = 0; bt < 4; bt++)
#pragma unroll
        for (int c = 0; c < 4; c++) oacc[bt][c] = 0.f;

#pragma unroll 1
    for (int k = 0; k < 17; k++) {
        uint32_t a[4];
        uint32_t aaddr = qphU +
            (uint32_t)((wy * 16 + (lane & 15)) * QSTR + k * 16 + ((lane >> 4) << 3)) * 2;
        ldm_x4(a[0], a[1], a[2], a[3], aaddr);
        uint32_t b[4][2];
#pragma unroll
        for (int p = 0; p < 2; p++) {
            uint32_t baddr = ChU +
                (uint32_t)((wx * 32 + p * 16 + (lane & 7) + ((lane >> 4) << 3)) * QSTR +
                           k * 16 + (lane & 8)) * 2;
            ldm_x4(b[2 * p][0], b[2 * p][1], b[2 * p + 1][0], b[2 * p + 1][1], baddr);
        }
#pragma unroll
        for (int bt = 0; bt < 4; bt++)
            mma16816(oacc[bt], a, b[bt]);
    }

    int b = bh >> 3, h = bh & 7;
    float dv1 = dinv_s[r1], dv2 = dinv_s[r2];
    size_t rb1 = (size_t)(b * Nn + n0 + r1) * K2 + h * 64;
    size_t rb2 = (size_t)(b * Nn + n0 + r2) * K2 + h * 64;
#pragma unroll
    for (int bt = 0; bt < 4; bt++) {
        int dh = wx * 32 + bt * 8 + tig * 2;
        *(__half2*)(g_attn2 + rb1 + dh) =
            __floats2half2_rn(oacc[bt][0] * dv1, oacc[bt][1] * dv1);
        *(__half2*)(g_attn2 + rb2 + dh) =
            __floats2half2_rn(oacc[bt][2] * dv2, oacc[bt][3] * dv2);
    }
}

// -------------------- launch --------------------
extern "C" void kernel_launch(void* const* d_in, const int* in_sizes, int n_in,
                              void* d_out, int out_size) {
    const float* x    = (const float*)d_in[0];
    const float* Wq   = (const float*)d_in[1];
    const float* Wk   = (const float*)d_in[2];
    const float* Wv   = (const float*)d_in[3];
    const float* Wo   = (const float*)d_in[4];
    const float* bo   = (const float*)d_in[5];
    const float* proj = (const float*)d_in[6];
    float* out = (float*)d_out;
    (void)in_sizes; (void)n_in; (void)out_size;

    cudaFuncSetAttribute(k_phi_q_out, cudaFuncAttributeMaxDynamicSharedMemorySize,
                         QO_SMEM_BYTES);
    cudaFuncSetAttribute(k_gemm, cudaFuncAttributeMaxDynamicSharedMemorySize, GEMM_DSMEM);

    __half *x2p, *wq2p, *wk2p, *wv2p, *wo2p, *attn2p;
    cudaGetSymbolAddress((void**)&x2p, g_x2);
    cudaGetSymbolAddress((void**)&wq2p, g_wq2);
    cudaGetSymbolAddress((void**)&wk2p, g_wk2);
    cudaGetSymbolAddress((void**)&wv2p, g_wv2);
    cudaGetSymbolAddress((void**)&wo2p, g_wo2);
    cudaGetSymbolAddress((void**)&attn2p, g_attn2);
    float *qp_, *kp_, *vp_;
    cudaGetSymbolAddress((void**)&qp_, g_q);
    cudaGetSymbolAddress((void**)&kp_, g_k);
    cudaGetSymbolAddress((void**)&vp_, g_v);

    k_init<<<(BHh * Mm * DHd + 255) / 256, 256>>>();
    k_half<<<(BNn * 128 + 255) / 256, 256>>>(x, x2p, BNn);
    k_half<<<(Dd * 128 + 255) / 256, 256>>>(Wq, wq2p, Dd);
    k_half<<<(Dd * 128 + 255) / 256, 256>>>(Wk, wk2p, Dd);
    k_half<<<(Dd * 128 + 255) / 256, 256>>>(Wv, wv2p, Dd);

    dim3 gG(BNn / 128, Dd / 128);
    k_gemm<<<gG, 256, GEMM_DSMEM>>>(x2p, wq2p, qp_, nullptr, nullptr, 0);
    k_gemm<<<gG, 256, GEMM_DSMEM>>>(x2p, wk2p, kp_, nullptr, nullptr, 0);
    k_gemm<<<gG, 256, GEMM_DSMEM>>>(x2p, wv2p, vp_, nullptr, nullptr, 0);

    k_half<<<(Dd * 128 + 255) / 256, 256>>>(Wo, wo2p, Dd);
    k_projh<<<(320 * 64 + 255) / 256, 256>>>(proj);

    k_phi_k<<<dim3(Nn / 64, BHh), 256>>>();
    k_ctx<<<dim3(5, Nn / 512, BHh), 256>>>();
    k_phi_q_out<<<dim3(Nn / 64, BHh), 256, QO_SMEM_BYTES>>>();

    k_gemm<<<gG, 256, GEMM_DSMEM>>>(attn2p, wo2p, out, x, bo, 1);
}